// round 2
// baseline (speedup 1.0000x reference)
#include <cuda_runtime.h>
#include <math_constants.h>
#include <cstdint>

#define NUMH 12
#define HD   64
#define BATCH 4
#define SEQ  2048
#define CH   768
#define MROWS (BATCH*SEQ)   // 8192

// ---------------- scratch (device globals; no allocation allowed) ----------
__device__ float g_qkv[(size_t)MROWS * 3 * CH];          // [B*N, 2304]
__device__ float g_q  [(size_t)BATCH*NUMH*SEQ*HD];       // [B*H, N, D]
__device__ float g_k  [(size_t)BATCH*NUMH*SEQ*HD];
__device__ float g_v  [(size_t)BATCH*NUMH*SEQ*HD];
__device__ float g_o  [(size_t)MROWS * CH];              // [B*N, C] (pre-proj)

// ---------------- GEMM: C[M,N] = A[M,K] @ W[N,K]^T (+bias) -----------------
// BM=BN=128, BK=16, 256 threads, 8x8 per-thread register tile.
__global__ __launch_bounds__(256) void gemm_nt(
    const float* __restrict__ A, const float* __restrict__ W,
    const float* __restrict__ bias, float* __restrict__ Cm,
    int M, int N, int K)
{
    const int LDA = 132;                     // padded row stride (floats)
    __shared__ float As[16 * LDA];
    __shared__ float Ws[16 * LDA];
    int tid = threadIdx.x;
    int bm = blockIdx.y * 128, bn = blockIdx.x * 128;
    int tx = tid & 15, ty = tid >> 4;
    int lr = tid >> 2;                       // 0..63
    int lk = (tid & 3) << 2;                 // 0,4,8,12

    float acc[8][8];
    #pragma unroll
    for (int i = 0; i < 8; i++)
        #pragma unroll
        for (int j = 0; j < 8; j++) acc[i][j] = 0.f;

    const float* Ap = A + (size_t)bm * K;
    const float* Wp = W + (size_t)bn * K;

    for (int k0 = 0; k0 < K; k0 += 16) {
        #pragma unroll
        for (int r = 0; r < 2; ++r) {
            int row = lr + r * 64;
            float4 va = *(const float4*)(Ap + (size_t)row * K + k0 + lk);
            As[(lk+0)*LDA + row] = va.x; As[(lk+1)*LDA + row] = va.y;
            As[(lk+2)*LDA + row] = va.z; As[(lk+3)*LDA + row] = va.w;
            float4 vw = *(const float4*)(Wp + (size_t)row * K + k0 + lk);
            Ws[(lk+0)*LDA + row] = vw.x; Ws[(lk+1)*LDA + row] = vw.y;
            Ws[(lk+2)*LDA + row] = vw.z; Ws[(lk+3)*LDA + row] = vw.w;
        }
        __syncthreads();
        #pragma unroll
        for (int k = 0; k < 16; ++k) {
            float4 a0 = *(const float4*)&As[k*LDA + ty*8];
            float4 a1 = *(const float4*)&As[k*LDA + ty*8 + 4];
            float4 b0 = *(const float4*)&Ws[k*LDA + tx*8];
            float4 b1 = *(const float4*)&Ws[k*LDA + tx*8 + 4];
            float a[8] = {a0.x,a0.y,a0.z,a0.w,a1.x,a1.y,a1.z,a1.w};
            float b[8] = {b0.x,b0.y,b0.z,b0.w,b1.x,b1.y,b1.z,b1.w};
            #pragma unroll
            for (int i = 0; i < 8; i++)
                #pragma unroll
                for (int j = 0; j < 8; j++)
                    acc[i][j] += a[i] * b[j];
        }
        __syncthreads();
    }

    #pragma unroll
    for (int i = 0; i < 8; i++) {
        size_t row = (size_t)(bm + ty*8 + i);
        #pragma unroll
        for (int j = 0; j < 8; j += 4) {
            int col = bn + tx*8 + j;
            float4 v;
            v.x = acc[i][j+0]; v.y = acc[i][j+1];
            v.z = acc[i][j+2]; v.w = acc[i][j+3];
            if (bias) {
                v.x += bias[col+0]; v.y += bias[col+1];
                v.z += bias[col+2]; v.w += bias[col+3];
            }
            *(float4*)&Cm[row * N + col] = v;
        }
    }
}

// ---------- RMSnorm + RoPE + [B,N,3,H,D] -> [B*H,N,D] scatter --------------
// one warp per (b,h,n); lane j holds elements j and j+32 (RoPE pairing).
__global__ __launch_bounds__(128) void prep_kernel(
    const float* __restrict__ qkv, const float* __restrict__ cs,
    const float* __restrict__ sn, const float* __restrict__ qw,
    const float* __restrict__ kw,
    float* __restrict__ qo, float* __restrict__ ko, float* __restrict__ vo)
{
    int task = blockIdx.x * 4 + (threadIdx.x >> 5);   // (b*H + h)*SEQ + n
    int lane = threadIdx.x & 31;
    int n  = task & (SEQ - 1);
    int bh = task >> 11;                              // SEQ = 2^11
    int h = bh % NUMH, b = bh / NUMH;

    const float* base = qkv + ((size_t)(b*SEQ + n)) * (3*CH) + h*HD;
    float q1 = base[lane],        q2 = base[lane+32];
    float k1 = base[CH+lane],     k2 = base[CH+lane+32];
    float v1 = base[2*CH+lane],   v2 = base[2*CH+lane+32];

    float sq = q1*q1 + q2*q2, sk = k1*k1 + k2*k2;
    #pragma unroll
    for (int o = 16; o >= 1; o >>= 1) {
        sq += __shfl_xor_sync(0xffffffffu, sq, o);
        sk += __shfl_xor_sync(0xffffffffu, sk, o);
    }
    float rq = rsqrtf(sq * (1.f/64.f) + 1e-6f);
    float rk = rsqrtf(sk * (1.f/64.f) + 1e-6f);
    q1 *= rq * qw[lane]; q2 *= rq * qw[lane+32];
    k1 *= rk * kw[lane]; k2 *= rk * kw[lane+32];

    float c = cs[n*32 + lane], s = sn[n*32 + lane];
    size_t o = ((size_t)bh * SEQ + n) * HD + lane;
    qo[o]    = q1*c - q2*s;  qo[o+32] = q2*c + q1*s;
    ko[o]    = k1*c - k2*s;  ko[o+32] = k2*c + k1*s;
    vo[o]    = v1;           vo[o+32] = v2;
}

// ---------------- flash attention: 64q x 64k tiles, fp32 -------------------
#define PADK 68
__global__ __launch_bounds__(256) void attn_kernel(
    const float* __restrict__ Q, const float* __restrict__ K,
    const float* __restrict__ V, float* __restrict__ O)
{
    extern __shared__ float sm[];
    float* Qst = sm;                 // [d][q]  64 x PADK (scaled by 1/8)
    float* Kst = sm + 64*PADK;       // [d][k]
    float* Vs  = sm + 2*64*PADK;     // [k][d]
    float* Pst = sm + 3*64*PADK;     // [k][q]

    int tid = threadIdx.x;
    int tx = tid & 15, ty = tid >> 4;
    int qt = blockIdx.x, bh = blockIdx.y;

    const float scale = 0.125f;      // 64^-0.5
    const float* Qb = Q + ((size_t)bh * SEQ + qt*64) * HD;
    const float* Kb = K + (size_t)bh * SEQ * HD;
    const float* Vb = V + (size_t)bh * SEQ * HD;

    int lr = tid >> 2;               // 0..63
    int lc = (tid & 3) * 16;         // 0,16,32,48

    // load Q tile transposed (scale folded in)
    #pragma unroll
    for (int c = 0; c < 16; c += 4) {
        float4 v = *(const float4*)(Qb + (size_t)lr * HD + lc + c);
        Qst[(lc+c+0)*PADK + lr] = v.x * scale;
        Qst[(lc+c+1)*PADK + lr] = v.y * scale;
        Qst[(lc+c+2)*PADK + lr] = v.z * scale;
        Qst[(lc+c+3)*PADK + lr] = v.w * scale;
    }

    float m[4], l[4], o[4][4];
    #pragma unroll
    for (int i = 0; i < 4; i++) {
        m[i] = -CUDART_INF_F; l[i] = 0.f;
        #pragma unroll
        for (int j = 0; j < 4; j++) o[i][j] = 0.f;
    }

    for (int kt = 0; kt < SEQ/64; ++kt) {
        // load K (transposed) and V (natural) tiles
        #pragma unroll
        for (int c = 0; c < 16; c += 4) {
            float4 vk = *(const float4*)(Kb + (size_t)(kt*64 + lr) * HD + lc + c);
            Kst[(lc+c+0)*PADK + lr] = vk.x;
            Kst[(lc+c+1)*PADK + lr] = vk.y;
            Kst[(lc+c+2)*PADK + lr] = vk.z;
            Kst[(lc+c+3)*PADK + lr] = vk.w;
            float4 vv = *(const float4*)(Vb + (size_t)(kt*64 + lr) * HD + lc + c);
            *(float4*)&Vs[lr*PADK + lc + c] = vv;
        }
        __syncthreads();

        // S = Q K^T (4x4 per thread)
        float s[4][4];
        #pragma unroll
        for (int i = 0; i < 4; i++)
            #pragma unroll
            for (int j = 0; j < 4; j++) s[i][j] = 0.f;
        #pragma unroll 8
        for (int d = 0; d < 64; ++d) {
            float4 a = *(const float4*)&Qst[d*PADK + ty*4];
            float4 b = *(const float4*)&Kst[d*PADK + tx*4];
            float av[4] = {a.x,a.y,a.z,a.w}, bv[4] = {b.x,b.y,b.z,b.w};
            #pragma unroll
            for (int i = 0; i < 4; i++)
                #pragma unroll
                for (int j = 0; j < 4; j++)
                    s[i][j] += av[i]*bv[j];
        }

        // online softmax
        #pragma unroll
        for (int i = 0; i < 4; i++) {
            float r = fmaxf(fmaxf(s[i][0], s[i][1]), fmaxf(s[i][2], s[i][3]));
            #pragma unroll
            for (int off = 8; off >= 1; off >>= 1)
                r = fmaxf(r, __shfl_xor_sync(0xffffffffu, r, off));
            float mn = fmaxf(m[i], r);
            float al = __expf(m[i] - mn);
            m[i] = mn;
            float rs = 0.f;
            #pragma unroll
            for (int j = 0; j < 4; j++) {
                float p = __expf(s[i][j] - mn);
                s[i][j] = p; rs += p;
            }
            #pragma unroll
            for (int off = 8; off >= 1; off >>= 1)
                rs += __shfl_xor_sync(0xffffffffu, rs, off);
            l[i] = l[i]*al + rs;
            #pragma unroll
            for (int j = 0; j < 4; j++) o[i][j] *= al;
        }
        // write P transposed [k][q]
        #pragma unroll
        for (int j = 0; j < 4; j++)
            #pragma unroll
            for (int i = 0; i < 4; i++)
                Pst[(tx*4 + j)*PADK + ty*4 + i] = s[i][j];
        __syncthreads();

        // O += P V
        #pragma unroll 8
        for (int kk = 0; kk < 64; ++kk) {
            float4 a = *(const float4*)&Pst[kk*PADK + ty*4];
            float4 b = *(const float4*)&Vs[kk*PADK + tx*4];
            float av[4] = {a.x,a.y,a.z,a.w}, bv[4] = {b.x,b.y,b.z,b.w};
            #pragma unroll
            for (int i = 0; i < 4; i++)
                #pragma unroll
                for (int j = 0; j < 4; j++)
                    o[i][j] += av[i]*bv[j];
        }
        __syncthreads();
    }

    int b_ = bh / NUMH, h_ = bh % NUMH;
    #pragma unroll
    for (int i = 0; i < 4; i++) {
        float inv = 1.f / l[i];
        float4 r;
        r.x = o[i][0]*inv; r.y = o[i][1]*inv;
        r.z = o[i][2]*inv; r.w = o[i][3]*inv;
        size_t row = (size_t)(b_*SEQ + qt*64 + ty*4 + i);
        *(float4*)&O[row*CH + h_*HD + tx*4] = r;
    }
}

// ---------------------------------------------------------------------------
extern "C" void kernel_launch(void* const* d_in, const int* in_sizes, int n_in,
                              void* d_out, int out_size)
{
    const float* x      = (const float*)d_in[0];
    const float* cs     = (const float*)d_in[1];
    const float* sn     = (const float*)d_in[2];
    const float* qkv_w  = (const float*)d_in[3];
    const float* qnw    = (const float*)d_in[4];
    const float* knw    = (const float*)d_in[5];
    const float* proj_w = (const float*)d_in[6];
    const float* proj_b = (const float*)d_in[7];
    float* out = (float*)d_out;

    float *qkv, *qb, *kb, *vb, *ob;
    cudaGetSymbolAddress((void**)&qkv, g_qkv);
    cudaGetSymbolAddress((void**)&qb,  g_q);
    cudaGetSymbolAddress((void**)&kb,  g_k);
    cudaGetSymbolAddress((void**)&vb,  g_v);
    cudaGetSymbolAddress((void**)&ob,  g_o);

    // 1) QKV projection: [8192,768] @ [2304,768]^T
    gemm_nt<<<dim3(3*CH/128, MROWS/128), 256>>>(x, qkv_w, nullptr, qkv,
                                                MROWS, 3*CH, CH);

    // 2) RMSnorm + RoPE + scatter to [B*H,N,D]
    prep_kernel<<<(BATCH*NUMH*SEQ)/4, 128>>>(qkv, cs, sn, qnw, knw, qb, kb, vb);

    // 3) flash attention
    const int smem = 4 * 64 * PADK * sizeof(float);   // 69632 B
    cudaFuncSetAttribute(attn_kernel, cudaFuncAttributeMaxDynamicSharedMemorySize, smem);
    attn_kernel<<<dim3(SEQ/64, BATCH*NUMH), 256, smem>>>(qb, kb, vb, ob);

    // 4) output projection (+bias): [8192,768] @ [768,768]^T
    gemm_nt<<<dim3(CH/128, MROWS/128), 256>>>(ob, proj_w, proj_b, out,
                                              MROWS, CH, CH);
}

// round 5
// speedup vs baseline: 1.1746x; 1.1746x over previous
#include <cuda_runtime.h>
#include <math_constants.h>
#include <cstdint>

#define NUMH 12
#define HD   64
#define BATCH 4
#define SEQ  2048
#define CH   768
#define MROWS (BATCH*SEQ)   // 8192

typedef unsigned long long u64;

// ---------------- packed f32x2 helpers (Blackwell FFMA2 path) --------------
__device__ __forceinline__ u64 dup2(float a) {
    u64 r; unsigned x = __float_as_uint(a);
    asm("mov.b64 %0, {%1, %2};" : "=l"(r) : "r"(x), "r"(x));
    return r;
}
__device__ __forceinline__ void fma2(u64& d, u64 a, u64 b) {
    asm("fma.rn.f32x2 %0, %1, %2, %0;" : "+l"(d) : "l"(a), "l"(b));
}
__device__ __forceinline__ void mul2(u64& d, u64 a) {
    asm("mul.rn.f32x2 %0, %0, %1;" : "+l"(d) : "l"(a));
}
__device__ __forceinline__ void unpack2(u64 v, float& lo, float& hi) {
    unsigned a, b;
    asm("mov.b64 {%0, %1}, %2;" : "=r"(a), "=r"(b) : "l"(v));
    lo = __uint_as_float(a); hi = __uint_as_float(b);
}

// ---------------- scratch (device globals; no allocation allowed) ----------
__device__ float g_qkv[(size_t)MROWS * 3 * CH];          // [B*N, 2304]
__device__ float g_q  [(size_t)BATCH*NUMH*SEQ*HD];       // [B*H, N, D]
__device__ float g_k  [(size_t)BATCH*NUMH*SEQ*HD];
__device__ float g_v  [(size_t)BATCH*NUMH*SEQ*HD];
__device__ float g_o  [(size_t)MROWS * CH];              // [B*N, C] (pre-proj)

// ---------------- GEMM: C[M,N] = A[M,K] @ W[N,K]^T (+bias) -----------------
// BM=BN=128, BK=8, 256 threads, 8x8 per-thread tile via f32x2, double buffer.
#define GLDA 132
__global__ __launch_bounds__(256, 2) void gemm_nt(
    const float* __restrict__ A, const float* __restrict__ W,
    const float* __restrict__ bias, float* __restrict__ Cm,
    int M, int N, int K)
{
    __shared__ float As[2][8][GLDA];
    __shared__ float Ws[2][8][GLDA];
    int tid = threadIdx.x;
    int bm = blockIdx.y * 128, bn = blockIdx.x * 128;
    int tx = tid & 15, ty = tid >> 4;

    // loader mapping: each thread loads one float4 per matrix per stage
    int lrow = tid >> 1;            // 0..127
    int lc   = (tid & 1) * 4;       // 0 or 4

    const float* Ap = A + (size_t)(bm + lrow) * K + lc;
    const float* Wp = W + (size_t)(bn + lrow) * K + lc;

    u64 acc[8][4];
    #pragma unroll
    for (int i = 0; i < 8; i++)
        #pragma unroll
        for (int j = 0; j < 4; j++) acc[i][j] = 0ull;

    // prologue: stage 0
    {
        float4 va = *(const float4*)(Ap);
        float4 vw = *(const float4*)(Wp);
        As[0][lc+0][lrow] = va.x; As[0][lc+1][lrow] = va.y;
        As[0][lc+2][lrow] = va.z; As[0][lc+3][lrow] = va.w;
        Ws[0][lc+0][lrow] = vw.x; Ws[0][lc+1][lrow] = vw.y;
        Ws[0][lc+2][lrow] = vw.z; Ws[0][lc+3][lrow] = vw.w;
    }
    __syncthreads();

    int nt = K >> 3;
    for (int t = 0; t < nt; ++t) {
        int cur = t & 1;
        float4 va, vw;
        bool more = (t + 1) < nt;
        if (more) {
            va = *(const float4*)(Ap + (size_t)(t + 1) * 8);
            vw = *(const float4*)(Wp + (size_t)(t + 1) * 8);
        }
        #pragma unroll
        for (int k = 0; k < 8; ++k) {
            float4 a0 = *(const float4*)&As[cur][k][ty*8];
            float4 a1 = *(const float4*)&As[cur][k][ty*8+4];
            u64 ad[8];
            ad[0]=dup2(a0.x); ad[1]=dup2(a0.y); ad[2]=dup2(a0.z); ad[3]=dup2(a0.w);
            ad[4]=dup2(a1.x); ad[5]=dup2(a1.y); ad[6]=dup2(a1.z); ad[7]=dup2(a1.w);
            ulonglong2 b0 = *(const ulonglong2*)&Ws[cur][k][tx*8];
            ulonglong2 b1 = *(const ulonglong2*)&Ws[cur][k][tx*8+4];
            u64 bp[4] = {b0.x, b0.y, b1.x, b1.y};
            #pragma unroll
            for (int i = 0; i < 8; i++)
                #pragma unroll
                for (int j = 0; j < 4; j++)
                    fma2(acc[i][j], ad[i], bp[j]);
        }
        if (more) {
            int nxt = cur ^ 1;
            As[nxt][lc+0][lrow] = va.x; As[nxt][lc+1][lrow] = va.y;
            As[nxt][lc+2][lrow] = va.z; As[nxt][lc+3][lrow] = va.w;
            Ws[nxt][lc+0][lrow] = vw.x; Ws[nxt][lc+1][lrow] = vw.y;
            Ws[nxt][lc+2][lrow] = vw.z; Ws[nxt][lc+3][lrow] = vw.w;
        }
        __syncthreads();
    }

    #pragma unroll
    for (int i = 0; i < 8; i++) {
        size_t row = (size_t)(bm + ty*8 + i);
        float c[8];
        #pragma unroll
        for (int j = 0; j < 4; j++) unpack2(acc[i][j], c[2*j], c[2*j+1]);
        int col = bn + tx*8;
        if (bias) {
            #pragma unroll
            for (int j = 0; j < 8; j++) c[j] += bias[col + j];
        }
        float4 v0 = {c[0], c[1], c[2], c[3]};
        float4 v1 = {c[4], c[5], c[6], c[7]};
        *(float4*)&Cm[row * N + col]     = v0;
        *(float4*)&Cm[row * N + col + 4] = v1;
    }
}

// ---------- RMSnorm + RoPE + [B,N,3,H,D] -> [B*H,N,D] scatter --------------
__global__ __launch_bounds__(128) void prep_kernel(
    const float* __restrict__ qkv, const float* __restrict__ cs,
    const float* __restrict__ sn, const float* __restrict__ qw,
    const float* __restrict__ kw,
    float* __restrict__ qo, float* __restrict__ ko, float* __restrict__ vo)
{
    int task = blockIdx.x * 4 + (threadIdx.x >> 5);   // (b*H + h)*SEQ + n
    int lane = threadIdx.x & 31;
    int n  = task & (SEQ - 1);
    int bh = task >> 11;                              // SEQ = 2^11
    int h = bh % NUMH, b = bh / NUMH;

    const float* base = qkv + ((size_t)(b*SEQ + n)) * (3*CH) + h*HD;
    float q1 = base[lane],        q2 = base[lane+32];
    float k1 = base[CH+lane],     k2 = base[CH+lane+32];
    float v1 = base[2*CH+lane],   v2 = base[2*CH+lane+32];

    float sq = q1*q1 + q2*q2, sk = k1*k1 + k2*k2;
    #pragma unroll
    for (int o = 16; o >= 1; o >>= 1) {
        sq += __shfl_xor_sync(0xffffffffu, sq, o);
        sk += __shfl_xor_sync(0xffffffffu, sk, o);
    }
    float rq = rsqrtf(sq * (1.f/64.f) + 1e-6f);
    float rk = rsqrtf(sk * (1.f/64.f) + 1e-6f);
    q1 *= rq * qw[lane]; q2 *= rq * qw[lane+32];
    k1 *= rk * kw[lane]; k2 *= rk * kw[lane+32];

    float c = cs[n*32 + lane], s = sn[n*32 + lane];
    size_t o = ((size_t)bh * SEQ + n) * HD + lane;
    qo[o]    = q1*c - q2*s;  qo[o+32] = q2*c + q1*s;
    ko[o]    = k1*c - k2*s;  ko[o+32] = k2*c + k1*s;
    vo[o]    = v1;           vo[o+32] = v2;
}

// ---------------- flash attention: 128q x 64k tiles, f32x2 -----------------
#define PADQ 132
#define PADK 68
__global__ __launch_bounds__(256, 2) void attn_kernel(
    const float* __restrict__ Q, const float* __restrict__ K,
    const float* __restrict__ V, float* __restrict__ O)
{
    extern __shared__ float sm[];
    float* Qst = sm;                       // [64][PADQ]  (d-major, scaled)
    float* Kst = Qst + 64*PADQ;            // [64][PADK]  (d-major)
    float* Vs  = Kst + 64*PADK;            // [64][PADK]  (k-major)
    float* Pst = Vs  + 64*PADK;            // [64][PADQ]  (k-major)

    int tid = threadIdx.x;
    int tx = tid & 15, ty = tid >> 4;      // 16 x 16
    int qt = blockIdx.x, bh = blockIdx.y;

    const float scale = 0.125f;            // 64^-0.5
    const float* Qb = Q + ((size_t)bh * SEQ + qt*128) * HD;
    const float* Kb = K + (size_t)bh * SEQ * HD;
    const float* Vb = V + (size_t)bh * SEQ * HD;

    // ---- load Q tile transposed: row = tid>>1 (0..127), d-base = (tid&1)*32
    {
        int r = tid >> 1, db = (tid & 1) * 32;
        const float* src = Qb + (size_t)r * HD + db;
        #pragma unroll
        for (int c = 0; c < 32; c += 4) {
            float4 v = *(const float4*)(src + c);
            Qst[(db+c+0)*PADQ + r] = v.x * scale;
            Qst[(db+c+1)*PADQ + r] = v.y * scale;
            Qst[(db+c+2)*PADQ + r] = v.z * scale;
            Qst[(db+c+3)*PADQ + r] = v.w * scale;
        }
    }

    float m[8], l[8];
    u64 o2[8][2];
    #pragma unroll
    for (int i = 0; i < 8; i++) {
        m[i] = -CUDART_INF_F; l[i] = 0.f;
        o2[i][0] = 0ull; o2[i][1] = 0ull;
    }

    // K/V loader mapping: r = tid>>2 (0..63), cb = (tid&3)*4, c in {0,16,32,48}
    int kr = tid >> 2, kcb = (tid & 3) * 4;

    for (int kt = 0; kt < SEQ/64; ++kt) {
        const float* Ksrc = Kb + (size_t)(kt*64 + kr) * HD + kcb;
        const float* Vsrc = Vb + (size_t)(kt*64 + kr) * HD + kcb;
        #pragma unroll
        for (int c = 0; c < 64; c += 16) {
            float4 vk = *(const float4*)(Ksrc + c);
            Kst[(kcb+c+0)*PADK + kr] = vk.x;
            Kst[(kcb+c+1)*PADK + kr] = vk.y;
            Kst[(kcb+c+2)*PADK + kr] = vk.z;
            Kst[(kcb+c+3)*PADK + kr] = vk.w;
            float4 vv = *(const float4*)(Vsrc + c);
            *(float4*)&Vs[kr*PADK + kcb + c] = vv;
        }
        __syncthreads();

        // ---- S = Q K^T : per-thread 8 q-rows x 4 k-cols (2 packed pairs)
        u64 s2[8][2];
        #pragma unroll
        for (int i = 0; i < 8; i++) { s2[i][0] = 0ull; s2[i][1] = 0ull; }
        #pragma unroll 8
        for (int d = 0; d < 64; ++d) {
            float4 a0 = *(const float4*)&Qst[d*PADQ + ty*8];
            float4 a1 = *(const float4*)&Qst[d*PADQ + ty*8 + 4];
            u64 ad[8];
            ad[0]=dup2(a0.x); ad[1]=dup2(a0.y); ad[2]=dup2(a0.z); ad[3]=dup2(a0.w);
            ad[4]=dup2(a1.x); ad[5]=dup2(a1.y); ad[6]=dup2(a1.z); ad[7]=dup2(a1.w);
            ulonglong2 bv = *(const ulonglong2*)&Kst[d*PADK + tx*4];
            #pragma unroll
            for (int i = 0; i < 8; i++) {
                fma2(s2[i][0], ad[i], bv.x);
                fma2(s2[i][1], ad[i], bv.y);
            }
        }

        // ---- online softmax (row group = 16 tx lanes)
        float s[8][4];
        #pragma unroll
        for (int i = 0; i < 8; i++) {
            unpack2(s2[i][0], s[i][0], s[i][1]);
            unpack2(s2[i][1], s[i][2], s[i][3]);
        }
        #pragma unroll
        for (int i = 0; i < 8; i++) {
            float r = fmaxf(fmaxf(s[i][0], s[i][1]), fmaxf(s[i][2], s[i][3]));
            #pragma unroll
            for (int off = 8; off >= 1; off >>= 1)
                r = fmaxf(r, __shfl_xor_sync(0xffffffffu, r, off));
            float mn = fmaxf(m[i], r);
            float al = __expf(m[i] - mn);
            m[i] = mn;
            float rs = 0.f;
            #pragma unroll
            for (int j = 0; j < 4; j++) {
                float p = __expf(s[i][j] - mn);
                s[i][j] = p; rs += p;
            }
            #pragma unroll
            for (int off = 8; off >= 1; off >>= 1)
                rs += __shfl_xor_sync(0xffffffffu, rs, off);
            l[i] = l[i]*al + rs;
            u64 a2 = dup2(al);
            mul2(o2[i][0], a2);
            mul2(o2[i][1], a2);
        }

        // ---- write P transposed [k][q]: per j, two float4 over i
        #pragma unroll
        for (int j = 0; j < 4; j++) {
            float4 p0 = {s[0][j], s[1][j], s[2][j], s[3][j]};
            float4 p1 = {s[4][j], s[5][j], s[6][j], s[7][j]};
            float* dst = &Pst[(tx*4 + j)*PADQ + ty*8];
            *(float4*)(dst)     = p0;
            *(float4*)(dst + 4) = p1;
        }
        __syncthreads();

        // ---- O += P V : per-thread 8 q-rows x 4 d-cols
        #pragma unroll 8
        for (int kk = 0; kk < 64; ++kk) {
            float4 a0 = *(const float4*)&Pst[kk*PADQ + ty*8];
            float4 a1 = *(const float4*)&Pst[kk*PADQ + ty*8 + 4];
            u64 ad[8];
            ad[0]=dup2(a0.x); ad[1]=dup2(a0.y); ad[2]=dup2(a0.z); ad[3]=dup2(a0.w);
            ad[4]=dup2(a1.x); ad[5]=dup2(a1.y); ad[6]=dup2(a1.z); ad[7]=dup2(a1.w);
            ulonglong2 bv = *(const ulonglong2*)&Vs[kk*PADK + tx*4];
            #pragma unroll
            for (int i = 0; i < 8; i++) {
                fma2(o2[i][0], ad[i], bv.x);
                fma2(o2[i][1], ad[i], bv.y);
            }
        }
        __syncthreads();
    }

    int b_ = bh / NUMH, h_ = bh % NUMH;
    #pragma unroll
    for (int i = 0; i < 8; i++) {
        float inv = 1.f / l[i];
        float c0, c1, c2, c3;
        unpack2(o2[i][0], c0, c1);
        unpack2(o2[i][1], c2, c3);
        float4 r = {c0*inv, c1*inv, c2*inv, c3*inv};
        size_t row = (size_t)(b_*SEQ + qt*128 + ty*8 + i);
        *(float4*)&O[row*CH + h_*HD + tx*4] = r;
    }
}

// ---------------------------------------------------------------------------
extern "C" void kernel_launch(void* const* d_in, const int* in_sizes, int n_in,
                              void* d_out, int out_size)
{
    const float* x      = (const float*)d_in[0];
    const float* cs     = (const float*)d_in[1];
    const float* sn     = (const float*)d_in[2];
    const float* qkv_w  = (const float*)d_in[3];
    const float* qnw    = (const float*)d_in[4];
    const float* knw    = (const float*)d_in[5];
    const float* proj_w = (const float*)d_in[6];
    const float* proj_b = (const float*)d_in[7];
    float* out = (float*)d_out;

    float *qkv, *qb, *kb, *vb, *ob;
    cudaGetSymbolAddress((void**)&qkv, g_qkv);
    cudaGetSymbolAddress((void**)&qb,  g_q);
    cudaGetSymbolAddress((void**)&kb,  g_k);
    cudaGetSymbolAddress((void**)&vb,  g_v);
    cudaGetSymbolAddress((void**)&ob,  g_o);

    // 1) QKV projection: [8192,768] @ [2304,768]^T
    gemm_nt<<<dim3(3*CH/128, MROWS/128), 256>>>(x, qkv_w, nullptr, qkv,
                                                MROWS, 3*CH, CH);

    // 2) RMSnorm + RoPE + scatter to [B*H,N,D]
    prep_kernel<<<(BATCH*NUMH*SEQ)/4, 128>>>(qkv, cs, sn, qnw, knw, qb, kb, vb);

    // 3) flash attention (128q x 64k tiles)
    const int smem = (64*PADQ + 64*PADK + 64*PADK + 64*PADQ) * sizeof(float); // 102400
    cudaFuncSetAttribute(attn_kernel, cudaFuncAttributeMaxDynamicSharedMemorySize, smem);
    attn_kernel<<<dim3(SEQ/128, BATCH*NUMH), 256, smem>>>(qb, kb, vb, ob);

    // 4) output projection (+bias): [8192,768] @ [768,768]^T
    gemm_nt<<<dim3(CH/128, MROWS/128), 256>>>(ob, proj_w, proj_b, out,
                                              MROWS, CH, CH);
}

// round 7
// speedup vs baseline: 1.5224x; 1.2962x over previous
#include <cuda_runtime.h>
#include <cuda_bf16.h>
#include <math_constants.h>
#include <cstdint>

#define NUMH 12
#define HD   64
#define BATCH 4
#define SEQ  2048
#define CH   768
#define MROWS (BATCH*SEQ)   // 8192

typedef unsigned long long u64;

// ---------------- packed f32x2 helpers (attention) -------------------------
__device__ __forceinline__ u64 dup2(float a) {
    u64 r; unsigned x = __float_as_uint(a);
    asm("mov.b64 %0, {%1, %2};" : "=l"(r) : "r"(x), "r"(x));
    return r;
}
__device__ __forceinline__ void fma2(u64& d, u64 a, u64 b) {
    asm("fma.rn.f32x2 %0, %1, %2, %0;" : "+l"(d) : "l"(a), "l"(b));
}
__device__ __forceinline__ void mul2(u64& d, u64 a) {
    asm("mul.rn.f32x2 %0, %0, %1;" : "+l"(d) : "l"(a));
}
__device__ __forceinline__ void unpack2(u64 v, float& lo, float& hi) {
    unsigned a, b;
    asm("mov.b64 {%0, %1}, %2;" : "=r"(a), "=r"(b) : "l"(v));
    lo = __uint_as_float(a); hi = __uint_as_float(b);
}

// ---------------- base-PTX tensor helpers (compute_80+, no 'a' needed) -----
__device__ __forceinline__ uint32_t smem_u32(const void* p) {
    uint32_t a;
    asm("{ .reg .u64 t; cvta.to.shared.u64 t, %1; cvt.u32.u64 %0, t; }"
        : "=r"(a) : "l"(p));
    return a;
}
__device__ __forceinline__ void cp16(uint32_t dst, const void* src) {
    asm volatile("cp.async.cg.shared.global [%0], [%1], 16;"
                 :: "r"(dst), "l"(src) : "memory");
}
__device__ __forceinline__ void cp_commit() {
    asm volatile("cp.async.commit_group;" ::: "memory");
}
template<int N>
__device__ __forceinline__ void cp_wait() {
    asm volatile("cp.async.wait_group %0;" :: "n"(N) : "memory");
}
__device__ __forceinline__ void ldsm4(uint32_t* r, uint32_t addr) {
    asm volatile("ldmatrix.sync.aligned.m8n8.x4.shared.b16 {%0,%1,%2,%3}, [%4];"
                 : "=r"(r[0]), "=r"(r[1]), "=r"(r[2]), "=r"(r[3]) : "r"(addr));
}
__device__ __forceinline__ void mma16816(float* d, const uint32_t* a,
                                         uint32_t b0, uint32_t b1) {
    asm volatile(
        "mma.sync.aligned.m16n8k16.row.col.f32.bf16.bf16.f32 "
        "{%0,%1,%2,%3}, {%4,%5,%6,%7}, {%8,%9}, {%0,%1,%2,%3};"
        : "+f"(d[0]), "+f"(d[1]), "+f"(d[2]), "+f"(d[3])
        : "r"(a[0]), "r"(a[1]), "r"(a[2]), "r"(a[3]), "r"(b0), "r"(b1));
}

// ---------------- scratch (device globals; no allocation allowed) ----------
__device__ float g_qkv[(size_t)MROWS * 3 * CH];          // [B*N, 2304]
__device__ float g_q  [(size_t)BATCH*NUMH*SEQ*HD];       // [B*H, N, D]
__device__ float g_k  [(size_t)BATCH*NUMH*SEQ*HD];
__device__ float g_v  [(size_t)BATCH*NUMH*SEQ*HD];
__device__ float g_o  [(size_t)MROWS * CH];              // [B*N, C] (pre-proj)

// bf16 hi/lo split buffers
__device__ __nv_bfloat16 g_xh[(size_t)MROWS * CH];
__device__ __nv_bfloat16 g_xl[(size_t)MROWS * CH];
__device__ __nv_bfloat16 g_wqh[(size_t)3 * CH * CH];
__device__ __nv_bfloat16 g_wql[(size_t)3 * CH * CH];
__device__ __nv_bfloat16 g_wph[(size_t)CH * CH];
__device__ __nv_bfloat16 g_wpl[(size_t)CH * CH];
__device__ __nv_bfloat16 g_oh[(size_t)MROWS * CH];
__device__ __nv_bfloat16 g_ol[(size_t)MROWS * CH];

// ---------------- fp32 -> bf16 hi/lo split ---------------------------------
__global__ __launch_bounds__(256) void cvt_split(
    const float* __restrict__ s, __nv_bfloat16* __restrict__ h,
    __nv_bfloat16* __restrict__ l, int n4)
{
    int i = blockIdx.x * 256 + threadIdx.x;
    if (i >= n4) return;
    float4 v = ((const float4*)s)[i];
    __nv_bfloat16 hx = __float2bfloat16(v.x);
    __nv_bfloat16 hy = __float2bfloat16(v.y);
    __nv_bfloat16 hz = __float2bfloat16(v.z);
    __nv_bfloat16 hw = __float2bfloat16(v.w);
    __nv_bfloat162 h0, h1, l0, l1;
    h0.x = hx; h0.y = hy; h1.x = hz; h1.y = hw;
    l0.x = __float2bfloat16(v.x - __bfloat162float(hx));
    l0.y = __float2bfloat16(v.y - __bfloat162float(hy));
    l1.x = __float2bfloat16(v.z - __bfloat162float(hz));
    l1.y = __float2bfloat16(v.w - __bfloat162float(hw));
    ((__nv_bfloat162*)h)[2*i]   = h0;
    ((__nv_bfloat162*)h)[2*i+1] = h1;
    ((__nv_bfloat162*)l)[2*i]   = l0;
    ((__nv_bfloat162*)l)[2*i+1] = l1;
}

// ---------------- HMMA GEMM: C[M,N] = A·Wᵀ, bf16 hi/lo 3-pass --------------
// BM=BN=128, BK=32, 256 threads (8 warps as 4m x 2n), cp.async double buffer.
#define BM 128
#define BN 128
#define BKK 32
#define TILE_B   (BM*BKK*2)          // 8192 B per tile
#define STG_B    (4*TILE_B)          // Ah,Al,Bh,Bl = 32768 B per stage
#define HSMEM    (2*STG_B)           // 65536 B

// swizzled byte offset within a [128 rows][32 bf16] tile
__device__ __forceinline__ uint32_t tswz(int row, int ch) {
    return (uint32_t)(row*64 + ((ch ^ ((row>>1)&3))<<4));
}

__global__ __launch_bounds__(256, 1) void hmma_gemm(
    const __nv_bfloat16* __restrict__ Ah, const __nv_bfloat16* __restrict__ Al,
    const __nv_bfloat16* __restrict__ Bh, const __nv_bfloat16* __restrict__ Bl,
    const float* __restrict__ bias, float* __restrict__ C,
    int K, int ldc)
{
    extern __shared__ char smx[];
    uint32_t sb = smem_u32(smx);
    int tid = threadIdx.x, lane = tid & 31, warp = tid >> 5;
    int wm = warp >> 1, wn = warp & 1;
    int bm = blockIdx.y * BM, bn = blockIdx.x * BN;

    const __nv_bfloat16* ApH = Ah + (size_t)bm * K;
    const __nv_bfloat16* ApL = Al + (size_t)bm * K;
    const __nv_bfloat16* BpH = Bh + (size_t)bn * K;
    const __nv_bfloat16* BpL = Bl + (size_t)bn * K;

    // loader per-thread coords (2 vectors per tile per stage)
    int r0 = tid >> 2, c0 = tid & 3;               // t=0: rows 0..63
    int r1 = r0 + 64;                              // t=1: rows 64..127
    uint32_t sw0 = tswz(r0, c0), sw1 = tswz(r1, c0);

    float acc[2][8][4];
    #pragma unroll
    for (int mt = 0; mt < 2; mt++)
        #pragma unroll
        for (int nt = 0; nt < 8; nt++)
            #pragma unroll
            for (int j = 0; j < 4; j++) acc[mt][nt][j] = 0.f;

    // ldmatrix per-lane row components
    int lrow8 = lane & 7, ghalf = (lane >> 3) & 1, ghi = lane >> 4;

    int NS = K / BKK;

    // ---- issue stage s into buffer b
    auto issue = [&](int s, int b) {
        uint32_t dst = sb + (uint32_t)b * STG_B;
        size_t ko = (size_t)s * BKK;
        size_t o0 = (size_t)r0 * K + ko + c0*8;
        size_t o1 = (size_t)r1 * K + ko + c0*8;
        cp16(dst + 0*TILE_B + sw0, ApH + o0);
        cp16(dst + 0*TILE_B + sw1, ApH + o1);
        cp16(dst + 1*TILE_B + sw0, ApL + o0);
        cp16(dst + 1*TILE_B + sw1, ApL + o1);
        cp16(dst + 2*TILE_B + sw0, BpH + o0);
        cp16(dst + 2*TILE_B + sw1, BpH + o1);
        cp16(dst + 3*TILE_B + sw0, BpL + o0);
        cp16(dst + 3*TILE_B + sw1, BpL + o1);
        cp_commit();
    };

    issue(0, 0);
    for (int s = 0; s < NS; ++s) {
        int b = s & 1;
        if (s + 1 < NS) { issue(s + 1, b ^ 1); cp_wait<1>(); }
        else cp_wait<0>();
        __syncthreads();

        uint32_t stg = sb + (uint32_t)b * STG_B;
        #pragma unroll
        for (int ks = 0; ks < 2; ++ks) {
            int kc = ks * 2;
            uint32_t fAh[2][4], fAl[2][4], fBh[4][4], fBl[4][4];
            #pragma unroll
            for (int mt = 0; mt < 2; mt++) {
                int r = wm*32 + mt*16 + lrow8 + ghalf*8;
                uint32_t ad = stg + tswz(r, kc + ghi);
                ldsm4(fAh[mt], ad);
                ldsm4(fAl[mt], ad + TILE_B);
            }
            #pragma unroll
            for (int t16 = 0; t16 < 4; t16++) {
                int r = wn*64 + t16*16 + lrow8 + ghalf*8;
                uint32_t ad = stg + 2*TILE_B + tswz(r, kc + ghi);
                ldsm4(fBh[t16], ad);
                ldsm4(fBl[t16], ad + TILE_B);
            }
            #pragma unroll
            for (int mt = 0; mt < 2; mt++)
                #pragma unroll
                for (int nt = 0; nt < 8; nt++) {
                    int t16 = nt >> 1, hi = nt & 1;
                    mma16816(acc[mt][nt], fAh[mt], fBh[t16][hi], fBh[t16][hi+2]);
                    mma16816(acc[mt][nt], fAh[mt], fBl[t16][hi], fBl[t16][hi+2]);
                    mma16816(acc[mt][nt], fAl[mt], fBh[t16][hi], fBh[t16][hi+2]);
                }
        }
        __syncthreads();
    }

    // ---- epilogue
    #pragma unroll
    for (int mt = 0; mt < 2; mt++) {
        int rlo = bm + wm*32 + mt*16 + (lane >> 2);
        int rhi = rlo + 8;
        #pragma unroll
        for (int nt = 0; nt < 8; nt++) {
            int col = bn + wn*64 + nt*8 + (lane & 3)*2;
            float b0 = 0.f, b1 = 0.f;
            if (bias) { b0 = bias[col]; b1 = bias[col+1]; }
            float2 vlo = {acc[mt][nt][0] + b0, acc[mt][nt][1] + b1};
            float2 vhi = {acc[mt][nt][2] + b0, acc[mt][nt][3] + b1};
            *(float2*)&C[(size_t)rlo * ldc + col] = vlo;
            *(float2*)&C[(size_t)rhi * ldc + col] = vhi;
        }
    }
}

// ---------- RMSnorm + RoPE + [B,N,3,H,D] -> [B*H,N,D] scatter --------------
__global__ __launch_bounds__(128) void prep_kernel(
    const float* __restrict__ qkv, const float* __restrict__ cs,
    const float* __restrict__ sn, const float* __restrict__ qw,
    const float* __restrict__ kw,
    float* __restrict__ qo, float* __restrict__ ko, float* __restrict__ vo)
{
    int task = blockIdx.x * 4 + (threadIdx.x >> 5);   // (b*H + h)*SEQ + n
    int lane = threadIdx.x & 31;
    int n  = task & (SEQ - 1);
    int bh = task >> 11;                              // SEQ = 2^11
    int h = bh % NUMH, b = bh / NUMH;

    const float* base = qkv + ((size_t)(b*SEQ + n)) * (3*CH) + h*HD;
    float q1 = base[lane],        q2 = base[lane+32];
    float k1 = base[CH+lane],     k2 = base[CH+lane+32];
    float v1 = base[2*CH+lane],   v2 = base[2*CH+lane+32];

    float sq = q1*q1 + q2*q2, sk = k1*k1 + k2*k2;
    #pragma unroll
    for (int o = 16; o >= 1; o >>= 1) {
        sq += __shfl_xor_sync(0xffffffffu, sq, o);
        sk += __shfl_xor_sync(0xffffffffu, sk, o);
    }
    float rq = rsqrtf(sq * (1.f/64.f) + 1e-6f);
    float rk = rsqrtf(sk * (1.f/64.f) + 1e-6f);
    q1 *= rq * qw[lane]; q2 *= rq * qw[lane+32];
    k1 *= rk * kw[lane]; k2 *= rk * kw[lane+32];

    float c = cs[n*32 + lane], s = sn[n*32 + lane];
    size_t o = ((size_t)bh * SEQ + n) * HD + lane;
    qo[o]    = q1*c - q2*s;  qo[o+32] = q2*c + q1*s;
    ko[o]    = k1*c - k2*s;  ko[o+32] = k2*c + k1*s;
    vo[o]    = v1;           vo[o+32] = v2;
}

// ---------------- flash attention: 128q x 64k tiles, f32x2 -----------------
#define PADQ 132
#define PADK 68
__global__ __launch_bounds__(256, 2) void attn_kernel(
    const float* __restrict__ Q, const float* __restrict__ K,
    const float* __restrict__ V, float* __restrict__ O)
{
    extern __shared__ float sm[];
    float* Qst = sm;                       // [64][PADQ]  (d-major, scaled)
    float* Kst = Qst + 64*PADQ;            // [64][PADK]  (d-major)
    float* Vs  = Kst + 64*PADK;            // [64][PADK]  (k-major)
    float* Pst = Vs  + 64*PADK;            // [64][PADQ]  (k-major)

    int tid = threadIdx.x;
    int tx = tid & 15, ty = tid >> 4;      // 16 x 16
    int qt = blockIdx.x, bh = blockIdx.y;

    const float scale = 0.125f;            // 64^-0.5
    const float* Qb = Q + ((size_t)bh * SEQ + qt*128) * HD;
    const float* Kb = K + (size_t)bh * SEQ * HD;
    const float* Vb = V + (size_t)bh * SEQ * HD;

    {
        int r = tid >> 1, db = (tid & 1) * 32;
        const float* src = Qb + (size_t)r * HD + db;
        #pragma unroll
        for (int c = 0; c < 32; c += 4) {
            float4 v = *(const float4*)(src + c);
            Qst[(db+c+0)*PADQ + r] = v.x * scale;
            Qst[(db+c+1)*PADQ + r] = v.y * scale;
            Qst[(db+c+2)*PADQ + r] = v.z * scale;
            Qst[(db+c+3)*PADQ + r] = v.w * scale;
        }
    }

    float m[8], l[8];
    u64 o2[8][2];
    #pragma unroll
    for (int i = 0; i < 8; i++) {
        m[i] = -CUDART_INF_F; l[i] = 0.f;
        o2[i][0] = 0ull; o2[i][1] = 0ull;
    }

    int kr = tid >> 2, kcb = (tid & 3) * 4;

    for (int kt = 0; kt < SEQ/64; ++kt) {
        const float* Ksrc = Kb + (size_t)(kt*64 + kr) * HD + kcb;
        const float* Vsrc = Vb + (size_t)(kt*64 + kr) * HD + kcb;
        #pragma unroll
        for (int c = 0; c < 64; c += 16) {
            float4 vk = *(const float4*)(Ksrc + c);
            Kst[(kcb+c+0)*PADK + kr] = vk.x;
            Kst[(kcb+c+1)*PADK + kr] = vk.y;
            Kst[(kcb+c+2)*PADK + kr] = vk.z;
            Kst[(kcb+c+3)*PADK + kr] = vk.w;
            float4 vv = *(const float4*)(Vsrc + c);
            *(float4*)&Vs[kr*PADK + kcb + c] = vv;
        }
        __syncthreads();

        u64 s2[8][2];
        #pragma unroll
        for (int i = 0; i < 8; i++) { s2[i][0] = 0ull; s2[i][1] = 0ull; }
        #pragma unroll 8
        for (int d = 0; d < 64; ++d) {
            float4 a0 = *(const float4*)&Qst[d*PADQ + ty*8];
            float4 a1 = *(const float4*)&Qst[d*PADQ + ty*8 + 4];
            u64 ad[8];
            ad[0]=dup2(a0.x); ad[1]=dup2(a0.y); ad[2]=dup2(a0.z); ad[3]=dup2(a0.w);
            ad[4]=dup2(a1.x); ad[5]=dup2(a1.y); ad[6]=dup2(a1.z); ad[7]=dup2(a1.w);
            ulonglong2 bv = *(const ulonglong2*)&Kst[d*PADK + tx*4];
            #pragma unroll
            for (int i = 0; i < 8; i++) {
                fma2(s2[i][0], ad[i], bv.x);
                fma2(s2[i][1], ad[i], bv.y);
            }
        }

        float s[8][4];
        #pragma unroll
        for (int i = 0; i < 8; i++) {
            unpack2(s2[i][0], s[i][0], s[i][1]);
            unpack2(s2[i][1], s[i][2], s[i][3]);
        }
        #pragma unroll
        for (int i = 0; i < 8; i++) {
            float r = fmaxf(fmaxf(s[i][0], s[i][1]), fmaxf(s[i][2], s[i][3]));
            #pragma unroll
            for (int off = 8; off >= 1; off >>= 1)
                r = fmaxf(r, __shfl_xor_sync(0xffffffffu, r, off));
            float mn = fmaxf(m[i], r);
            float al = __expf(m[i] - mn);
            m[i] = mn;
            float rs = 0.f;
            #pragma unroll
            for (int j = 0; j < 4; j++) {
                float p = __expf(s[i][j] - mn);
                s[i][j] = p; rs += p;
            }
            #pragma unroll
            for (int off = 8; off >= 1; off >>= 1)
                rs += __shfl_xor_sync(0xffffffffu, rs, off);
            l[i] = l[i]*al + rs;
            u64 a2 = dup2(al);
            mul2(o2[i][0], a2);
            mul2(o2[i][1], a2);
        }

        #pragma unroll
        for (int j = 0; j < 4; j++) {
            float4 p0 = {s[0][j], s[1][j], s[2][j], s[3][j]};
            float4 p1 = {s[4][j], s[5][j], s[6][j], s[7][j]};
            float* dst = &Pst[(tx*4 + j)*PADQ + ty*8];
            *(float4*)(dst)     = p0;
            *(float4*)(dst + 4) = p1;
        }
        __syncthreads();

        #pragma unroll 8
        for (int kk = 0; kk < 64; ++kk) {
            float4 a0 = *(const float4*)&Pst[kk*PADQ + ty*8];
            float4 a1 = *(const float4*)&Pst[kk*PADQ + ty*8 + 4];
            u64 ad[8];
            ad[0]=dup2(a0.x); ad[1]=dup2(a0.y); ad[2]=dup2(a0.z); ad[3]=dup2(a0.w);
            ad[4]=dup2(a1.x); ad[5]=dup2(a1.y); ad[6]=dup2(a1.z); ad[7]=dup2(a1.w);
            ulonglong2 bv = *(const ulonglong2*)&Vs[kk*PADK + tx*4];
            #pragma unroll
            for (int i = 0; i < 8; i++) {
                fma2(o2[i][0], ad[i], bv.x);
                fma2(o2[i][1], ad[i], bv.y);
            }
        }
        __syncthreads();
    }

    int b_ = bh / NUMH, h_ = bh % NUMH;
    #pragma unroll
    for (int i = 0; i < 8; i++) {
        float inv = 1.f / l[i];
        float c0, c1, c2, c3;
        unpack2(o2[i][0], c0, c1);
        unpack2(o2[i][1], c2, c3);
        float4 r = {c0*inv, c1*inv, c2*inv, c3*inv};
        size_t row = (size_t)(b_*SEQ + qt*128 + ty*8 + i);
        *(float4*)&O[row*CH + h_*HD + tx*4] = r;
    }
}

// ---------------------------------------------------------------------------
extern "C" void kernel_launch(void* const* d_in, const int* in_sizes, int n_in,
                              void* d_out, int out_size)
{
    const float* x      = (const float*)d_in[0];
    const float* cs     = (const float*)d_in[1];
    const float* sn     = (const float*)d_in[2];
    const float* qkv_w  = (const float*)d_in[3];
    const float* qnw    = (const float*)d_in[4];
    const float* knw    = (const float*)d_in[5];
    const float* proj_w = (const float*)d_in[6];
    const float* proj_b = (const float*)d_in[7];
    float* out = (float*)d_out;

    float *qkv, *qb, *kb, *vb, *ob;
    cudaGetSymbolAddress((void**)&qkv, g_qkv);
    cudaGetSymbolAddress((void**)&qb,  g_q);
    cudaGetSymbolAddress((void**)&kb,  g_k);
    cudaGetSymbolAddress((void**)&vb,  g_v);
    cudaGetSymbolAddress((void**)&ob,  g_o);
    __nv_bfloat16 *xh, *xl, *wqh, *wql, *wph, *wpl, *oh, *ol;
    cudaGetSymbolAddress((void**)&xh,  g_xh);
    cudaGetSymbolAddress((void**)&xl,  g_xl);
    cudaGetSymbolAddress((void**)&wqh, g_wqh);
    cudaGetSymbolAddress((void**)&wql, g_wql);
    cudaGetSymbolAddress((void**)&wph, g_wph);
    cudaGetSymbolAddress((void**)&wpl, g_wpl);
    cudaGetSymbolAddress((void**)&oh,  g_oh);
    cudaGetSymbolAddress((void**)&ol,  g_ol);

    // 0) split inputs/weights into bf16 hi/lo
    {
        int n4x = MROWS*CH/4, n4q = 3*CH*CH/4, n4p = CH*CH/4;
        cvt_split<<<(n4x+255)/256, 256>>>(x, xh, xl, n4x);
        cvt_split<<<(n4q+255)/256, 256>>>(qkv_w, wqh, wql, n4q);
        cvt_split<<<(n4p+255)/256, 256>>>(proj_w, wph, wpl, n4p);
    }

    // 1) QKV projection: [8192,768] @ [2304,768]^T  (HMMA, 3-pass split)
    cudaFuncSetAttribute(hmma_gemm, cudaFuncAttributeMaxDynamicSharedMemorySize,
                         HSMEM);
    hmma_gemm<<<dim3(3*CH/BN, MROWS/BM), 256, HSMEM>>>(
        xh, xl, wqh, wql, nullptr, qkv, CH, 3*CH);

    // 2) RMSnorm + RoPE + scatter to [B*H,N,D]
    prep_kernel<<<(BATCH*NUMH*SEQ)/4, 128>>>(qkv, cs, sn, qnw, knw, qb, kb, vb);

    // 3) flash attention (128q x 64k tiles, f32x2)
    const int smem = (64*PADQ + 64*PADK + 64*PADK + 64*PADQ) * sizeof(float);
    cudaFuncSetAttribute(attn_kernel, cudaFuncAttributeMaxDynamicSharedMemorySize, smem);
    attn_kernel<<<dim3(SEQ/128, BATCH*NUMH), 256, smem>>>(qb, kb, vb, ob);

    // 4) split attention output, then proj (+bias) via HMMA
    {
        int n4o = MROWS*CH/4;
        cvt_split<<<(n4o+255)/256, 256>>>(ob, oh, ol, n4o);
    }
    hmma_gemm<<<dim3(CH/BN, MROWS/BM), 256, HSMEM>>>(
        oh, ol, wph, wpl, proj_b, out, CH, CH);
}

// round 11
// speedup vs baseline: 3.1152x; 2.0462x over previous
#include <cuda_runtime.h>
#include <cuda_bf16.h>
#include <math_constants.h>
#include <cstdint>

#define NUMH 12
#define HD   64
#define BATCH 4
#define SEQ  2048
#define CH   768
#define MROWS (BATCH*SEQ)   // 8192
#define NBH  (BATCH*NUMH)   // 48

// ---------------- base-PTX tensor helpers (compute_80+) --------------------
__device__ __forceinline__ uint32_t smem_u32(const void* p) {
    uint32_t a;
    asm("{ .reg .u64 t; cvta.to.shared.u64 t, %1; cvt.u32.u64 %0, t; }"
        : "=r"(a) : "l"(p));
    return a;
}
__device__ __forceinline__ void cp16(uint32_t dst, const void* src) {
    asm volatile("cp.async.cg.shared.global [%0], [%1], 16;"
                 :: "r"(dst), "l"(src) : "memory");
}
__device__ __forceinline__ void cp_commit() {
    asm volatile("cp.async.commit_group;" ::: "memory");
}
template<int N>
__device__ __forceinline__ void cp_wait() {
    asm volatile("cp.async.wait_group %0;" :: "n"(N) : "memory");
}
__device__ __forceinline__ void ldsm4(uint32_t* r, uint32_t addr) {
    asm volatile("ldmatrix.sync.aligned.m8n8.x4.shared.b16 {%0,%1,%2,%3}, [%4];"
                 : "=r"(r[0]), "=r"(r[1]), "=r"(r[2]), "=r"(r[3]) : "r"(addr));
}
__device__ __forceinline__ void ldsm4t(uint32_t* r, uint32_t addr) {
    asm volatile("ldmatrix.sync.aligned.m8n8.x4.trans.shared.b16 {%0,%1,%2,%3}, [%4];"
                 : "=r"(r[0]), "=r"(r[1]), "=r"(r[2]), "=r"(r[3]) : "r"(addr));
}
__device__ __forceinline__ void mma16816(float* d, const uint32_t* a,
                                         uint32_t b0, uint32_t b1) {
    asm volatile(
        "mma.sync.aligned.m16n8k16.row.col.f32.bf16.bf16.f32 "
        "{%0,%1,%2,%3}, {%4,%5,%6,%7}, {%8,%9}, {%0,%1,%2,%3};"
        : "+f"(d[0]), "+f"(d[1]), "+f"(d[2]), "+f"(d[3])
        : "r"(a[0]), "r"(a[1]), "r"(a[2]), "r"(a[3]), "r"(b0), "r"(b1));
}
__device__ __forceinline__ uint32_t packbf(float lo, float hi) {
    uint32_t r;
    asm("cvt.rn.bf16x2.f32 %0, %1, %2;" : "=r"(r) : "f"(hi), "f"(lo));
    return r;
}
__device__ __forceinline__ float bflo(float f) {
    return f - __bfloat162float(__float2bfloat16(f));
}

// ---------------- scratch (device globals; no allocation allowed) ----------
__device__ float g_qkv[(size_t)MROWS * 3 * CH];          // [B*N, 2304]

// bf16 split weight/activation buffers
__device__ __nv_bfloat16 g_xh[(size_t)MROWS * CH];
__device__ __nv_bfloat16 g_xl[(size_t)MROWS * CH];
__device__ __nv_bfloat16 g_wqh[(size_t)3 * CH * CH];
__device__ __nv_bfloat16 g_wql[(size_t)3 * CH * CH];
__device__ __nv_bfloat16 g_wph[(size_t)CH * CH];
__device__ __nv_bfloat16 g_wpl[(size_t)CH * CH];

// attention operands bf16 hi/lo
__device__ __nv_bfloat16 g_qh[(size_t)NBH*SEQ*HD];
__device__ __nv_bfloat16 g_ql[(size_t)NBH*SEQ*HD];
__device__ __nv_bfloat16 g_kh[(size_t)NBH*SEQ*HD];
__device__ __nv_bfloat16 g_kl[(size_t)NBH*SEQ*HD];
__device__ __nv_bfloat16 g_vh[(size_t)NBH*SEQ*HD];
__device__ __nv_bfloat16 g_vl[(size_t)NBH*SEQ*HD];

// attention output split (proj A operand)
__device__ __nv_bfloat16 g_oh[(size_t)MROWS * CH];
__device__ __nv_bfloat16 g_ol[(size_t)MROWS * CH];

// ---------------- fp32 -> bf16 hi/lo split ---------------------------------
__global__ __launch_bounds__(256) void cvt_split(
    const float* __restrict__ s, __nv_bfloat16* __restrict__ h,
    __nv_bfloat16* __restrict__ l, int n4)
{
    int i = blockIdx.x * 256 + threadIdx.x;
    if (i >= n4) return;
    float4 v = ((const float4*)s)[i];
    __nv_bfloat16 hx = __float2bfloat16(v.x);
    __nv_bfloat16 hy = __float2bfloat16(v.y);
    __nv_bfloat16 hz = __float2bfloat16(v.z);
    __nv_bfloat16 hw = __float2bfloat16(v.w);
    __nv_bfloat162 h0, h1, l0, l1;
    h0.x = hx; h0.y = hy; h1.x = hz; h1.y = hw;
    l0.x = __float2bfloat16(v.x - __bfloat162float(hx));
    l0.y = __float2bfloat16(v.y - __bfloat162float(hy));
    l1.x = __float2bfloat16(v.z - __bfloat162float(hz));
    l1.y = __float2bfloat16(v.w - __bfloat162float(hw));
    ((__nv_bfloat162*)h)[2*i]   = h0;
    ((__nv_bfloat162*)h)[2*i+1] = h1;
    ((__nv_bfloat162*)l)[2*i]   = l0;
    ((__nv_bfloat162*)l)[2*i+1] = l1;
}

// ---------------- HMMA GEMM: C[M,N] = A·Wᵀ, bf16 hi/lo 3-pass --------------
#define BM 128
#define BN 128
#define BKK 32
#define TILE_B   (BM*BKK*2)          // 8192 B per tile
#define STG_B    (4*TILE_B)          // 32768 B per stage
#define HSMEM    (2*STG_B)           // 65536 B

__device__ __forceinline__ uint32_t tswz(int row, int ch) {
    return (uint32_t)(row*64 + ((ch ^ ((row>>1)&3))<<4));
}

__global__ __launch_bounds__(256, 2) void hmma_gemm(
    const __nv_bfloat16* __restrict__ Ah, const __nv_bfloat16* __restrict__ Al,
    const __nv_bfloat16* __restrict__ Bh, const __nv_bfloat16* __restrict__ Bl,
    const float* __restrict__ bias, float* __restrict__ C,
    int K, int ldc)
{
    extern __shared__ char smx[];
    uint32_t sb = smem_u32(smx);
    int tid = threadIdx.x, lane = tid & 31, warp = tid >> 5;
    int wm = warp >> 1, wn = warp & 1;
    int bm = blockIdx.y * BM, bn = blockIdx.x * BN;

    const __nv_bfloat16* ApH = Ah + (size_t)bm * K;
    const __nv_bfloat16* ApL = Al + (size_t)bm * K;
    const __nv_bfloat16* BpH = Bh + (size_t)bn * K;
    const __nv_bfloat16* BpL = Bl + (size_t)bn * K;

    int r0 = tid >> 2, c0 = tid & 3;
    int r1 = r0 + 64;
    uint32_t sw0 = tswz(r0, c0), sw1 = tswz(r1, c0);

    float acc[2][8][4];
    #pragma unroll
    for (int mt = 0; mt < 2; mt++)
        #pragma unroll
        for (int nt = 0; nt < 8; nt++)
            #pragma unroll
            for (int j = 0; j < 4; j++) acc[mt][nt][j] = 0.f;

    int lrow8 = lane & 7, ghalf = (lane >> 3) & 1, ghi = lane >> 4;
    int NS = K / BKK;

    auto issue = [&](int s, int b) {
        uint32_t dst = sb + (uint32_t)b * STG_B;
        size_t ko = (size_t)s * BKK;
        size_t o0 = (size_t)r0 * K + ko + c0*8;
        size_t o1 = (size_t)r1 * K + ko + c0*8;
        cp16(dst + 0*TILE_B + sw0, ApH + o0);
        cp16(dst + 0*TILE_B + sw1, ApH + o1);
        cp16(dst + 1*TILE_B + sw0, ApL + o0);
        cp16(dst + 1*TILE_B + sw1, ApL + o1);
        cp16(dst + 2*TILE_B + sw0, BpH + o0);
        cp16(dst + 2*TILE_B + sw1, BpH + o1);
        cp16(dst + 3*TILE_B + sw0, BpL + o0);
        cp16(dst + 3*TILE_B + sw1, BpL + o1);
        cp_commit();
    };

    issue(0, 0);
    for (int s = 0; s < NS; ++s) {
        int b = s & 1;
        if (s + 1 < NS) { issue(s + 1, b ^ 1); cp_wait<1>(); }
        else cp_wait<0>();
        __syncthreads();

        uint32_t stg = sb + (uint32_t)b * STG_B;
        #pragma unroll
        for (int ks = 0; ks < 2; ++ks) {
            int kc = ks * 2;
            uint32_t fAh[2][4], fAl[2][4], fBh[4][4], fBl[4][4];
            #pragma unroll
            for (int mt = 0; mt < 2; mt++) {
                int r = wm*32 + mt*16 + lrow8 + ghalf*8;
                uint32_t ad = stg + tswz(r, kc + ghi);
                ldsm4(fAh[mt], ad);
                ldsm4(fAl[mt], ad + TILE_B);
            }
            #pragma unroll
            for (int t16 = 0; t16 < 4; t16++) {
                int r = wn*64 + t16*16 + lrow8 + ghalf*8;
                uint32_t ad = stg + 2*TILE_B + tswz(r, kc + ghi);
                ldsm4(fBh[t16], ad);
                ldsm4(fBl[t16], ad + TILE_B);
            }
            #pragma unroll
            for (int mt = 0; mt < 2; mt++)
                #pragma unroll
                for (int nt = 0; nt < 8; nt++) {
                    int t16 = nt >> 1, hi = nt & 1;
                    mma16816(acc[mt][nt], fAh[mt], fBh[t16][hi], fBh[t16][hi+2]);
                    mma16816(acc[mt][nt], fAh[mt], fBl[t16][hi], fBl[t16][hi+2]);
                    mma16816(acc[mt][nt], fAl[mt], fBh[t16][hi], fBh[t16][hi+2]);
                }
        }
        __syncthreads();
    }

    #pragma unroll
    for (int mt = 0; mt < 2; mt++) {
        int rlo = bm + wm*32 + mt*16 + (lane >> 2);
        int rhi = rlo + 8;
        #pragma unroll
        for (int nt = 0; nt < 8; nt++) {
            int col = bn + wn*64 + nt*8 + (lane & 3)*2;
            float b0 = 0.f, b1 = 0.f;
            if (bias) { b0 = bias[col]; b1 = bias[col+1]; }
            float2 vlo = {acc[mt][nt][0] + b0, acc[mt][nt][1] + b1};
            float2 vhi = {acc[mt][nt][2] + b0, acc[mt][nt][3] + b1};
            *(float2*)&C[(size_t)rlo * ldc + col] = vlo;
            *(float2*)&C[(size_t)rhi * ldc + col] = vhi;
        }
    }
}

// ---------- RMSnorm + RoPE + split -> bf16 [B*H,N,D] -----------------------
__global__ __launch_bounds__(128) void prep_kernel(
    const float* __restrict__ qkv, const float* __restrict__ cs,
    const float* __restrict__ sn, const float* __restrict__ qw,
    const float* __restrict__ kw,
    __nv_bfloat16* __restrict__ qh, __nv_bfloat16* __restrict__ ql,
    __nv_bfloat16* __restrict__ kh, __nv_bfloat16* __restrict__ kl,
    __nv_bfloat16* __restrict__ vh, __nv_bfloat16* __restrict__ vl)
{
    int task = blockIdx.x * 4 + (threadIdx.x >> 5);   // (b*H + h)*SEQ + n
    int lane = threadIdx.x & 31;
    int n  = task & (SEQ - 1);
    int bh = task >> 11;
    int h = bh % NUMH, b = bh / NUMH;

    const float* base = qkv + ((size_t)(b*SEQ + n)) * (3*CH) + h*HD;
    float q1 = base[lane],        q2 = base[lane+32];
    float k1 = base[CH+lane],     k2 = base[CH+lane+32];
    float v1 = base[2*CH+lane],   v2 = base[2*CH+lane+32];

    float sq = q1*q1 + q2*q2, sk = k1*k1 + k2*k2;
    #pragma unroll
    for (int o = 16; o >= 1; o >>= 1) {
        sq += __shfl_xor_sync(0xffffffffu, sq, o);
        sk += __shfl_xor_sync(0xffffffffu, sk, o);
    }
    float rq = rsqrtf(sq * (1.f/64.f) + 1e-6f) * 0.125f;   // fold attn scale into q
    float rk = rsqrtf(sk * (1.f/64.f) + 1e-6f);
    q1 *= rq * qw[lane]; q2 *= rq * qw[lane+32];
    k1 *= rk * kw[lane]; k2 *= rk * kw[lane+32];

    float c = cs[n*32 + lane], s = sn[n*32 + lane];
    float qa = q1*c - q2*s, qb2 = q2*c + q1*s;
    float ka = k1*c - k2*s, kb2 = k2*c + k1*s;

    size_t o = ((size_t)bh * SEQ + n) * HD + lane;
    __nv_bfloat16 t;
    t = __float2bfloat16(qa);  qh[o] = t;    ql[o]    = __float2bfloat16(qa - __bfloat162float(t));
    t = __float2bfloat16(qb2); qh[o+32] = t; ql[o+32] = __float2bfloat16(qb2 - __bfloat162float(t));
    t = __float2bfloat16(ka);  kh[o] = t;    kl[o]    = __float2bfloat16(ka - __bfloat162float(t));
    t = __float2bfloat16(kb2); kh[o+32] = t; kl[o+32] = __float2bfloat16(kb2 - __bfloat162float(t));
    t = __float2bfloat16(v1);  vh[o] = t;    vl[o]    = __float2bfloat16(v1 - __bfloat162float(t));
    t = __float2bfloat16(v2);  vh[o+32] = t; vl[o+32] = __float2bfloat16(v2 - __bfloat162float(t));
}

// ---------------- flash attention via HMMA ---------------------------------
// 128 q x 64 k tiles. 8 warps, each owns 16 q rows. 3-pass QK, 3-pass PV.
#define AQ 128
#define AK 64
#define ANT (SEQ/AK)            // 32
#define QH_OFF 0
#define QL_OFF (AQ*128)         // 16384
#define ASTG0  (2*AQ*128)       // 32768
#define KH_O 0
#define KL_O (AK*128)           // 8192
#define VH_O (2*AK*128)         // 16384
#define VL_O (3*AK*128)         // 24576
#define ASTG (4*AK*128)         // 32768
#define ASMEM (ASTG0 + 2*ASTG)  // 98304

__device__ __forceinline__ uint32_t swz(int row, int ch) {
    return (uint32_t)(row*128 + ((ch ^ (row & 7)) << 4));
}

__global__ __launch_bounds__(256, 2) void attn_mma(
    const __nv_bfloat16* __restrict__ Qh, const __nv_bfloat16* __restrict__ Ql,
    const __nv_bfloat16* __restrict__ Kh, const __nv_bfloat16* __restrict__ Kl,
    const __nv_bfloat16* __restrict__ Vh, const __nv_bfloat16* __restrict__ Vl,
    __nv_bfloat16* __restrict__ Oh, __nv_bfloat16* __restrict__ Ol)
{
    extern __shared__ char smx[];
    uint32_t sb = smem_u32(smx);
    int tid = threadIdx.x, lane = tid & 31, warp = tid >> 5;
    int qt = blockIdx.x, bh = blockIdx.y;

    const __nv_bfloat16* Qhb = Qh + ((size_t)bh*SEQ + qt*AQ) * HD;
    const __nv_bfloat16* Qlb = Ql + ((size_t)bh*SEQ + qt*AQ) * HD;
    const __nv_bfloat16* Khb = Kh + (size_t)bh*SEQ*HD;
    const __nv_bfloat16* Klb = Kl + (size_t)bh*SEQ*HD;
    const __nv_bfloat16* Vhb = Vh + (size_t)bh*SEQ*HD;
    const __nv_bfloat16* Vlb = Vl + (size_t)bh*SEQ*HD;

    auto issueKV = [&](int s, int b) {
        uint32_t dst = sb + ASTG0 + (uint32_t)b * ASTG;
        #pragma unroll
        for (int t = 0; t < 2; ++t) {
            int v = tid + t*256;
            int row = v >> 3, ch = v & 7;
            size_t go = (size_t)(s*AK + row) * HD + ch*8;
            uint32_t so = swz(row, ch);
            cp16(dst + KH_O + so, Khb + go);
            cp16(dst + KL_O + so, Klb + go);
            cp16(dst + VH_O + so, Vhb + go);
            cp16(dst + VL_O + so, Vlb + go);
        }
        cp_commit();
    };

    // load Q (both tiles) + stage 0 in group 0
    {
        #pragma unroll
        for (int t = 0; t < 4; ++t) {
            int v = tid + t*256;
            int row = v >> 3, ch = v & 7;
            size_t go = (size_t)row * HD + ch*8;
            uint32_t so = swz(row, ch);
            cp16(sb + QH_OFF + so, Qhb + go);
            cp16(sb + QL_OFF + so, Qlb + go);
        }
        #pragma unroll
        for (int t = 0; t < 2; ++t) {
            int v = tid + t*256;
            int row = v >> 3, ch = v & 7;
            size_t go = (size_t)row * HD + ch*8;
            uint32_t so = swz(row, ch);
            cp16(sb + ASTG0 + KH_O + so, Khb + go);
            cp16(sb + ASTG0 + KL_O + so, Klb + go);
            cp16(sb + ASTG0 + VH_O + so, Vhb + go);
            cp16(sb + ASTG0 + VL_O + so, Vlb + go);
        }
        cp_commit();
    }
    issueKV(1, 1);

    int lrow8 = lane & 7, ghalf = (lane >> 3) & 1, ghi = lane >> 4;
    int arow = warp*16 + lrow8 + ghalf*8;

    float m0 = -CUDART_INF_F, m1 = -CUDART_INF_F, sl0 = 0.f, sl1 = 0.f;
    float o[8][4];
    #pragma unroll
    for (int j = 0; j < 8; j++)
        #pragma unroll
        for (int t = 0; t < 4; t++) o[j][t] = 0.f;

    for (int kt = 0; kt < ANT; ++kt) {
        cp_wait<1>();
        __syncthreads();
        uint32_t stg = sb + ASTG0 + (uint32_t)(kt & 1) * ASTG;

        // ---- S = Q Kᵀ (3-pass)
        float s[8][4];
        #pragma unroll
        for (int j = 0; j < 8; j++)
            #pragma unroll
            for (int t = 0; t < 4; t++) s[j][t] = 0.f;
        #pragma unroll
        for (int ks = 0; ks < 4; ++ks) {
            uint32_t aH[4], aL[4];
            uint32_t qa = swz(arow, ks*2 + ghi);
            ldsm4(aH, sb + QH_OFF + qa);
            ldsm4(aL, sb + QL_OFF + qa);
            #pragma unroll
            for (int nt = 0; nt < 4; ++nt) {
                uint32_t bH[4], bL[4];
                uint32_t ka = swz(nt*16 + lrow8 + ghalf*8, ks*2 + ghi);
                ldsm4(bH, stg + KH_O + ka);
                ldsm4(bL, stg + KL_O + ka);
                mma16816(s[nt*2],   aH, bH[0], bH[2]);
                mma16816(s[nt*2+1], aH, bH[1], bH[3]);
                mma16816(s[nt*2],   aH, bL[0], bL[2]);
                mma16816(s[nt*2+1], aH, bL[1], bL[3]);
                mma16816(s[nt*2],   aL, bH[0], bH[2]);
                mma16816(s[nt*2+1], aL, bH[1], bH[3]);
            }
        }

        // ---- online softmax (rows r and r+8)
        float mx0 = -CUDART_INF_F, mx1 = -CUDART_INF_F;
        #pragma unroll
        for (int j = 0; j < 8; j++) {
            mx0 = fmaxf(mx0, fmaxf(s[j][0], s[j][1]));
            mx1 = fmaxf(mx1, fmaxf(s[j][2], s[j][3]));
        }
        mx0 = fmaxf(mx0, __shfl_xor_sync(0xffffffffu, mx0, 1));
        mx0 = fmaxf(mx0, __shfl_xor_sync(0xffffffffu, mx0, 2));
        mx1 = fmaxf(mx1, __shfl_xor_sync(0xffffffffu, mx1, 1));
        mx1 = fmaxf(mx1, __shfl_xor_sync(0xffffffffu, mx1, 2));
        float nm0 = fmaxf(m0, mx0), nm1 = fmaxf(m1, mx1);
        float al0 = __expf(m0 - nm0), al1 = __expf(m1 - nm1);
        m0 = nm0; m1 = nm1;
        float rs0 = 0.f, rs1 = 0.f;
        #pragma unroll
        for (int j = 0; j < 8; j++) {
            s[j][0] = __expf(s[j][0] - nm0); rs0 += s[j][0];
            s[j][1] = __expf(s[j][1] - nm0); rs0 += s[j][1];
            s[j][2] = __expf(s[j][2] - nm1); rs1 += s[j][2];
            s[j][3] = __expf(s[j][3] - nm1); rs1 += s[j][3];
        }
        rs0 += __shfl_xor_sync(0xffffffffu, rs0, 1);
        rs0 += __shfl_xor_sync(0xffffffffu, rs0, 2);
        rs1 += __shfl_xor_sync(0xffffffffu, rs1, 1);
        rs1 += __shfl_xor_sync(0xffffffffu, rs1, 2);
        sl0 = sl0*al0 + rs0;
        sl1 = sl1*al1 + rs1;
        #pragma unroll
        for (int j = 0; j < 8; j++) {
            o[j][0] *= al0; o[j][1] *= al0;
            o[j][2] *= al1; o[j][3] *= al1;
        }

        // ---- O += P V (3-pass: Ph·Vh + Ph·Vl + Pl·Vh)
        #pragma unroll
        for (int ks = 0; ks < 4; ++ks) {
            // pack P hi and residual-lo fragments for this 16-k chunk
            uint32_t ph[4], pl[4];
            ph[0] = packbf(s[2*ks][0],   s[2*ks][1]);
            ph[1] = packbf(s[2*ks][2],   s[2*ks][3]);
            ph[2] = packbf(s[2*ks+1][0], s[2*ks+1][1]);
            ph[3] = packbf(s[2*ks+1][2], s[2*ks+1][3]);
            pl[0] = packbf(bflo(s[2*ks][0]),   bflo(s[2*ks][1]));
            pl[1] = packbf(bflo(s[2*ks][2]),   bflo(s[2*ks][3]));
            pl[2] = packbf(bflo(s[2*ks+1][0]), bflo(s[2*ks+1][1]));
            pl[3] = packbf(bflo(s[2*ks+1][2]), bflo(s[2*ks+1][3]));

            int vrow = ks*16 + lrow8 + ghalf*8;
            #pragma unroll
            for (int nb2 = 0; nb2 < 4; ++nb2) {
                uint32_t vH[4], vL[4];
                uint32_t va = swz(vrow, nb2*2 + ghi);
                ldsm4t(vH, stg + VH_O + va);
                ldsm4t(vL, stg + VL_O + va);
                mma16816(o[nb2*2],   ph, vH[0], vH[1]);
                mma16816(o[nb2*2+1], ph, vH[2], vH[3]);
                mma16816(o[nb2*2],   ph, vL[0], vL[1]);
                mma16816(o[nb2*2+1], ph, vL[2], vL[3]);
                mma16816(o[nb2*2],   pl, vH[0], vH[1]);
                mma16816(o[nb2*2+1], pl, vH[2], vH[3]);
            }
        }
        __syncthreads();
        if (kt + 2 < ANT) issueKV(kt + 2, kt & 1);
    }

    // ---- epilogue: normalize, split to bf16 hi/lo, write [B,N,C]
    int b_ = bh / NUMH, h_ = bh % NUMH;
    int r0 = warp*16 + (lane >> 2);
    size_t row0 = (size_t)b_*SEQ + qt*AQ + r0;
    size_t row1 = row0 + 8;
    float inv0 = 1.f / sl0, inv1 = 1.f / sl1;
    #pragma unroll
    for (int j = 0; j < 8; j++) {
        int col = h_*HD + j*8 + (lane & 3)*2;
        float f0 = o[j][0]*inv0, f1 = o[j][1]*inv0;
        float f2 = o[j][2]*inv1, f3 = o[j][3]*inv1;
        __nv_bfloat162 hh, ll;
        hh.x = __float2bfloat16(f0); hh.y = __float2bfloat16(f1);
        ll.x = __float2bfloat16(f0 - __bfloat162float(hh.x));
        ll.y = __float2bfloat16(f1 - __bfloat162float(hh.y));
        *(__nv_bfloat162*)&Oh[row0*CH + col] = hh;
        *(__nv_bfloat162*)&Ol[row0*CH + col] = ll;
        hh.x = __float2bfloat16(f2); hh.y = __float2bfloat16(f3);
        ll.x = __float2bfloat16(f2 - __bfloat162float(hh.x));
        ll.y = __float2bfloat16(f3 - __bfloat162float(hh.y));
        *(__nv_bfloat162*)&Oh[row1*CH + col] = hh;
        *(__nv_bfloat162*)&Ol[row1*CH + col] = ll;
    }
}

// ---------------------------------------------------------------------------
extern "C" void kernel_launch(void* const* d_in, const int* in_sizes, int n_in,
                              void* d_out, int out_size)
{
    const float* x      = (const float*)d_in[0];
    const float* cs     = (const float*)d_in[1];
    const float* sn     = (const float*)d_in[2];
    const float* qkv_w  = (const float*)d_in[3];
    const float* qnw    = (const float*)d_in[4];
    const float* knw    = (const float*)d_in[5];
    const float* proj_w = (const float*)d_in[6];
    const float* proj_b = (const float*)d_in[7];
    float* out = (float*)d_out;

    float* qkv;
    cudaGetSymbolAddress((void**)&qkv, g_qkv);
    __nv_bfloat16 *xh, *xl, *wqh, *wql, *wph, *wpl, *oh, *ol;
    __nv_bfloat16 *qh, *ql, *kh, *kl, *vh, *vl;
    cudaGetSymbolAddress((void**)&xh,  g_xh);
    cudaGetSymbolAddress((void**)&xl,  g_xl);
    cudaGetSymbolAddress((void**)&wqh, g_wqh);
    cudaGetSymbolAddress((void**)&wql, g_wql);
    cudaGetSymbolAddress((void**)&wph, g_wph);
    cudaGetSymbolAddress((void**)&wpl, g_wpl);
    cudaGetSymbolAddress((void**)&oh,  g_oh);
    cudaGetSymbolAddress((void**)&ol,  g_ol);
    cudaGetSymbolAddress((void**)&qh,  g_qh);
    cudaGetSymbolAddress((void**)&ql,  g_ql);
    cudaGetSymbolAddress((void**)&kh,  g_kh);
    cudaGetSymbolAddress((void**)&kl,  g_kl);
    cudaGetSymbolAddress((void**)&vh,  g_vh);
    cudaGetSymbolAddress((void**)&vl,  g_vl);

    // 0) split inputs/weights into bf16 hi/lo
    {
        int n4x = MROWS*CH/4, n4q = 3*CH*CH/4, n4p = CH*CH/4;
        cvt_split<<<(n4x+255)/256, 256>>>(x, xh, xl, n4x);
        cvt_split<<<(n4q+255)/256, 256>>>(qkv_w, wqh, wql, n4q);
        cvt_split<<<(n4p+255)/256, 256>>>(proj_w, wph, wpl, n4p);
    }

    // 1) QKV projection (HMMA 3-pass)
    cudaFuncSetAttribute(hmma_gemm, cudaFuncAttributeMaxDynamicSharedMemorySize,
                         HSMEM);
    hmma_gemm<<<dim3(3*CH/BN, MROWS/BM), 256, HSMEM>>>(
        xh, xl, wqh, wql, nullptr, qkv, CH, 3*CH);

    // 2) RMSnorm + RoPE + bf16 hi/lo scatter
    prep_kernel<<<(NBH*SEQ)/4, 128>>>(qkv, cs, sn, qnw, knw, qh, ql, kh, kl, vh, vl);

    // 3) flash attention (HMMA, 3-pass QK + 3-pass PV)
    cudaFuncSetAttribute(attn_mma, cudaFuncAttributeMaxDynamicSharedMemorySize,
                         ASMEM);
    attn_mma<<<dim3(SEQ/AQ, NBH), 256, ASMEM>>>(qh, ql, kh, kl, vh, vl, oh, ol);

    // 4) output projection (+bias) via HMMA
    hmma_gemm<<<dim3(CH/BN, MROWS/BM), 256, HSMEM>>>(
        oh, ol, wph, wpl, proj_b, out, CH, CH);
}

// round 13
// speedup vs baseline: 3.6677x; 1.1773x over previous
#include <cuda_runtime.h>
#include <cuda_bf16.h>
#include <cuda_fp16.h>
#include <math_constants.h>
#include <cstdint>

#define NUMH 12
#define HD   64
#define BATCH 4
#define SEQ  2048
#define CH   768
#define MROWS (BATCH*SEQ)   // 8192
#define NBH  (BATCH*NUMH)   // 48

// ---------------- base-PTX tensor helpers (compute_80+) --------------------
__device__ __forceinline__ uint32_t smem_u32(const void* p) {
    uint32_t a;
    asm("{ .reg .u64 t; cvta.to.shared.u64 t, %1; cvt.u32.u64 %0, t; }"
        : "=r"(a) : "l"(p));
    return a;
}
__device__ __forceinline__ void cp16(uint32_t dst, const void* src) {
    asm volatile("cp.async.cg.shared.global [%0], [%1], 16;"
                 :: "r"(dst), "l"(src) : "memory");
}
__device__ __forceinline__ void cp_commit() {
    asm volatile("cp.async.commit_group;" ::: "memory");
}
template<int N>
__device__ __forceinline__ void cp_wait() {
    asm volatile("cp.async.wait_group %0;" :: "n"(N) : "memory");
}
__device__ __forceinline__ void ldsm4(uint32_t* r, uint32_t addr) {
    asm volatile("ldmatrix.sync.aligned.m8n8.x4.shared.b16 {%0,%1,%2,%3}, [%4];"
                 : "=r"(r[0]), "=r"(r[1]), "=r"(r[2]), "=r"(r[3]) : "r"(addr));
}
__device__ __forceinline__ void ldsm4t(uint32_t* r, uint32_t addr) {
    asm volatile("ldmatrix.sync.aligned.m8n8.x4.trans.shared.b16 {%0,%1,%2,%3}, [%4];"
                 : "=r"(r[0]), "=r"(r[1]), "=r"(r[2]), "=r"(r[3]) : "r"(addr));
}
__device__ __forceinline__ void mma16816(float* d, const uint32_t* a,
                                         uint32_t b0, uint32_t b1) {
    asm volatile(
        "mma.sync.aligned.m16n8k16.row.col.f32.bf16.bf16.f32 "
        "{%0,%1,%2,%3}, {%4,%5,%6,%7}, {%8,%9}, {%0,%1,%2,%3};"
        : "+f"(d[0]), "+f"(d[1]), "+f"(d[2]), "+f"(d[3])
        : "r"(a[0]), "r"(a[1]), "r"(a[2]), "r"(a[3]), "r"(b0), "r"(b1));
}
__device__ __forceinline__ void mma16816h(float* d, const uint32_t* a,
                                          uint32_t b0, uint32_t b1) {
    asm volatile(
        "mma.sync.aligned.m16n8k16.row.col.f32.f16.f16.f32 "
        "{%0,%1,%2,%3}, {%4,%5,%6,%7}, {%8,%9}, {%0,%1,%2,%3};"
        : "+f"(d[0]), "+f"(d[1]), "+f"(d[2]), "+f"(d[3])
        : "r"(a[0]), "r"(a[1]), "r"(a[2]), "r"(a[3]), "r"(b0), "r"(b1));
}
__device__ __forceinline__ uint32_t packbf(float lo, float hi) {
    uint32_t r;
    asm("cvt.rn.bf16x2.f32 %0, %1, %2;" : "=r"(r) : "f"(hi), "f"(lo));
    return r;
}
__device__ __forceinline__ uint32_t packhf(float lo, float hi) {
    uint32_t r;
    asm("cvt.rn.f16x2.f32 %0, %1, %2;" : "=r"(r) : "f"(hi), "f"(lo));
    return r;
}

// ---------------- scratch (device globals; no allocation allowed) ----------
__device__ float g_qkv[(size_t)MROWS * 3 * CH];          // [B*N, 2304]

// bf16 split weight/activation buffers
__device__ __nv_bfloat16 g_xh[(size_t)MROWS * CH];
__device__ __nv_bfloat16 g_xl[(size_t)MROWS * CH];
__device__ __nv_bfloat16 g_wqh[(size_t)3 * CH * CH];
__device__ __nv_bfloat16 g_wql[(size_t)3 * CH * CH];
__device__ __nv_bfloat16 g_wph[(size_t)CH * CH];
__device__ __nv_bfloat16 g_wpl[(size_t)CH * CH];

// attention operands: q/k bf16 hi/lo, v fp16
__device__ __nv_bfloat16 g_qh[(size_t)NBH*SEQ*HD];
__device__ __nv_bfloat16 g_ql[(size_t)NBH*SEQ*HD];
__device__ __nv_bfloat16 g_kh[(size_t)NBH*SEQ*HD];
__device__ __nv_bfloat16 g_kl[(size_t)NBH*SEQ*HD];
__device__ __half        g_vf[(size_t)NBH*SEQ*HD];

// attention output split (proj A operand)
__device__ __nv_bfloat16 g_oh[(size_t)MROWS * CH];
__device__ __nv_bfloat16 g_ol[(size_t)MROWS * CH];

// ---------------- fp32 -> bf16 hi/lo split ---------------------------------
__global__ __launch_bounds__(256) void cvt_split(
    const float* __restrict__ s, __nv_bfloat16* __restrict__ h,
    __nv_bfloat16* __restrict__ l, int n4)
{
    int i = blockIdx.x * 256 + threadIdx.x;
    if (i >= n4) return;
    float4 v = ((const float4*)s)[i];
    __nv_bfloat16 hx = __float2bfloat16(v.x);
    __nv_bfloat16 hy = __float2bfloat16(v.y);
    __nv_bfloat16 hz = __float2bfloat16(v.z);
    __nv_bfloat16 hw = __float2bfloat16(v.w);
    __nv_bfloat162 h0, h1, l0, l1;
    h0.x = hx; h0.y = hy; h1.x = hz; h1.y = hw;
    l0.x = __float2bfloat16(v.x - __bfloat162float(hx));
    l0.y = __float2bfloat16(v.y - __bfloat162float(hy));
    l1.x = __float2bfloat16(v.z - __bfloat162float(hz));
    l1.y = __float2bfloat16(v.w - __bfloat162float(hw));
    ((__nv_bfloat162*)h)[2*i]   = h0;
    ((__nv_bfloat162*)h)[2*i+1] = h1;
    ((__nv_bfloat162*)l)[2*i]   = l0;
    ((__nv_bfloat162*)l)[2*i+1] = l1;
}

// ---------------- HMMA GEMM: C[M,N] = A·Wᵀ, bf16 hi/lo 3-pass --------------
#define BM 128
#define BN 128
#define BKK 32
#define TILE_B   (BM*BKK*2)          // 8192 B per tile
#define STG_B    (4*TILE_B)          // 32768 B per stage
#define HSMEM    (2*STG_B)           // 65536 B

__device__ __forceinline__ uint32_t tswz(int row, int ch) {
    return (uint32_t)(row*64 + ((ch ^ ((row>>1)&3))<<4));
}

__global__ __launch_bounds__(256, 2) void hmma_gemm(
    const __nv_bfloat16* __restrict__ Ah, const __nv_bfloat16* __restrict__ Al,
    const __nv_bfloat16* __restrict__ Bh, const __nv_bfloat16* __restrict__ Bl,
    const float* __restrict__ bias, float* __restrict__ C,
    int K, int ldc)
{
    extern __shared__ char smx[];
    uint32_t sb = smem_u32(smx);
    int tid = threadIdx.x, lane = tid & 31, warp = tid >> 5;
    int wm = warp >> 1, wn = warp & 1;
    int bm = blockIdx.y * BM, bn = blockIdx.x * BN;

    const __nv_bfloat16* ApH = Ah + (size_t)bm * K;
    const __nv_bfloat16* ApL = Al + (size_t)bm * K;
    const __nv_bfloat16* BpH = Bh + (size_t)bn * K;
    const __nv_bfloat16* BpL = Bl + (size_t)bn * K;

    int r0 = tid >> 2, c0 = tid & 3;
    int r1 = r0 + 64;
    uint32_t sw0 = tswz(r0, c0), sw1 = tswz(r1, c0);

    float acc[2][8][4];
    #pragma unroll
    for (int mt = 0; mt < 2; mt++)
        #pragma unroll
        for (int nt = 0; nt < 8; nt++)
            #pragma unroll
            for (int j = 0; j < 4; j++) acc[mt][nt][j] = 0.f;

    int lrow8 = lane & 7, ghalf = (lane >> 3) & 1, ghi = lane >> 4;
    int NS = K / BKK;

    auto issue = [&](int s, int b) {
        uint32_t dst = sb + (uint32_t)b * STG_B;
        size_t ko = (size_t)s * BKK;
        size_t o0 = (size_t)r0 * K + ko + c0*8;
        size_t o1 = (size_t)r1 * K + ko + c0*8;
        cp16(dst + 0*TILE_B + sw0, ApH + o0);
        cp16(dst + 0*TILE_B + sw1, ApH + o1);
        cp16(dst + 1*TILE_B + sw0, ApL + o0);
        cp16(dst + 1*TILE_B + sw1, ApL + o1);
        cp16(dst + 2*TILE_B + sw0, BpH + o0);
        cp16(dst + 2*TILE_B + sw1, BpH + o1);
        cp16(dst + 3*TILE_B + sw0, BpL + o0);
        cp16(dst + 3*TILE_B + sw1, BpL + o1);
        cp_commit();
    };

    issue(0, 0);
    for (int s = 0; s < NS; ++s) {
        int b = s & 1;
        if (s + 1 < NS) { issue(s + 1, b ^ 1); cp_wait<1>(); }
        else cp_wait<0>();
        __syncthreads();

        uint32_t stg = sb + (uint32_t)b * STG_B;
        #pragma unroll
        for (int ks = 0; ks < 2; ++ks) {
            int kc = ks * 2;
            uint32_t fAh[2][4], fAl[2][4], fBh[4][4], fBl[4][4];
            #pragma unroll
            for (int mt = 0; mt < 2; mt++) {
                int r = wm*32 + mt*16 + lrow8 + ghalf*8;
                uint32_t ad = stg + tswz(r, kc + ghi);
                ldsm4(fAh[mt], ad);
                ldsm4(fAl[mt], ad + TILE_B);
            }
            #pragma unroll
            for (int t16 = 0; t16 < 4; t16++) {
                int r = wn*64 + t16*16 + lrow8 + ghalf*8;
                uint32_t ad = stg + 2*TILE_B + tswz(r, kc + ghi);
                ldsm4(fBh[t16], ad);
                ldsm4(fBl[t16], ad + TILE_B);
            }
            #pragma unroll
            for (int mt = 0; mt < 2; mt++)
                #pragma unroll
                for (int nt = 0; nt < 8; nt++) {
                    int t16 = nt >> 1, hi = nt & 1;
                    mma16816(acc[mt][nt], fAh[mt], fBh[t16][hi], fBh[t16][hi+2]);
                    mma16816(acc[mt][nt], fAh[mt], fBl[t16][hi], fBl[t16][hi+2]);
                    mma16816(acc[mt][nt], fAl[mt], fBh[t16][hi], fBh[t16][hi+2]);
                }
        }
        __syncthreads();
    }

    #pragma unroll
    for (int mt = 0; mt < 2; mt++) {
        int rlo = bm + wm*32 + mt*16 + (lane >> 2);
        int rhi = rlo + 8;
        #pragma unroll
        for (int nt = 0; nt < 8; nt++) {
            int col = bn + wn*64 + nt*8 + (lane & 3)*2;
            float b0 = 0.f, b1 = 0.f;
            if (bias) { b0 = bias[col]; b1 = bias[col+1]; }
            float2 vlo = {acc[mt][nt][0] + b0, acc[mt][nt][1] + b1};
            float2 vhi = {acc[mt][nt][2] + b0, acc[mt][nt][3] + b1};
            *(float2*)&C[(size_t)rlo * ldc + col] = vlo;
            *(float2*)&C[(size_t)rhi * ldc + col] = vhi;
        }
    }
}

// ---------- RMSnorm + RoPE + split -> bf16/fp16 [B*H,N,D] ------------------
__global__ __launch_bounds__(128) void prep_kernel(
    const float* __restrict__ qkv, const float* __restrict__ cs,
    const float* __restrict__ sn, const float* __restrict__ qw,
    const float* __restrict__ kw,
    __nv_bfloat16* __restrict__ qh, __nv_bfloat16* __restrict__ ql,
    __nv_bfloat16* __restrict__ kh, __nv_bfloat16* __restrict__ kl,
    __half* __restrict__ vf)
{
    int task = blockIdx.x * 4 + (threadIdx.x >> 5);   // (b*H + h)*SEQ + n
    int lane = threadIdx.x & 31;
    int n  = task & (SEQ - 1);
    int bh = task >> 11;
    int h = bh % NUMH, b = bh / NUMH;

    const float* base = qkv + ((size_t)(b*SEQ + n)) * (3*CH) + h*HD;
    float q1 = base[lane],        q2 = base[lane+32];
    float k1 = base[CH+lane],     k2 = base[CH+lane+32];
    float v1 = base[2*CH+lane],   v2 = base[2*CH+lane+32];

    float sq = q1*q1 + q2*q2, sk = k1*k1 + k2*k2;
    #pragma unroll
    for (int o = 16; o >= 1; o >>= 1) {
        sq += __shfl_xor_sync(0xffffffffu, sq, o);
        sk += __shfl_xor_sync(0xffffffffu, sk, o);
    }
    float rq = rsqrtf(sq * (1.f/64.f) + 1e-6f) * 0.125f;   // fold attn scale into q
    float rk = rsqrtf(sk * (1.f/64.f) + 1e-6f);
    q1 *= rq * qw[lane]; q2 *= rq * qw[lane+32];
    k1 *= rk * kw[lane]; k2 *= rk * kw[lane+32];

    float c = cs[n*32 + lane], s = sn[n*32 + lane];
    float qa = q1*c - q2*s, qb2 = q2*c + q1*s;
    float ka = k1*c - k2*s, kb2 = k2*c + k1*s;

    size_t o = ((size_t)bh * SEQ + n) * HD + lane;
    __nv_bfloat16 t;
    t = __float2bfloat16(qa);  qh[o] = t;    ql[o]    = __float2bfloat16(qa - __bfloat162float(t));
    t = __float2bfloat16(qb2); qh[o+32] = t; ql[o+32] = __float2bfloat16(qb2 - __bfloat162float(t));
    t = __float2bfloat16(ka);  kh[o] = t;    kl[o]    = __float2bfloat16(ka - __bfloat162float(t));
    t = __float2bfloat16(kb2); kh[o+32] = t; kl[o+32] = __float2bfloat16(kb2 - __bfloat162float(t));
    vf[o]    = __float2half(v1);
    vf[o+32] = __float2half(v2);
}

// ---------------- flash attention via HMMA ---------------------------------
// 128 q x 64 k tiles. 8 warps, each owns 16 q rows. 3-pass bf16 QK, 1-pass fp16 PV.
#define AQ 128
#define AK 64
#define ANT (SEQ/AK)            // 32
#define QH_OFF 0
#define QL_OFF (AQ*128)         // 16384
#define ASTG0  (2*AQ*128)       // 32768
#define KH_O 0
#define KL_O (AK*128)           // 8192
#define VF_O (2*AK*128)         // 16384
#define ASTG (3*AK*128)         // 24576
#define ASMEM (ASTG0 + 2*ASTG)  // 81920

__device__ __forceinline__ uint32_t swz(int row, int ch) {
    return (uint32_t)(row*128 + ((ch ^ (row & 7)) << 4));
}

__global__ __launch_bounds__(256, 2) void attn_mma(
    const __nv_bfloat16* __restrict__ Qh, const __nv_bfloat16* __restrict__ Ql,
    const __nv_bfloat16* __restrict__ Kh, const __nv_bfloat16* __restrict__ Kl,
    const __half* __restrict__ Vf,
    __nv_bfloat16* __restrict__ Oh, __nv_bfloat16* __restrict__ Ol)
{
    extern __shared__ char smx[];
    uint32_t sb = smem_u32(smx);
    int tid = threadIdx.x, lane = tid & 31, warp = tid >> 5;
    int qt = blockIdx.x, bh = blockIdx.y;

    const __nv_bfloat16* Qhb = Qh + ((size_t)bh*SEQ + qt*AQ) * HD;
    const __nv_bfloat16* Qlb = Ql + ((size_t)bh*SEQ + qt*AQ) * HD;
    const __nv_bfloat16* Khb = Kh + (size_t)bh*SEQ*HD;
    const __nv_bfloat16* Klb = Kl + (size_t)bh*SEQ*HD;
    const __half*        Vfb = Vf + (size_t)bh*SEQ*HD;

    auto issueKV = [&](int s, int b) {
        uint32_t dst = sb + ASTG0 + (uint32_t)b * ASTG;
        #pragma unroll
        for (int t = 0; t < 2; ++t) {
            int v = tid + t*256;
            int row = v >> 3, ch = v & 7;
            size_t go = (size_t)(s*AK + row) * HD + ch*8;
            uint32_t so = swz(row, ch);
            cp16(dst + KH_O + so, Khb + go);
            cp16(dst + KL_O + so, Klb + go);
            cp16(dst + VF_O + so, Vfb + go);
        }
        cp_commit();
    };

    // load Q (both tiles) + stage 0 in group 0
    {
        #pragma unroll
        for (int t = 0; t < 4; ++t) {
            int v = tid + t*256;
            int row = v >> 3, ch = v & 7;
            size_t go = (size_t)row * HD + ch*8;
            uint32_t so = swz(row, ch);
            cp16(sb + QH_OFF + so, Qhb + go);
            cp16(sb + QL_OFF + so, Qlb + go);
        }
        #pragma unroll
        for (int t = 0; t < 2; ++t) {
            int v = tid + t*256;
            int row = v >> 3, ch = v & 7;
            size_t go = (size_t)row * HD + ch*8;
            uint32_t so = swz(row, ch);
            cp16(sb + ASTG0 + KH_O + so, Khb + go);
            cp16(sb + ASTG0 + KL_O + so, Klb + go);
            cp16(sb + ASTG0 + VF_O + so, Vfb + go);
        }
        cp_commit();
    }
    issueKV(1, 1);

    int lrow8 = lane & 7, ghalf = (lane >> 3) & 1, ghi = lane >> 4;
    int arow = warp*16 + lrow8 + ghalf*8;

    float m0 = -CUDART_INF_F, m1 = -CUDART_INF_F, sl0 = 0.f, sl1 = 0.f;
    float o[8][4];
    #pragma unroll
    for (int j = 0; j < 8; j++)
        #pragma unroll
        for (int t = 0; t < 4; t++) o[j][t] = 0.f;

    for (int kt = 0; kt < ANT; ++kt) {
        cp_wait<1>();
        __syncthreads();
        uint32_t stg = sb + ASTG0 + (uint32_t)(kt & 1) * ASTG;

        // ---- S = Q Kᵀ (3-pass bf16)
        float s[8][4];
        #pragma unroll
        for (int j = 0; j < 8; j++)
            #pragma unroll
            for (int t = 0; t < 4; t++) s[j][t] = 0.f;
        #pragma unroll
        for (int ks = 0; ks < 4; ++ks) {
            uint32_t aH[4], aL[4];
            uint32_t qa = swz(arow, ks*2 + ghi);
            ldsm4(aH, sb + QH_OFF + qa);
            ldsm4(aL, sb + QL_OFF + qa);
            #pragma unroll
            for (int nt = 0; nt < 4; ++nt) {
                uint32_t bH[4], bL[4];
                uint32_t ka = swz(nt*16 + lrow8 + ghalf*8, ks*2 + ghi);
                ldsm4(bH, stg + KH_O + ka);
                ldsm4(bL, stg + KL_O + ka);
                mma16816(s[nt*2],   aH, bH[0], bH[2]);
                mma16816(s[nt*2+1], aH, bH[1], bH[3]);
                mma16816(s[nt*2],   aH, bL[0], bL[2]);
                mma16816(s[nt*2+1], aH, bL[1], bL[3]);
                mma16816(s[nt*2],   aL, bH[0], bH[2]);
                mma16816(s[nt*2+1], aL, bH[1], bH[3]);
            }
        }

        // ---- online softmax (rows r and r+8)
        float mx0 = -CUDART_INF_F, mx1 = -CUDART_INF_F;
        #pragma unroll
        for (int j = 0; j < 8; j++) {
            mx0 = fmaxf(mx0, fmaxf(s[j][0], s[j][1]));
            mx1 = fmaxf(mx1, fmaxf(s[j][2], s[j][3]));
        }
        mx0 = fmaxf(mx0, __shfl_xor_sync(0xffffffffu, mx0, 1));
        mx0 = fmaxf(mx0, __shfl_xor_sync(0xffffffffu, mx0, 2));
        mx1 = fmaxf(mx1, __shfl_xor_sync(0xffffffffu, mx1, 1));
        mx1 = fmaxf(mx1, __shfl_xor_sync(0xffffffffu, mx1, 2));
        float nm0 = fmaxf(m0, mx0), nm1 = fmaxf(m1, mx1);
        float al0 = __expf(m0 - nm0), al1 = __expf(m1 - nm1);
        m0 = nm0; m1 = nm1;
        float rs0 = 0.f, rs1 = 0.f;
        #pragma unroll
        for (int j = 0; j < 8; j++) {
            s[j][0] = __expf(s[j][0] - nm0); rs0 += s[j][0];
            s[j][1] = __expf(s[j][1] - nm0); rs0 += s[j][1];
            s[j][2] = __expf(s[j][2] - nm1); rs1 += s[j][2];
            s[j][3] = __expf(s[j][3] - nm1); rs1 += s[j][3];
        }
        rs0 += __shfl_xor_sync(0xffffffffu, rs0, 1);
        rs0 += __shfl_xor_sync(0xffffffffu, rs0, 2);
        rs1 += __shfl_xor_sync(0xffffffffu, rs1, 1);
        rs1 += __shfl_xor_sync(0xffffffffu, rs1, 2);
        sl0 = sl0*al0 + rs0;
        sl1 = sl1*al1 + rs1;
        #pragma unroll
        for (int j = 0; j < 8; j++) {
            o[j][0] *= al0; o[j][1] *= al0;
            o[j][2] *= al1; o[j][3] *= al1;
        }

        // ---- O += P V (1-pass fp16)
        #pragma unroll
        for (int ks = 0; ks < 4; ++ks) {
            uint32_t ph[4];
            ph[0] = packhf(s[2*ks][0],   s[2*ks][1]);
            ph[1] = packhf(s[2*ks][2],   s[2*ks][3]);
            ph[2] = packhf(s[2*ks+1][0], s[2*ks+1][1]);
            ph[3] = packhf(s[2*ks+1][2], s[2*ks+1][3]);

            int vrow = ks*16 + lrow8 + ghalf*8;
            #pragma unroll
            for (int nb2 = 0; nb2 < 4; ++nb2) {
                uint32_t vF[4];
                ldsm4t(vF, stg + VF_O + swz(vrow, nb2*2 + ghi));
                mma16816h(o[nb2*2],   ph, vF[0], vF[1]);
                mma16816h(o[nb2*2+1], ph, vF[2], vF[3]);
            }
        }
        __syncthreads();
        if (kt + 2 < ANT) issueKV(kt + 2, kt & 1);
    }

    // ---- epilogue: normalize, split to bf16 hi/lo, write [B,N,C]
    int b_ = bh / NUMH, h_ = bh % NUMH;
    int r0 = warp*16 + (lane >> 2);
    size_t row0 = (size_t)b_*SEQ + qt*AQ + r0;
    size_t row1 = row0 + 8;
    float inv0 = 1.f / sl0, inv1 = 1.f / sl1;
    #pragma unroll
    for (int j = 0; j < 8; j++) {
        int col = h_*HD + j*8 + (lane & 3)*2;
        float f0 = o[j][0]*inv0, f1 = o[j][1]*inv0;
        float f2 = o[j][2]*inv1, f3 = o[j][3]*inv1;
        __nv_bfloat162 hh, ll;
        hh.x = __float2bfloat16(f0); hh.y = __float2bfloat16(f1);
        ll.x = __float2bfloat16(f0 - __bfloat162float(hh.x));
        ll.y = __float2bfloat16(f1 - __bfloat162float(hh.y));
        *(__nv_bfloat162*)&Oh[row0*CH + col] = hh;
        *(__nv_bfloat162*)&Ol[row0*CH + col] = ll;
        hh.x = __float2bfloat16(f2); hh.y = __float2bfloat16(f3);
        ll.x = __float2bfloat16(f2 - __bfloat162float(hh.x));
        ll.y = __float2bfloat16(f3 - __bfloat162float(hh.y));
        *(__nv_bfloat162*)&Oh[row1*CH + col] = hh;
        *(__nv_bfloat162*)&Ol[row1*CH + col] = ll;
    }
}

// ---------------------------------------------------------------------------
extern "C" void kernel_launch(void* const* d_in, const int* in_sizes, int n_in,
                              void* d_out, int out_size)
{
    const float* x      = (const float*)d_in[0];
    const float* cs     = (const float*)d_in[1];
    const float* sn     = (const float*)d_in[2];
    const float* qkv_w  = (const float*)d_in[3];
    const float* qnw    = (const float*)d_in[4];
    const float* knw    = (const float*)d_in[5];
    const float* proj_w = (const float*)d_in[6];
    const float* proj_b = (const float*)d_in[7];
    float* out = (float*)d_out;

    float* qkv;
    cudaGetSymbolAddress((void**)&qkv, g_qkv);
    __nv_bfloat16 *xh, *xl, *wqh, *wql, *wph, *wpl, *oh, *ol;
    __nv_bfloat16 *qh, *ql, *kh, *kl;
    __half *vf;
    cudaGetSymbolAddress((void**)&xh,  g_xh);
    cudaGetSymbolAddress((void**)&xl,  g_xl);
    cudaGetSymbolAddress((void**)&wqh, g_wqh);
    cudaGetSymbolAddress((void**)&wql, g_wql);
    cudaGetSymbolAddress((void**)&wph, g_wph);
    cudaGetSymbolAddress((void**)&wpl, g_wpl);
    cudaGetSymbolAddress((void**)&oh,  g_oh);
    cudaGetSymbolAddress((void**)&ol,  g_ol);
    cudaGetSymbolAddress((void**)&qh,  g_qh);
    cudaGetSymbolAddress((void**)&ql,  g_ql);
    cudaGetSymbolAddress((void**)&kh,  g_kh);
    cudaGetSymbolAddress((void**)&kl,  g_kl);
    cudaGetSymbolAddress((void**)&vf,  g_vf);

    // 0) split inputs/weights into bf16 hi/lo
    {
        int n4x = MROWS*CH/4, n4q = 3*CH*CH/4, n4p = CH*CH/4;
        cvt_split<<<(n4x+255)/256, 256>>>(x, xh, xl, n4x);
        cvt_split<<<(n4q+255)/256, 256>>>(qkv_w, wqh, wql, n4q);
        cvt_split<<<(n4p+255)/256, 256>>>(proj_w, wph, wpl, n4p);
    }

    // 1) QKV projection (HMMA 3-pass)
    cudaFuncSetAttribute(hmma_gemm, cudaFuncAttributeMaxDynamicSharedMemorySize,
                         HSMEM);
    hmma_gemm<<<dim3(3*CH/BN, MROWS/BM), 256, HSMEM>>>(
        xh, xl, wqh, wql, nullptr, qkv, CH, 3*CH);

    // 2) RMSnorm + RoPE + scatter (q/k bf16 hi/lo, v fp16)
    prep_kernel<<<(NBH*SEQ)/4, 128>>>(qkv, cs, sn, qnw, knw, qh, ql, kh, kl, vf);

    // 3) flash attention (HMMA: 3-pass bf16 QK, 1-pass fp16 PV)
    cudaFuncSetAttribute(attn_mma, cudaFuncAttributeMaxDynamicSharedMemorySize,
                         ASMEM);
    attn_mma<<<dim3(SEQ/AQ, NBH), 256, ASMEM>>>(qh, ql, kh, kl, vf, oh, ol);

    // 4) output projection (+bias) via HMMA
    hmma_gemm<<<dim3(CH/BN, MROWS/BM), 256, HSMEM>>>(
        oh, ol, wph, wpl, proj_b, out, CH, CH);
}

// round 14
// speedup vs baseline: 4.6418x; 1.2656x over previous
#include <cuda_runtime.h>
#include <cuda_bf16.h>
#include <cuda_fp16.h>
#include <math_constants.h>
#include <cstdint>

#define NUMH 12
#define HD   64
#define BATCH 4
#define SEQ  2048
#define CH   768
#define MROWS (BATCH*SEQ)   // 8192
#define NBH  (BATCH*NUMH)   // 48

// ---------------- base-PTX tensor helpers (compute_80+) --------------------
__device__ __forceinline__ uint32_t smem_u32(const void* p) {
    uint32_t a;
    asm("{ .reg .u64 t; cvta.to.shared.u64 t, %1; cvt.u32.u64 %0, t; }"
        : "=r"(a) : "l"(p));
    return a;
}
__device__ __forceinline__ void cp16(uint32_t dst, const void* src) {
    asm volatile("cp.async.cg.shared.global [%0], [%1], 16;"
                 :: "r"(dst), "l"(src) : "memory");
}
__device__ __forceinline__ void cp_commit() {
    asm volatile("cp.async.commit_group;" ::: "memory");
}
template<int N>
__device__ __forceinline__ void cp_wait() {
    asm volatile("cp.async.wait_group %0;" :: "n"(N) : "memory");
}
__device__ __forceinline__ void ldsm4(uint32_t* r, uint32_t addr) {
    asm volatile("ldmatrix.sync.aligned.m8n8.x4.shared.b16 {%0,%1,%2,%3}, [%4];"
                 : "=r"(r[0]), "=r"(r[1]), "=r"(r[2]), "=r"(r[3]) : "r"(addr));
}
__device__ __forceinline__ void ldsm4t(uint32_t* r, uint32_t addr) {
    asm volatile("ldmatrix.sync.aligned.m8n8.x4.trans.shared.b16 {%0,%1,%2,%3}, [%4];"
                 : "=r"(r[0]), "=r"(r[1]), "=r"(r[2]), "=r"(r[3]) : "r"(addr));
}
__device__ __forceinline__ void mma16816(float* d, const uint32_t* a,
                                         uint32_t b0, uint32_t b1) {
    asm volatile(
        "mma.sync.aligned.m16n8k16.row.col.f32.bf16.bf16.f32 "
        "{%0,%1,%2,%3}, {%4,%5,%6,%7}, {%8,%9}, {%0,%1,%2,%3};"
        : "+f"(d[0]), "+f"(d[1]), "+f"(d[2]), "+f"(d[3])
        : "r"(a[0]), "r"(a[1]), "r"(a[2]), "r"(a[3]), "r"(b0), "r"(b1));
}
__device__ __forceinline__ void mma16816h(float* d, const uint32_t* a,
                                          uint32_t b0, uint32_t b1) {
    asm volatile(
        "mma.sync.aligned.m16n8k16.row.col.f32.f16.f16.f32 "
        "{%0,%1,%2,%3}, {%4,%5,%6,%7}, {%8,%9}, {%0,%1,%2,%3};"
        : "+f"(d[0]), "+f"(d[1]), "+f"(d[2]), "+f"(d[3])
        : "r"(a[0]), "r"(a[1]), "r"(a[2]), "r"(a[3]), "r"(b0), "r"(b1));
}
__device__ __forceinline__ uint32_t packhf(float lo, float hi) {
    uint32_t r;
    asm("cvt.rn.f16x2.f32 %0, %1, %2;" : "=r"(r) : "f"(hi), "f"(lo));
    return r;
}

// ---------------- scratch (device globals; no allocation allowed) ----------
__device__ float g_qkv[(size_t)MROWS * 3 * CH];          // [B*N, 2304]

// fp16 operands for QKV GEMM (1-pass)
__device__ __half g_xf[(size_t)MROWS * CH];
__device__ __half g_wqf[(size_t)3 * CH * CH];

// bf16 split weights for proj (3-pass)
__device__ __nv_bfloat16 g_wph[(size_t)CH * CH];
__device__ __nv_bfloat16 g_wpl[(size_t)CH * CH];

// attention operands: q/k bf16 hi/lo, v fp16
__device__ __nv_bfloat16 g_qh[(size_t)NBH*SEQ*HD];
__device__ __nv_bfloat16 g_ql[(size_t)NBH*SEQ*HD];
__device__ __nv_bfloat16 g_kh[(size_t)NBH*SEQ*HD];
__device__ __nv_bfloat16 g_kl[(size_t)NBH*SEQ*HD];
__device__ __half        g_vf[(size_t)NBH*SEQ*HD];

// attention output split (proj A operand, bf16 hi/lo)
__device__ __nv_bfloat16 g_oh[(size_t)MROWS * CH];
__device__ __nv_bfloat16 g_ol[(size_t)MROWS * CH];

// ---------------- fp32 -> bf16 hi/lo split ---------------------------------
__global__ __launch_bounds__(256) void cvt_split(
    const float* __restrict__ s, __nv_bfloat16* __restrict__ h,
    __nv_bfloat16* __restrict__ l, int n4)
{
    int i = blockIdx.x * 256 + threadIdx.x;
    if (i >= n4) return;
    float4 v = ((const float4*)s)[i];
    __nv_bfloat16 hx = __float2bfloat16(v.x);
    __nv_bfloat16 hy = __float2bfloat16(v.y);
    __nv_bfloat16 hz = __float2bfloat16(v.z);
    __nv_bfloat16 hw = __float2bfloat16(v.w);
    __nv_bfloat162 h0, h1, l0, l1;
    h0.x = hx; h0.y = hy; h1.x = hz; h1.y = hw;
    l0.x = __float2bfloat16(v.x - __bfloat162float(hx));
    l0.y = __float2bfloat16(v.y - __bfloat162float(hy));
    l1.x = __float2bfloat16(v.z - __bfloat162float(hz));
    l1.y = __float2bfloat16(v.w - __bfloat162float(hw));
    ((__nv_bfloat162*)h)[2*i]   = h0;
    ((__nv_bfloat162*)h)[2*i+1] = h1;
    ((__nv_bfloat162*)l)[2*i]   = l0;
    ((__nv_bfloat162*)l)[2*i+1] = l1;
}

// ---------------- fp32 -> fp16 convert --------------------------------------
__global__ __launch_bounds__(256) void cvt_f16(
    const float* __restrict__ s, __half* __restrict__ d, int n4)
{
    int i = blockIdx.x * 256 + threadIdx.x;
    if (i >= n4) return;
    float4 v = ((const float4*)s)[i];
    __half2 a, b;
    a.x = __float2half(v.x); a.y = __float2half(v.y);
    b.x = __float2half(v.z); b.y = __float2half(v.w);
    ((__half2*)d)[2*i]   = a;
    ((__half2*)d)[2*i+1] = b;
}

// ---------------- shared GEMM geometry --------------------------------------
#define BM 128
#define BN 128
#define BKK 32
#define TILE_B   (BM*BKK*2)          // 8192 B per tile
#define STG_B    (4*TILE_B)          // 32768 B per stage (3-pass)
#define HSMEM    (2*STG_B)           // 65536 B
#define F16_STG  (2*TILE_B)          // 16384 B per stage (1-pass)
#define F16_SMEM (2*F16_STG)         // 32768 B

__device__ __forceinline__ uint32_t tswz(int row, int ch) {
    return (uint32_t)(row*64 + ((ch ^ ((row>>1)&3))<<4));
}

// ---------------- HMMA GEMM (1-pass fp16): C = A·Bᵀ -------------------------
__global__ __launch_bounds__(256, 2) void hmma_gemm_f16(
    const __half* __restrict__ A, const __half* __restrict__ B,
    float* __restrict__ C, int K, int ldc)
{
    extern __shared__ char smx[];
    uint32_t sb = smem_u32(smx);
    int tid = threadIdx.x, lane = tid & 31, warp = tid >> 5;
    int wm = warp >> 1, wn = warp & 1;
    int bm = blockIdx.y * BM, bn = blockIdx.x * BN;

    const __half* Ap = A + (size_t)bm * K;
    const __half* Bp = B + (size_t)bn * K;

    int r0 = tid >> 2, c0 = tid & 3;
    int r1 = r0 + 64;
    uint32_t sw0 = tswz(r0, c0), sw1 = tswz(r1, c0);

    float acc[2][8][4];
    #pragma unroll
    for (int mt = 0; mt < 2; mt++)
        #pragma unroll
        for (int nt = 0; nt < 8; nt++)
            #pragma unroll
            for (int j = 0; j < 4; j++) acc[mt][nt][j] = 0.f;

    int lrow8 = lane & 7, ghalf = (lane >> 3) & 1, ghi = lane >> 4;
    int NS = K / BKK;

    auto issue = [&](int s, int b) {
        uint32_t dst = sb + (uint32_t)b * F16_STG;
        size_t ko = (size_t)s * BKK;
        size_t o0 = (size_t)r0 * K + ko + c0*8;
        size_t o1 = (size_t)r1 * K + ko + c0*8;
        cp16(dst + sw0, Ap + o0);
        cp16(dst + sw1, Ap + o1);
        cp16(dst + TILE_B + sw0, Bp + o0);
        cp16(dst + TILE_B + sw1, Bp + o1);
        cp_commit();
    };

    issue(0, 0);
    for (int s = 0; s < NS; ++s) {
        int b = s & 1;
        if (s + 1 < NS) { issue(s + 1, b ^ 1); cp_wait<1>(); }
        else cp_wait<0>();
        __syncthreads();

        uint32_t stg = sb + (uint32_t)b * F16_STG;
        #pragma unroll
        for (int ks = 0; ks < 2; ++ks) {
            int kc = ks * 2;
            uint32_t fA[2][4], fB[4][4];
            #pragma unroll
            for (int mt = 0; mt < 2; mt++) {
                int r = wm*32 + mt*16 + lrow8 + ghalf*8;
                ldsm4(fA[mt], stg + tswz(r, kc + ghi));
            }
            #pragma unroll
            for (int t16 = 0; t16 < 4; t16++) {
                int r = wn*64 + t16*16 + lrow8 + ghalf*8;
                ldsm4(fB[t16], stg + TILE_B + tswz(r, kc + ghi));
            }
            #pragma unroll
            for (int mt = 0; mt < 2; mt++)
                #pragma unroll
                for (int nt = 0; nt < 8; nt++) {
                    int t16 = nt >> 1, hi = nt & 1;
                    mma16816h(acc[mt][nt], fA[mt], fB[t16][hi], fB[t16][hi+2]);
                }
        }
        __syncthreads();
    }

    #pragma unroll
    for (int mt = 0; mt < 2; mt++) {
        int rlo = bm + wm*32 + mt*16 + (lane >> 2);
        int rhi = rlo + 8;
        #pragma unroll
        for (int nt = 0; nt < 8; nt++) {
            int col = bn + wn*64 + nt*8 + (lane & 3)*2;
            float2 vlo = {acc[mt][nt][0], acc[mt][nt][1]};
            float2 vhi = {acc[mt][nt][2], acc[mt][nt][3]};
            *(float2*)&C[(size_t)rlo * ldc + col] = vlo;
            *(float2*)&C[(size_t)rhi * ldc + col] = vhi;
        }
    }
}

// ---------------- HMMA GEMM (3-pass bf16 hi/lo): C = A·Bᵀ (+bias) ----------
__global__ __launch_bounds__(256, 2) void hmma_gemm(
    const __nv_bfloat16* __restrict__ Ah, const __nv_bfloat16* __restrict__ Al,
    const __nv_bfloat16* __restrict__ Bh, const __nv_bfloat16* __restrict__ Bl,
    const float* __restrict__ bias, float* __restrict__ C,
    int K, int ldc)
{
    extern __shared__ char smx[];
    uint32_t sb = smem_u32(smx);
    int tid = threadIdx.x, lane = tid & 31, warp = tid >> 5;
    int wm = warp >> 1, wn = warp & 1;
    int bm = blockIdx.y * BM, bn = blockIdx.x * BN;

    const __nv_bfloat16* ApH = Ah + (size_t)bm * K;
    const __nv_bfloat16* ApL = Al + (size_t)bm * K;
    const __nv_bfloat16* BpH = Bh + (size_t)bn * K;
    const __nv_bfloat16* BpL = Bl + (size_t)bn * K;

    int r0 = tid >> 2, c0 = tid & 3;
    int r1 = r0 + 64;
    uint32_t sw0 = tswz(r0, c0), sw1 = tswz(r1, c0);

    float acc[2][8][4];
    #pragma unroll
    for (int mt = 0; mt < 2; mt++)
        #pragma unroll
        for (int nt = 0; nt < 8; nt++)
            #pragma unroll
            for (int j = 0; j < 4; j++) acc[mt][nt][j] = 0.f;

    int lrow8 = lane & 7, ghalf = (lane >> 3) & 1, ghi = lane >> 4;
    int NS = K / BKK;

    auto issue = [&](int s, int b) {
        uint32_t dst = sb + (uint32_t)b * STG_B;
        size_t ko = (size_t)s * BKK;
        size_t o0 = (size_t)r0 * K + ko + c0*8;
        size_t o1 = (size_t)r1 * K + ko + c0*8;
        cp16(dst + 0*TILE_B + sw0, ApH + o0);
        cp16(dst + 0*TILE_B + sw1, ApH + o1);
        cp16(dst + 1*TILE_B + sw0, ApL + o0);
        cp16(dst + 1*TILE_B + sw1, ApL + o1);
        cp16(dst + 2*TILE_B + sw0, BpH + o0);
        cp16(dst + 2*TILE_B + sw1, BpH + o1);
        cp16(dst + 3*TILE_B + sw0, BpL + o0);
        cp16(dst + 3*TILE_B + sw1, BpL + o1);
        cp_commit();
    };

    issue(0, 0);
    for (int s = 0; s < NS; ++s) {
        int b = s & 1;
        if (s + 1 < NS) { issue(s + 1, b ^ 1); cp_wait<1>(); }
        else cp_wait<0>();
        __syncthreads();

        uint32_t stg = sb + (uint32_t)b * STG_B;
        #pragma unroll
        for (int ks = 0; ks < 2; ++ks) {
            int kc = ks * 2;
            uint32_t fAh[2][4], fAl[2][4], fBh[4][4], fBl[4][4];
            #pragma unroll
            for (int mt = 0; mt < 2; mt++) {
                int r = wm*32 + mt*16 + lrow8 + ghalf*8;
                uint32_t ad = stg + tswz(r, kc + ghi);
                ldsm4(fAh[mt], ad);
                ldsm4(fAl[mt], ad + TILE_B);
            }
            #pragma unroll
            for (int t16 = 0; t16 < 4; t16++) {
                int r = wn*64 + t16*16 + lrow8 + ghalf*8;
                uint32_t ad = stg + 2*TILE_B + tswz(r, kc + ghi);
                ldsm4(fBh[t16], ad);
                ldsm4(fBl[t16], ad + TILE_B);
            }
            #pragma unroll
            for (int mt = 0; mt < 2; mt++)
                #pragma unroll
                for (int nt = 0; nt < 8; nt++) {
                    int t16 = nt >> 1, hi = nt & 1;
                    mma16816(acc[mt][nt], fAh[mt], fBh[t16][hi], fBh[t16][hi+2]);
                    mma16816(acc[mt][nt], fAh[mt], fBl[t16][hi], fBl[t16][hi+2]);
                    mma16816(acc[mt][nt], fAl[mt], fBh[t16][hi], fBh[t16][hi+2]);
                }
        }
        __syncthreads();
    }

    #pragma unroll
    for (int mt = 0; mt < 2; mt++) {
        int rlo = bm + wm*32 + mt*16 + (lane >> 2);
        int rhi = rlo + 8;
        #pragma unroll
        for (int nt = 0; nt < 8; nt++) {
            int col = bn + wn*64 + nt*8 + (lane & 3)*2;
            float b0 = 0.f, b1 = 0.f;
            if (bias) { b0 = bias[col]; b1 = bias[col+1]; }
            float2 vlo = {acc[mt][nt][0] + b0, acc[mt][nt][1] + b1};
            float2 vhi = {acc[mt][nt][2] + b0, acc[mt][nt][3] + b1};
            *(float2*)&C[(size_t)rlo * ldc + col] = vlo;
            *(float2*)&C[(size_t)rhi * ldc + col] = vhi;
        }
    }
}

// ---------- RMSnorm + RoPE + split -> bf16/fp16 [B*H,N,D] ------------------
__global__ __launch_bounds__(128) void prep_kernel(
    const float* __restrict__ qkv, const float* __restrict__ cs,
    const float* __restrict__ sn, const float* __restrict__ qw,
    const float* __restrict__ kw,
    __nv_bfloat16* __restrict__ qh, __nv_bfloat16* __restrict__ ql,
    __nv_bfloat16* __restrict__ kh, __nv_bfloat16* __restrict__ kl,
    __half* __restrict__ vf)
{
    int task = blockIdx.x * 4 + (threadIdx.x >> 5);   // (b*H + h)*SEQ + n
    int lane = threadIdx.x & 31;
    int n  = task & (SEQ - 1);
    int bh = task >> 11;
    int h = bh % NUMH, b = bh / NUMH;

    const float* base = qkv + ((size_t)(b*SEQ + n)) * (3*CH) + h*HD;
    float q1 = base[lane],        q2 = base[lane+32];
    float k1 = base[CH+lane],     k2 = base[CH+lane+32];
    float v1 = base[2*CH+lane],   v2 = base[2*CH+lane+32];

    float sq = q1*q1 + q2*q2, sk = k1*k1 + k2*k2;
    #pragma unroll
    for (int o = 16; o >= 1; o >>= 1) {
        sq += __shfl_xor_sync(0xffffffffu, sq, o);
        sk += __shfl_xor_sync(0xffffffffu, sk, o);
    }
    float rq = rsqrtf(sq * (1.f/64.f) + 1e-6f) * 0.125f;   // fold attn scale into q
    float rk = rsqrtf(sk * (1.f/64.f) + 1e-6f);
    q1 *= rq * qw[lane]; q2 *= rq * qw[lane+32];
    k1 *= rk * kw[lane]; k2 *= rk * kw[lane+32];

    float c = cs[n*32 + lane], s = sn[n*32 + lane];
    float qa = q1*c - q2*s, qb2 = q2*c + q1*s;
    float ka = k1*c - k2*s, kb2 = k2*c + k1*s;

    size_t o = ((size_t)bh * SEQ + n) * HD + lane;
    __nv_bfloat16 t;
    t = __float2bfloat16(qa);  qh[o] = t;    ql[o]    = __float2bfloat16(qa - __bfloat162float(t));
    t = __float2bfloat16(qb2); qh[o+32] = t; ql[o+32] = __float2bfloat16(qb2 - __bfloat162float(t));
    t = __float2bfloat16(ka);  kh[o] = t;    kl[o]    = __float2bfloat16(ka - __bfloat162float(t));
    t = __float2bfloat16(kb2); kh[o+32] = t; kl[o+32] = __float2bfloat16(kb2 - __bfloat162float(t));
    vf[o]    = __float2half(v1);
    vf[o+32] = __float2half(v2);
}

// ---------------- flash attention via HMMA ---------------------------------
// 128 q x 64 k tiles. 8 warps, each owns 16 q rows. 3-pass bf16 QK, 1-pass fp16 PV.
#define AQ 128
#define AK 64
#define ANT (SEQ/AK)            // 32
#define QH_OFF 0
#define QL_OFF (AQ*128)         // 16384
#define ASTG0  (2*AQ*128)       // 32768
#define KH_O 0
#define KL_O (AK*128)           // 8192
#define VF_O (2*AK*128)         // 16384
#define ASTG (3*AK*128)         // 24576
#define ASMEM (ASTG0 + 2*ASTG)  // 81920

__device__ __forceinline__ uint32_t swz(int row, int ch) {
    return (uint32_t)(row*128 + ((ch ^ (row & 7)) << 4));
}

__global__ __launch_bounds__(256, 2) void attn_mma(
    const __nv_bfloat16* __restrict__ Qh, const __nv_bfloat16* __restrict__ Ql,
    const __nv_bfloat16* __restrict__ Kh, const __nv_bfloat16* __restrict__ Kl,
    const __half* __restrict__ Vf,
    __nv_bfloat16* __restrict__ Oh, __nv_bfloat16* __restrict__ Ol)
{
    extern __shared__ char smx[];
    uint32_t sb = smem_u32(smx);
    int tid = threadIdx.x, lane = tid & 31, warp = tid >> 5;
    int qt = blockIdx.x, bh = blockIdx.y;

    const __nv_bfloat16* Qhb = Qh + ((size_t)bh*SEQ + qt*AQ) * HD;
    const __nv_bfloat16* Qlb = Ql + ((size_t)bh*SEQ + qt*AQ) * HD;
    const __nv_bfloat16* Khb = Kh + (size_t)bh*SEQ*HD;
    const __nv_bfloat16* Klb = Kl + (size_t)bh*SEQ*HD;
    const __half*        Vfb = Vf + (size_t)bh*SEQ*HD;

    auto issueKV = [&](int s, int b) {
        uint32_t dst = sb + ASTG0 + (uint32_t)b * ASTG;
        #pragma unroll
        for (int t = 0; t < 2; ++t) {
            int v = tid + t*256;
            int row = v >> 3, ch = v & 7;
            size_t go = (size_t)(s*AK + row) * HD + ch*8;
            uint32_t so = swz(row, ch);
            cp16(dst + KH_O + so, Khb + go);
            cp16(dst + KL_O + so, Klb + go);
            cp16(dst + VF_O + so, Vfb + go);
        }
        cp_commit();
    };

    // load Q (both tiles) + stage 0 in group 0
    {
        #pragma unroll
        for (int t = 0; t < 4; ++t) {
            int v = tid + t*256;
            int row = v >> 3, ch = v & 7;
            size_t go = (size_t)row * HD + ch*8;
            uint32_t so = swz(row, ch);
            cp16(sb + QH_OFF + so, Qhb + go);
            cp16(sb + QL_OFF + so, Qlb + go);
        }
        #pragma unroll
        for (int t = 0; t < 2; ++t) {
            int v = tid + t*256;
            int row = v >> 3, ch = v & 7;
            size_t go = (size_t)row * HD + ch*8;
            uint32_t so = swz(row, ch);
            cp16(sb + ASTG0 + KH_O + so, Khb + go);
            cp16(sb + ASTG0 + KL_O + so, Klb + go);
            cp16(sb + ASTG0 + VF_O + so, Vfb + go);
        }
        cp_commit();
    }
    issueKV(1, 1);

    int lrow8 = lane & 7, ghalf = (lane >> 3) & 1, ghi = lane >> 4;
    int arow = warp*16 + lrow8 + ghalf*8;

    float m0 = -CUDART_INF_F, m1 = -CUDART_INF_F, sl0 = 0.f, sl1 = 0.f;
    float o[8][4];
    #pragma unroll
    for (int j = 0; j < 8; j++)
        #pragma unroll
        for (int t = 0; t < 4; t++) o[j][t] = 0.f;

    for (int kt = 0; kt < ANT; ++kt) {
        cp_wait<1>();
        __syncthreads();
        uint32_t stg = sb + ASTG0 + (uint32_t)(kt & 1) * ASTG;

        // ---- S = Q Kᵀ (3-pass bf16)
        float s[8][4];
        #pragma unroll
        for (int j = 0; j < 8; j++)
            #pragma unroll
            for (int t = 0; t < 4; t++) s[j][t] = 0.f;
        #pragma unroll
        for (int ks = 0; ks < 4; ++ks) {
            uint32_t aH[4], aL[4];
            uint32_t qa = swz(arow, ks*2 + ghi);
            ldsm4(aH, sb + QH_OFF + qa);
            ldsm4(aL, sb + QL_OFF + qa);
            #pragma unroll
            for (int nt = 0; nt < 4; ++nt) {
                uint32_t bH[4], bL[4];
                uint32_t ka = swz(nt*16 + lrow8 + ghalf*8, ks*2 + ghi);
                ldsm4(bH, stg + KH_O + ka);
                ldsm4(bL, stg + KL_O + ka);
                mma16816(s[nt*2],   aH, bH[0], bH[2]);
                mma16816(s[nt*2+1], aH, bH[1], bH[3]);
                mma16816(s[nt*2],   aH, bL[0], bL[2]);
                mma16816(s[nt*2+1], aH, bL[1], bL[3]);
                mma16816(s[nt*2],   aL, bH[0], bH[2]);
                mma16816(s[nt*2+1], aL, bH[1], bH[3]);
            }
        }

        // ---- online softmax (rows r and r+8)
        float mx0 = -CUDART_INF_F, mx1 = -CUDART_INF_F;
        #pragma unroll
        for (int j = 0; j < 8; j++) {
            mx0 = fmaxf(mx0, fmaxf(s[j][0], s[j][1]));
            mx1 = fmaxf(mx1, fmaxf(s[j][2], s[j][3]));
        }
        mx0 = fmaxf(mx0, __shfl_xor_sync(0xffffffffu, mx0, 1));
        mx0 = fmaxf(mx0, __shfl_xor_sync(0xffffffffu, mx0, 2));
        mx1 = fmaxf(mx1, __shfl_xor_sync(0xffffffffu, mx1, 1));
        mx1 = fmaxf(mx1, __shfl_xor_sync(0xffffffffu, mx1, 2));
        float nm0 = fmaxf(m0, mx0), nm1 = fmaxf(m1, mx1);
        float al0 = __expf(m0 - nm0), al1 = __expf(m1 - nm1);
        m0 = nm0; m1 = nm1;
        float rs0 = 0.f, rs1 = 0.f;
        #pragma unroll
        for (int j = 0; j < 8; j++) {
            s[j][0] = __expf(s[j][0] - nm0); rs0 += s[j][0];
            s[j][1] = __expf(s[j][1] - nm0); rs0 += s[j][1];
            s[j][2] = __expf(s[j][2] - nm1); rs1 += s[j][2];
            s[j][3] = __expf(s[j][3] - nm1); rs1 += s[j][3];
        }
        rs0 += __shfl_xor_sync(0xffffffffu, rs0, 1);
        rs0 += __shfl_xor_sync(0xffffffffu, rs0, 2);
        rs1 += __shfl_xor_sync(0xffffffffu, rs1, 1);
        rs1 += __shfl_xor_sync(0xffffffffu, rs1, 2);
        sl0 = sl0*al0 + rs0;
        sl1 = sl1*al1 + rs1;
        #pragma unroll
        for (int j = 0; j < 8; j++) {
            o[j][0] *= al0; o[j][1] *= al0;
            o[j][2] *= al1; o[j][3] *= al1;
        }

        // ---- O += P V (1-pass fp16)
        #pragma unroll
        for (int ks = 0; ks < 4; ++ks) {
            uint32_t ph[4];
            ph[0] = packhf(s[2*ks][0],   s[2*ks][1]);
            ph[1] = packhf(s[2*ks][2],   s[2*ks][3]);
            ph[2] = packhf(s[2*ks+1][0], s[2*ks+1][1]);
            ph[3] = packhf(s[2*ks+1][2], s[2*ks+1][3]);

            int vrow = ks*16 + lrow8 + ghalf*8;
            #pragma unroll
            for (int nb2 = 0; nb2 < 4; ++nb2) {
                uint32_t vF[4];
                ldsm4t(vF, stg + VF_O + swz(vrow, nb2*2 + ghi));
                mma16816h(o[nb2*2],   ph, vF[0], vF[1]);
                mma16816h(o[nb2*2+1], ph, vF[2], vF[3]);
            }
        }
        __syncthreads();
        if (kt + 2 < ANT) issueKV(kt + 2, kt & 1);
    }

    // ---- epilogue: normalize, split to bf16 hi/lo, write [B,N,C]
    int b_ = bh / NUMH, h_ = bh % NUMH;
    int r0 = warp*16 + (lane >> 2);
    size_t row0 = (size_t)b_*SEQ + qt*AQ + r0;
    size_t row1 = row0 + 8;
    float inv0 = 1.f / sl0, inv1 = 1.f / sl1;
    #pragma unroll
    for (int j = 0; j < 8; j++) {
        int col = h_*HD + j*8 + (lane & 3)*2;
        float f0 = o[j][0]*inv0, f1 = o[j][1]*inv0;
        float f2 = o[j][2]*inv1, f3 = o[j][3]*inv1;
        __nv_bfloat162 hh, ll;
        hh.x = __float2bfloat16(f0); hh.y = __float2bfloat16(f1);
        ll.x = __float2bfloat16(f0 - __bfloat162float(hh.x));
        ll.y = __float2bfloat16(f1 - __bfloat162float(hh.y));
        *(__nv_bfloat162*)&Oh[row0*CH + col] = hh;
        *(__nv_bfloat162*)&Ol[row0*CH + col] = ll;
        hh.x = __float2bfloat16(f2); hh.y = __float2bfloat16(f3);
        ll.x = __float2bfloat16(f2 - __bfloat162float(hh.x));
        ll.y = __float2bfloat16(f3 - __bfloat162float(hh.y));
        *(__nv_bfloat162*)&Oh[row1*CH + col] = hh;
        *(__nv_bfloat162*)&Ol[row1*CH + col] = ll;
    }
}

// ---------------------------------------------------------------------------
extern "C" void kernel_launch(void* const* d_in, const int* in_sizes, int n_in,
                              void* d_out, int out_size)
{
    const float* x      = (const float*)d_in[0];
    const float* cs     = (const float*)d_in[1];
    const float* sn     = (const float*)d_in[2];
    const float* qkv_w  = (const float*)d_in[3];
    const float* qnw    = (const float*)d_in[4];
    const float* knw    = (const float*)d_in[5];
    const float* proj_w = (const float*)d_in[6];
    const float* proj_b = (const float*)d_in[7];
    float* out = (float*)d_out;

    float* qkv;
    cudaGetSymbolAddress((void**)&qkv, g_qkv);
    __half *xf, *wqf, *vf;
    __nv_bfloat16 *wph, *wpl, *oh, *ol, *qh, *ql, *kh, *kl;
    cudaGetSymbolAddress((void**)&xf,  g_xf);
    cudaGetSymbolAddress((void**)&wqf, g_wqf);
    cudaGetSymbolAddress((void**)&wph, g_wph);
    cudaGetSymbolAddress((void**)&wpl, g_wpl);
    cudaGetSymbolAddress((void**)&oh,  g_oh);
    cudaGetSymbolAddress((void**)&ol,  g_ol);
    cudaGetSymbolAddress((void**)&qh,  g_qh);
    cudaGetSymbolAddress((void**)&ql,  g_ql);
    cudaGetSymbolAddress((void**)&kh,  g_kh);
    cudaGetSymbolAddress((void**)&kl,  g_kl);
    cudaGetSymbolAddress((void**)&vf,  g_vf);

    // 0) converts: x/qkv_w -> fp16; proj_w -> bf16 hi/lo
    {
        int n4x = MROWS*CH/4, n4q = 3*CH*CH/4, n4p = CH*CH/4;
        cvt_f16<<<(n4x+255)/256, 256>>>(x, xf, n4x);
        cvt_f16<<<(n4q+255)/256, 256>>>(qkv_w, wqf, n4q);
        cvt_split<<<(n4p+255)/256, 256>>>(proj_w, wph, wpl, n4p);
    }

    // 1) QKV projection (HMMA, 1-pass fp16)
    cudaFuncSetAttribute(hmma_gemm_f16, cudaFuncAttributeMaxDynamicSharedMemorySize,
                         F16_SMEM);
    hmma_gemm_f16<<<dim3(3*CH/BN, MROWS/BM), 256, F16_SMEM>>>(
        xf, wqf, qkv, CH, 3*CH);

    // 2) RMSnorm + RoPE + scatter (q/k bf16 hi/lo, v fp16)
    prep_kernel<<<(NBH*SEQ)/4, 128>>>(qkv, cs, sn, qnw, knw, qh, ql, kh, kl, vf);

    // 3) flash attention (HMMA: 3-pass bf16 QK, 1-pass fp16 PV)
    cudaFuncSetAttribute(attn_mma, cudaFuncAttributeMaxDynamicSharedMemorySize,
                         ASMEM);
    attn_mma<<<dim3(SEQ/AQ, NBH), 256, ASMEM>>>(qh, ql, kh, kl, vf, oh, ol);

    // 4) output projection (+bias, HMMA 3-pass bf16)
    cudaFuncSetAttribute(hmma_gemm, cudaFuncAttributeMaxDynamicSharedMemorySize,
                         HSMEM);
    hmma_gemm<<<dim3(CH/BN, MROWS/BM), 256, HSMEM>>>(
        oh, ol, wph, wpl, proj_b, out, CH, CH);
}

// round 15
// speedup vs baseline: 5.9622x; 1.2844x over previous
#include <cuda_runtime.h>
#include <cuda_bf16.h>
#include <cuda_fp16.h>
#include <math_constants.h>
#include <cstdint>

#define NUMH 12
#define HD   64
#define BATCH 4
#define SEQ  2048
#define CH   768
#define MROWS (BATCH*SEQ)   // 8192
#define NBH  (BATCH*NUMH)   // 48

// ---------------- base-PTX tensor helpers (compute_80+) --------------------
__device__ __forceinline__ uint32_t smem_u32(const void* p) {
    uint32_t a;
    asm("{ .reg .u64 t; cvta.to.shared.u64 t, %1; cvt.u32.u64 %0, t; }"
        : "=r"(a) : "l"(p));
    return a;
}
__device__ __forceinline__ void cp16(uint32_t dst, const void* src) {
    asm volatile("cp.async.cg.shared.global [%0], [%1], 16;"
                 :: "r"(dst), "l"(src) : "memory");
}
__device__ __forceinline__ void cp_commit() {
    asm volatile("cp.async.commit_group;" ::: "memory");
}
template<int N>
__device__ __forceinline__ void cp_wait() {
    asm volatile("cp.async.wait_group %0;" :: "n"(N) : "memory");
}
__device__ __forceinline__ void ldsm4(uint32_t* r, uint32_t addr) {
    asm volatile("ldmatrix.sync.aligned.m8n8.x4.shared.b16 {%0,%1,%2,%3}, [%4];"
                 : "=r"(r[0]), "=r"(r[1]), "=r"(r[2]), "=r"(r[3]) : "r"(addr));
}
__device__ __forceinline__ void ldsm4t(uint32_t* r, uint32_t addr) {
    asm volatile("ldmatrix.sync.aligned.m8n8.x4.trans.shared.b16 {%0,%1,%2,%3}, [%4];"
                 : "=r"(r[0]), "=r"(r[1]), "=r"(r[2]), "=r"(r[3]) : "r"(addr));
}
__device__ __forceinline__ void mma16816(float* d, const uint32_t* a,
                                         uint32_t b0, uint32_t b1) {
    asm volatile(
        "mma.sync.aligned.m16n8k16.row.col.f32.bf16.bf16.f32 "
        "{%0,%1,%2,%3}, {%4,%5,%6,%7}, {%8,%9}, {%0,%1,%2,%3};"
        : "+f"(d[0]), "+f"(d[1]), "+f"(d[2]), "+f"(d[3])
        : "r"(a[0]), "r"(a[1]), "r"(a[2]), "r"(a[3]), "r"(b0), "r"(b1));
}
__device__ __forceinline__ void mma16816h(float* d, const uint32_t* a,
                                          uint32_t b0, uint32_t b1) {
    asm volatile(
        "mma.sync.aligned.m16n8k16.row.col.f32.f16.f16.f32 "
        "{%0,%1,%2,%3}, {%4,%5,%6,%7}, {%8,%9}, {%0,%1,%2,%3};"
        : "+f"(d[0]), "+f"(d[1]), "+f"(d[2]), "+f"(d[3])
        : "r"(a[0]), "r"(a[1]), "r"(a[2]), "r"(a[3]), "r"(b0), "r"(b1));
}
__device__ __forceinline__ uint32_t packhf(float lo, float hi) {
    uint32_t r;
    asm("cvt.rn.f16x2.f32 %0, %1, %2;" : "=r"(r) : "f"(hi), "f"(lo));
    return r;
}

// ---------------- scratch (device globals; no allocation allowed) ----------
__device__ float g_qkv[(size_t)MROWS * 3 * CH];          // [B*N, 2304]

// fp16 operands for QKV GEMM (1-pass)
__device__ __half g_xf[(size_t)MROWS * CH];
__device__ __half g_wqf[(size_t)3 * CH * CH];

// bf16 split weights for proj (3-pass)
__device__ __nv_bfloat16 g_wph[(size_t)CH * CH];
__device__ __nv_bfloat16 g_wpl[(size_t)CH * CH];

// attention operands: all fp16 (1-pass QK + 1-pass PV)
__device__ __half g_qf[(size_t)NBH*SEQ*HD];
__device__ __half g_kf[(size_t)NBH*SEQ*HD];
__device__ __half g_vf[(size_t)NBH*SEQ*HD];

// attention output split (proj A operand, bf16 hi/lo)
__device__ __nv_bfloat16 g_oh[(size_t)MROWS * CH];
__device__ __nv_bfloat16 g_ol[(size_t)MROWS * CH];

// ---------------- fp32 -> bf16 hi/lo split ---------------------------------
__global__ __launch_bounds__(256) void cvt_split(
    const float* __restrict__ s, __nv_bfloat16* __restrict__ h,
    __nv_bfloat16* __restrict__ l, int n4)
{
    int i = blockIdx.x * 256 + threadIdx.x;
    if (i >= n4) return;
    float4 v = ((const float4*)s)[i];
    __nv_bfloat16 hx = __float2bfloat16(v.x);
    __nv_bfloat16 hy = __float2bfloat16(v.y);
    __nv_bfloat16 hz = __float2bfloat16(v.z);
    __nv_bfloat16 hw = __float2bfloat16(v.w);
    __nv_bfloat162 h0, h1, l0, l1;
    h0.x = hx; h0.y = hy; h1.x = hz; h1.y = hw;
    l0.x = __float2bfloat16(v.x - __bfloat162float(hx));
    l0.y = __float2bfloat16(v.y - __bfloat162float(hy));
    l1.x = __float2bfloat16(v.z - __bfloat162float(hz));
    l1.y = __float2bfloat16(v.w - __bfloat162float(hw));
    ((__nv_bfloat162*)h)[2*i]   = h0;
    ((__nv_bfloat162*)h)[2*i+1] = h1;
    ((__nv_bfloat162*)l)[2*i]   = l0;
    ((__nv_bfloat162*)l)[2*i+1] = l1;
}

// ---------------- fp32 -> fp16 convert --------------------------------------
__global__ __launch_bounds__(256) void cvt_f16(
    const float* __restrict__ s, __half* __restrict__ d, int n4)
{
    int i = blockIdx.x * 256 + threadIdx.x;
    if (i >= n4) return;
    float4 v = ((const float4*)s)[i];
    __half2 a, b;
    a.x = __float2half(v.x); a.y = __float2half(v.y);
    b.x = __float2half(v.z); b.y = __float2half(v.w);
    ((__half2*)d)[2*i]   = a;
    ((__half2*)d)[2*i+1] = b;
}

// ---------------- shared GEMM geometry --------------------------------------
#define BM 128
#define BN 128
#define BKK 32
#define TILE_B   (BM*BKK*2)          // 8192 B per tile
#define STG_B    (4*TILE_B)          // 32768 B per stage (3-pass)
#define HSMEM    (2*STG_B)           // 65536 B
#define F16_STG  (2*TILE_B)          // 16384 B per stage (1-pass)
#define F16_SMEM (2*F16_STG)         // 32768 B

__device__ __forceinline__ uint32_t tswz(int row, int ch) {
    return (uint32_t)(row*64 + ((ch ^ ((row>>1)&3))<<4));
}

// ---------------- HMMA GEMM (1-pass fp16): C = A·Bᵀ -------------------------
__global__ __launch_bounds__(256, 2) void hmma_gemm_f16(
    const __half* __restrict__ A, const __half* __restrict__ B,
    float* __restrict__ C, int K, int ldc)
{
    extern __shared__ char smx[];
    uint32_t sb = smem_u32(smx);
    int tid = threadIdx.x, lane = tid & 31, warp = tid >> 5;
    int wm = warp >> 1, wn = warp & 1;
    int bm = blockIdx.y * BM, bn = blockIdx.x * BN;

    const __half* Ap = A + (size_t)bm * K;
    const __half* Bp = B + (size_t)bn * K;

    int r0 = tid >> 2, c0 = tid & 3;
    int r1 = r0 + 64;
    uint32_t sw0 = tswz(r0, c0), sw1 = tswz(r1, c0);

    float acc[2][8][4];
    #pragma unroll
    for (int mt = 0; mt < 2; mt++)
        #pragma unroll
        for (int nt = 0; nt < 8; nt++)
            #pragma unroll
            for (int j = 0; j < 4; j++) acc[mt][nt][j] = 0.f;

    int lrow8 = lane & 7, ghalf = (lane >> 3) & 1, ghi = lane >> 4;
    int NS = K / BKK;

    auto issue = [&](int s, int b) {
        uint32_t dst = sb + (uint32_t)b * F16_STG;
        size_t ko = (size_t)s * BKK;
        size_t o0 = (size_t)r0 * K + ko + c0*8;
        size_t o1 = (size_t)r1 * K + ko + c0*8;
        cp16(dst + sw0, Ap + o0);
        cp16(dst + sw1, Ap + o1);
        cp16(dst + TILE_B + sw0, Bp + o0);
        cp16(dst + TILE_B + sw1, Bp + o1);
        cp_commit();
    };

    issue(0, 0);
    for (int s = 0; s < NS; ++s) {
        int b = s & 1;
        if (s + 1 < NS) { issue(s + 1, b ^ 1); cp_wait<1>(); }
        else cp_wait<0>();
        __syncthreads();

        uint32_t stg = sb + (uint32_t)b * F16_STG;
        #pragma unroll
        for (int ks = 0; ks < 2; ++ks) {
            int kc = ks * 2;
            uint32_t fA[2][4], fB[4][4];
            #pragma unroll
            for (int mt = 0; mt < 2; mt++) {
                int r = wm*32 + mt*16 + lrow8 + ghalf*8;
                ldsm4(fA[mt], stg + tswz(r, kc + ghi));
            }
            #pragma unroll
            for (int t16 = 0; t16 < 4; t16++) {
                int r = wn*64 + t16*16 + lrow8 + ghalf*8;
                ldsm4(fB[t16], stg + TILE_B + tswz(r, kc + ghi));
            }
            #pragma unroll
            for (int mt = 0; mt < 2; mt++)
                #pragma unroll
                for (int nt = 0; nt < 8; nt++) {
                    int t16 = nt >> 1, hi = nt & 1;
                    mma16816h(acc[mt][nt], fA[mt], fB[t16][hi], fB[t16][hi+2]);
                }
        }
        __syncthreads();
    }

    #pragma unroll
    for (int mt = 0; mt < 2; mt++) {
        int rlo = bm + wm*32 + mt*16 + (lane >> 2);
        int rhi = rlo + 8;
        #pragma unroll
        for (int nt = 0; nt < 8; nt++) {
            int col = bn + wn*64 + nt*8 + (lane & 3)*2;
            float2 vlo = {acc[mt][nt][0], acc[mt][nt][1]};
            float2 vhi = {acc[mt][nt][2], acc[mt][nt][3]};
            *(float2*)&C[(size_t)rlo * ldc + col] = vlo;
            *(float2*)&C[(size_t)rhi * ldc + col] = vhi;
        }
    }
}

// ---------------- HMMA GEMM (3-pass bf16 hi/lo): C = A·Bᵀ (+bias) ----------
__global__ __launch_bounds__(256, 2) void hmma_gemm(
    const __nv_bfloat16* __restrict__ Ah, const __nv_bfloat16* __restrict__ Al,
    const __nv_bfloat16* __restrict__ Bh, const __nv_bfloat16* __restrict__ Bl,
    const float* __restrict__ bias, float* __restrict__ C,
    int K, int ldc)
{
    extern __shared__ char smx[];
    uint32_t sb = smem_u32(smx);
    int tid = threadIdx.x, lane = tid & 31, warp = tid >> 5;
    int wm = warp >> 1, wn = warp & 1;
    int bm = blockIdx.y * BM, bn = blockIdx.x * BN;

    const __nv_bfloat16* ApH = Ah + (size_t)bm * K;
    const __nv_bfloat16* ApL = Al + (size_t)bm * K;
    const __nv_bfloat16* BpH = Bh + (size_t)bn * K;
    const __nv_bfloat16* BpL = Bl + (size_t)bn * K;

    int r0 = tid >> 2, c0 = tid & 3;
    int r1 = r0 + 64;
    uint32_t sw0 = tswz(r0, c0), sw1 = tswz(r1, c0);

    float acc[2][8][4];
    #pragma unroll
    for (int mt = 0; mt < 2; mt++)
        #pragma unroll
        for (int nt = 0; nt < 8; nt++)
            #pragma unroll
            for (int j = 0; j < 4; j++) acc[mt][nt][j] = 0.f;

    int lrow8 = lane & 7, ghalf = (lane >> 3) & 1, ghi = lane >> 4;
    int NS = K / BKK;

    auto issue = [&](int s, int b) {
        uint32_t dst = sb + (uint32_t)b * STG_B;
        size_t ko = (size_t)s * BKK;
        size_t o0 = (size_t)r0 * K + ko + c0*8;
        size_t o1 = (size_t)r1 * K + ko + c0*8;
        cp16(dst + 0*TILE_B + sw0, ApH + o0);
        cp16(dst + 0*TILE_B + sw1, ApH + o1);
        cp16(dst + 1*TILE_B + sw0, ApL + o0);
        cp16(dst + 1*TILE_B + sw1, ApL + o1);
        cp16(dst + 2*TILE_B + sw0, BpH + o0);
        cp16(dst + 2*TILE_B + sw1, BpH + o1);
        cp16(dst + 3*TILE_B + sw0, BpL + o0);
        cp16(dst + 3*TILE_B + sw1, BpL + o1);
        cp_commit();
    };

    issue(0, 0);
    for (int s = 0; s < NS; ++s) {
        int b = s & 1;
        if (s + 1 < NS) { issue(s + 1, b ^ 1); cp_wait<1>(); }
        else cp_wait<0>();
        __syncthreads();

        uint32_t stg = sb + (uint32_t)b * STG_B;
        #pragma unroll
        for (int ks = 0; ks < 2; ++ks) {
            int kc = ks * 2;
            uint32_t fAh[2][4], fAl[2][4], fBh[4][4], fBl[4][4];
            #pragma unroll
            for (int mt = 0; mt < 2; mt++) {
                int r = wm*32 + mt*16 + lrow8 + ghalf*8;
                uint32_t ad = stg + tswz(r, kc + ghi);
                ldsm4(fAh[mt], ad);
                ldsm4(fAl[mt], ad + TILE_B);
            }
            #pragma unroll
            for (int t16 = 0; t16 < 4; t16++) {
                int r = wn*64 + t16*16 + lrow8 + ghalf*8;
                uint32_t ad = stg + 2*TILE_B + tswz(r, kc + ghi);
                ldsm4(fBh[t16], ad);
                ldsm4(fBl[t16], ad + TILE_B);
            }
            #pragma unroll
            for (int mt = 0; mt < 2; mt++)
                #pragma unroll
                for (int nt = 0; nt < 8; nt++) {
                    int t16 = nt >> 1, hi = nt & 1;
                    mma16816(acc[mt][nt], fAh[mt], fBh[t16][hi], fBh[t16][hi+2]);
                    mma16816(acc[mt][nt], fAh[mt], fBl[t16][hi], fBl[t16][hi+2]);
                    mma16816(acc[mt][nt], fAl[mt], fBh[t16][hi], fBh[t16][hi+2]);
                }
        }
        __syncthreads();
    }

    #pragma unroll
    for (int mt = 0; mt < 2; mt++) {
        int rlo = bm + wm*32 + mt*16 + (lane >> 2);
        int rhi = rlo + 8;
        #pragma unroll
        for (int nt = 0; nt < 8; nt++) {
            int col = bn + wn*64 + nt*8 + (lane & 3)*2;
            float b0 = 0.f, b1 = 0.f;
            if (bias) { b0 = bias[col]; b1 = bias[col+1]; }
            float2 vlo = {acc[mt][nt][0] + b0, acc[mt][nt][1] + b1};
            float2 vhi = {acc[mt][nt][2] + b0, acc[mt][nt][3] + b1};
            *(float2*)&C[(size_t)rlo * ldc + col] = vlo;
            *(float2*)&C[(size_t)rhi * ldc + col] = vhi;
        }
    }
}

// ---------- RMSnorm + RoPE + fp16 scatter [B*H,N,D] ------------------------
__global__ __launch_bounds__(128) void prep_kernel(
    const float* __restrict__ qkv, const float* __restrict__ cs,
    const float* __restrict__ sn, const float* __restrict__ qw,
    const float* __restrict__ kw,
    __half* __restrict__ qf, __half* __restrict__ kf,
    __half* __restrict__ vf)
{
    int task = blockIdx.x * 4 + (threadIdx.x >> 5);   // (b*H + h)*SEQ + n
    int lane = threadIdx.x & 31;
    int n  = task & (SEQ - 1);
    int bh = task >> 11;
    int h = bh % NUMH, b = bh / NUMH;

    const float* base = qkv + ((size_t)(b*SEQ + n)) * (3*CH) + h*HD;
    float q1 = base[lane],        q2 = base[lane+32];
    float k1 = base[CH+lane],     k2 = base[CH+lane+32];
    float v1 = base[2*CH+lane],   v2 = base[2*CH+lane+32];

    float sq = q1*q1 + q2*q2, sk = k1*k1 + k2*k2;
    #pragma unroll
    for (int o = 16; o >= 1; o >>= 1) {
        sq += __shfl_xor_sync(0xffffffffu, sq, o);
        sk += __shfl_xor_sync(0xffffffffu, sk, o);
    }
    float rq = rsqrtf(sq * (1.f/64.f) + 1e-6f) * 0.125f;   // fold attn scale into q
    float rk = rsqrtf(sk * (1.f/64.f) + 1e-6f);
    q1 *= rq * qw[lane]; q2 *= rq * qw[lane+32];
    k1 *= rk * kw[lane]; k2 *= rk * kw[lane+32];

    float c = cs[n*32 + lane], s = sn[n*32 + lane];
    float qa = q1*c - q2*s, qb2 = q2*c + q1*s;
    float ka = k1*c - k2*s, kb2 = k2*c + k1*s;

    size_t o = ((size_t)bh * SEQ + n) * HD + lane;
    qf[o]    = __float2half(qa);
    qf[o+32] = __float2half(qb2);
    kf[o]    = __float2half(ka);
    kf[o+32] = __float2half(kb2);
    vf[o]    = __float2half(v1);
    vf[o+32] = __float2half(v2);
}

// ---------------- flash attention via HMMA (all fp16) ----------------------
// 128 q x 64 k tiles. 8 warps, each owns 16 q rows. 1-pass fp16 QK and PV.
#define AQ 128
#define AK 64
#define ANT (SEQ/AK)            // 32
#define QF_OFF 0
#define ASTG0  (AQ*128)         // 16384
#define KF_O 0
#define VF_O (AK*128)           // 8192
#define ASTG (2*AK*128)         // 16384
#define ASMEM (ASTG0 + 2*ASTG)  // 49152

__device__ __forceinline__ uint32_t swz(int row, int ch) {
    return (uint32_t)(row*128 + ((ch ^ (row & 7)) << 4));
}

__global__ __launch_bounds__(256, 2) void attn_mma(
    const __half* __restrict__ Qf, const __half* __restrict__ Kf,
    const __half* __restrict__ Vf,
    __nv_bfloat16* __restrict__ Oh, __nv_bfloat16* __restrict__ Ol)
{
    extern __shared__ char smx[];
    uint32_t sb = smem_u32(smx);
    int tid = threadIdx.x, lane = tid & 31, warp = tid >> 5;
    int qt = blockIdx.x, bh = blockIdx.y;

    const __half* Qfb = Qf + ((size_t)bh*SEQ + qt*AQ) * HD;
    const __half* Kfb = Kf + (size_t)bh*SEQ*HD;
    const __half* Vfb = Vf + (size_t)bh*SEQ*HD;

    auto issueKV = [&](int s, int b) {
        uint32_t dst = sb + ASTG0 + (uint32_t)b * ASTG;
        #pragma unroll
        for (int t = 0; t < 2; ++t) {
            int v = tid + t*256;
            int row = v >> 3, ch = v & 7;
            size_t go = (size_t)(s*AK + row) * HD + ch*8;
            uint32_t so = swz(row, ch);
            cp16(dst + KF_O + so, Kfb + go);
            cp16(dst + VF_O + so, Vfb + go);
        }
        cp_commit();
    };

    // load Q + stage 0 in group 0
    {
        #pragma unroll
        for (int t = 0; t < 4; ++t) {
            int v = tid + t*256;
            int row = v >> 3, ch = v & 7;
            cp16(sb + QF_OFF + swz(row, ch), Qfb + (size_t)row * HD + ch*8);
        }
        #pragma unroll
        for (int t = 0; t < 2; ++t) {
            int v = tid + t*256;
            int row = v >> 3, ch = v & 7;
            size_t go = (size_t)row * HD + ch*8;
            uint32_t so = swz(row, ch);
            cp16(sb + ASTG0 + KF_O + so, Kfb + go);
            cp16(sb + ASTG0 + VF_O + so, Vfb + go);
        }
        cp_commit();
    }
    issueKV(1, 1);

    int lrow8 = lane & 7, ghalf = (lane >> 3) & 1, ghi = lane >> 4;
    int arow = warp*16 + lrow8 + ghalf*8;

    float m0 = -CUDART_INF_F, m1 = -CUDART_INF_F, sl0 = 0.f, sl1 = 0.f;
    float o[8][4];
    #pragma unroll
    for (int j = 0; j < 8; j++)
        #pragma unroll
        for (int t = 0; t < 4; t++) o[j][t] = 0.f;

    for (int kt = 0; kt < ANT; ++kt) {
        cp_wait<1>();
        __syncthreads();
        uint32_t stg = sb + ASTG0 + (uint32_t)(kt & 1) * ASTG;

        // ---- S = Q Kᵀ (1-pass fp16)
        float s[8][4];
        #pragma unroll
        for (int j = 0; j < 8; j++)
            #pragma unroll
            for (int t = 0; t < 4; t++) s[j][t] = 0.f;
        #pragma unroll
        for (int ks = 0; ks < 4; ++ks) {
            uint32_t aF[4];
            ldsm4(aF, sb + QF_OFF + swz(arow, ks*2 + ghi));
            #pragma unroll
            for (int nt = 0; nt < 4; ++nt) {
                uint32_t bF[4];
                ldsm4(bF, stg + KF_O + swz(nt*16 + lrow8 + ghalf*8, ks*2 + ghi));
                mma16816h(s[nt*2],   aF, bF[0], bF[2]);
                mma16816h(s[nt*2+1], aF, bF[1], bF[3]);
            }
        }

        // ---- online softmax (rows r and r+8)
        float mx0 = -CUDART_INF_F, mx1 = -CUDART_INF_F;
        #pragma unroll
        for (int j = 0; j < 8; j++) {
            mx0 = fmaxf(mx0, fmaxf(s[j][0], s[j][1]));
            mx1 = fmaxf(mx1, fmaxf(s[j][2], s[j][3]));
        }
        mx0 = fmaxf(mx0, __shfl_xor_sync(0xffffffffu, mx0, 1));
        mx0 = fmaxf(mx0, __shfl_xor_sync(0xffffffffu, mx0, 2));
        mx1 = fmaxf(mx1, __shfl_xor_sync(0xffffffffu, mx1, 1));
        mx1 = fmaxf(mx1, __shfl_xor_sync(0xffffffffu, mx1, 2));
        float nm0 = fmaxf(m0, mx0), nm1 = fmaxf(m1, mx1);
        float al0 = __expf(m0 - nm0), al1 = __expf(m1 - nm1);
        m0 = nm0; m1 = nm1;
        float rs0 = 0.f, rs1 = 0.f;
        #pragma unroll
        for (int j = 0; j < 8; j++) {
            s[j][0] = __expf(s[j][0] - nm0); rs0 += s[j][0];
            s[j][1] = __expf(s[j][1] - nm0); rs0 += s[j][1];
            s[j][2] = __expf(s[j][2] - nm1); rs1 += s[j][2];
            s[j][3] = __expf(s[j][3] - nm1); rs1 += s[j][3];
        }
        rs0 += __shfl_xor_sync(0xffffffffu, rs0, 1);
        rs0 += __shfl_xor_sync(0xffffffffu, rs0, 2);
        rs1 += __shfl_xor_sync(0xffffffffu, rs1, 1);
        rs1 += __shfl_xor_sync(0xffffffffu, rs1, 2);
        sl0 = sl0*al0 + rs0;
        sl1 = sl1*al1 + rs1;
        #pragma unroll
        for (int j = 0; j < 8; j++) {
            o[j][0] *= al0; o[j][1] *= al0;
            o[j][2] *= al1; o[j][3] *= al1;
        }

        // ---- O += P V (1-pass fp16)
        #pragma unroll
        for (int ks = 0; ks < 4; ++ks) {
            uint32_t ph[4];
            ph[0] = packhf(s[2*ks][0],   s[2*ks][1]);
            ph[1] = packhf(s[2*ks][2],   s[2*ks][3]);
            ph[2] = packhf(s[2*ks+1][0], s[2*ks+1][1]);
            ph[3] = packhf(s[2*ks+1][2], s[2*ks+1][3]);

            int vrow = ks*16 + lrow8 + ghalf*8;
            #pragma unroll
            for (int nb2 = 0; nb2 < 4; ++nb2) {
                uint32_t vF[4];
                ldsm4t(vF, stg + VF_O + swz(vrow, nb2*2 + ghi));
                mma16816h(o[nb2*2],   ph, vF[0], vF[1]);
                mma16816h(o[nb2*2+1], ph, vF[2], vF[3]);
            }
        }
        __syncthreads();
        if (kt + 2 < ANT) issueKV(kt + 2, kt & 1);
    }

    // ---- epilogue: normalize, split to bf16 hi/lo, write [B,N,C]
    int b_ = bh / NUMH, h_ = bh % NUMH;
    int r0 = warp*16 + (lane >> 2);
    size_t row0 = (size_t)b_*SEQ + qt*AQ + r0;
    size_t row1 = row0 + 8;
    float inv0 = 1.f / sl0, inv1 = 1.f / sl1;
    #pragma unroll
    for (int j = 0; j < 8; j++) {
        int col = h_*HD + j*8 + (lane & 3)*2;
        float f0 = o[j][0]*inv0, f1 = o[j][1]*inv0;
        float f2 = o[j][2]*inv1, f3 = o[j][3]*inv1;
        __nv_bfloat162 hh, ll;
        hh.x = __float2bfloat16(f0); hh.y = __float2bfloat16(f1);
        ll.x = __float2bfloat16(f0 - __bfloat162float(hh.x));
        ll.y = __float2bfloat16(f1 - __bfloat162float(hh.y));
        *(__nv_bfloat162*)&Oh[row0*CH + col] = hh;
        *(__nv_bfloat162*)&Ol[row0*CH + col] = ll;
        hh.x = __float2bfloat16(f2); hh.y = __float2bfloat16(f3);
        ll.x = __float2bfloat16(f2 - __bfloat162float(hh.x));
        ll.y = __float2bfloat16(f3 - __bfloat162float(hh.y));
        *(__nv_bfloat162*)&Oh[row1*CH + col] = hh;
        *(__nv_bfloat162*)&Ol[row1*CH + col] = ll;
    }
}

// ---------------------------------------------------------------------------
extern "C" void kernel_launch(void* const* d_in, const int* in_sizes, int n_in,
                              void* d_out, int out_size)
{
    const float* x      = (const float*)d_in[0];
    const float* cs     = (const float*)d_in[1];
    const float* sn     = (const float*)d_in[2];
    const float* qkv_w  = (const float*)d_in[3];
    const float* qnw    = (const float*)d_in[4];
    const float* knw    = (const float*)d_in[5];
    const float* proj_w = (const float*)d_in[6];
    const float* proj_b = (const float*)d_in[7];
    float* out = (float*)d_out;

    float* qkv;
    cudaGetSymbolAddress((void**)&qkv, g_qkv);
    __half *xf, *wqf, *qf, *kf, *vf;
    __nv_bfloat16 *wph, *wpl, *oh, *ol;
    cudaGetSymbolAddress((void**)&xf,  g_xf);
    cudaGetSymbolAddress((void**)&wqf, g_wqf);
    cudaGetSymbolAddress((void**)&wph, g_wph);
    cudaGetSymbolAddress((void**)&wpl, g_wpl);
    cudaGetSymbolAddress((void**)&oh,  g_oh);
    cudaGetSymbolAddress((void**)&ol,  g_ol);
    cudaGetSymbolAddress((void**)&qf,  g_qf);
    cudaGetSymbolAddress((void**)&kf,  g_kf);
    cudaGetSymbolAddress((void**)&vf,  g_vf);

    // 0) converts: x/qkv_w -> fp16; proj_w -> bf16 hi/lo
    {
        int n4x = MROWS*CH/4, n4q = 3*CH*CH/4, n4p = CH*CH/4;
        cvt_f16<<<(n4x+255)/256, 256>>>(x, xf, n4x);
        cvt_f16<<<(n4q+255)/256, 256>>>(qkv_w, wqf, n4q);
        cvt_split<<<(n4p+255)/256, 256>>>(proj_w, wph, wpl, n4p);
    }

    // 1) QKV projection (HMMA, 1-pass fp16)
    cudaFuncSetAttribute(hmma_gemm_f16, cudaFuncAttributeMaxDynamicSharedMemorySize,
                         F16_SMEM);
    hmma_gemm_f16<<<dim3(3*CH/BN, MROWS/BM), 256, F16_SMEM>>>(
        xf, wqf, qkv, CH, 3*CH);

    // 2) RMSnorm + RoPE + fp16 scatter
    prep_kernel<<<(NBH*SEQ)/4, 128>>>(qkv, cs, sn, qnw, knw, qf, kf, vf);

    // 3) flash attention (HMMA, all fp16)
    cudaFuncSetAttribute(attn_mma, cudaFuncAttributeMaxDynamicSharedMemorySize,
                         ASMEM);
    attn_mma<<<dim3(SEQ/AQ, NBH), 256, ASMEM>>>(qf, kf, vf, oh, ol);

    // 4) output projection (+bias, HMMA 3-pass bf16)
    cudaFuncSetAttribute(hmma_gemm, cudaFuncAttributeMaxDynamicSharedMemorySize,
                         HSMEM);
    hmma_gemm<<<dim3(CH/BN, MROWS/BM), 256, HSMEM>>>(
        oh, ol, wph, wpl, proj_b, out, CH, CH);
}

// round 16
// speedup vs baseline: 6.9295x; 1.1622x over previous
#include <cuda_runtime.h>
#include <cuda_bf16.h>
#include <cuda_fp16.h>
#include <math_constants.h>
#include <cstdint>

#define NUMH 12
#define HD   64
#define BATCH 4
#define SEQ  2048
#define CH   768
#define MROWS (BATCH*SEQ)   // 8192
#define NBH  (BATCH*NUMH)   // 48

// ---------------- base-PTX tensor helpers (compute_80+) --------------------
__device__ __forceinline__ uint32_t smem_u32(const void* p) {
    uint32_t a;
    asm("{ .reg .u64 t; cvta.to.shared.u64 t, %1; cvt.u32.u64 %0, t; }"
        : "=r"(a) : "l"(p));
    return a;
}
__device__ __forceinline__ void cp16(uint32_t dst, const void* src) {
    asm volatile("cp.async.cg.shared.global [%0], [%1], 16;"
                 :: "r"(dst), "l"(src) : "memory");
}
__device__ __forceinline__ void cp_commit() {
    asm volatile("cp.async.commit_group;" ::: "memory");
}
template<int N>
__device__ __forceinline__ void cp_wait() {
    asm volatile("cp.async.wait_group %0;" :: "n"(N) : "memory");
}
__device__ __forceinline__ void ldsm4(uint32_t* r, uint32_t addr) {
    asm volatile("ldmatrix.sync.aligned.m8n8.x4.shared.b16 {%0,%1,%2,%3}, [%4];"
                 : "=r"(r[0]), "=r"(r[1]), "=r"(r[2]), "=r"(r[3]) : "r"(addr));
}
__device__ __forceinline__ void ldsm4t(uint32_t* r, uint32_t addr) {
    asm volatile("ldmatrix.sync.aligned.m8n8.x4.trans.shared.b16 {%0,%1,%2,%3}, [%4];"
                 : "=r"(r[0]), "=r"(r[1]), "=r"(r[2]), "=r"(r[3]) : "r"(addr));
}
__device__ __forceinline__ void mma16816h(float* d, const uint32_t* a,
                                          uint32_t b0, uint32_t b1) {
    asm volatile(
        "mma.sync.aligned.m16n8k16.row.col.f32.f16.f16.f32 "
        "{%0,%1,%2,%3}, {%4,%5,%6,%7}, {%8,%9}, {%0,%1,%2,%3};"
        : "+f"(d[0]), "+f"(d[1]), "+f"(d[2]), "+f"(d[3])
        : "r"(a[0]), "r"(a[1]), "r"(a[2]), "r"(a[3]), "r"(b0), "r"(b1));
}
__device__ __forceinline__ uint32_t packhf(float lo, float hi) {
    uint32_t r;
    asm("cvt.rn.f16x2.f32 %0, %1, %2;" : "=r"(r) : "f"(hi), "f"(lo));
    return r;
}

// ---------------- scratch (device globals; no allocation allowed) ----------
__device__ float g_qkv[(size_t)MROWS * 3 * CH];          // [B*N, 2304]

// fp16 operands for GEMMs (1-pass)
__device__ __half g_xf[(size_t)MROWS * CH];
__device__ __half g_wqf[(size_t)3 * CH * CH];
__device__ __half g_wpf[(size_t)CH * CH];

// attention operands: all fp16
__device__ __half g_qf[(size_t)NBH*SEQ*HD];
__device__ __half g_kf[(size_t)NBH*SEQ*HD];
__device__ __half g_vf[(size_t)NBH*SEQ*HD];

// attention output (proj A operand, fp16)
__device__ __half g_of[(size_t)MROWS * CH];

// ---------------- fp32 -> fp16 convert --------------------------------------
__global__ __launch_bounds__(256) void cvt_f16(
    const float* __restrict__ s, __half* __restrict__ d, int n4)
{
    int i = blockIdx.x * 256 + threadIdx.x;
    if (i >= n4) return;
    float4 v = ((const float4*)s)[i];
    __half2 a, b;
    a.x = __float2half(v.x); a.y = __float2half(v.y);
    b.x = __float2half(v.z); b.y = __float2half(v.w);
    ((__half2*)d)[2*i]   = a;
    ((__half2*)d)[2*i+1] = b;
}

// ---------------- shared GEMM geometry --------------------------------------
#define BM 128
#define BN 128
#define BKK 32
#define TILE_B   (BM*BKK*2)          // 8192 B per tile
#define F16_STG  (2*TILE_B)          // 16384 B per stage
#define F16_SMEM (2*F16_STG)         // 32768 B

__device__ __forceinline__ uint32_t tswz(int row, int ch) {
    return (uint32_t)(row*64 + ((ch ^ ((row>>1)&3))<<4));
}

// ---------------- HMMA GEMM (1-pass fp16): C = A·Bᵀ (+bias) -----------------
__global__ __launch_bounds__(256, 2) void hmma_gemm_f16(
    const __half* __restrict__ A, const __half* __restrict__ B,
    const float* __restrict__ bias, float* __restrict__ C, int K, int ldc)
{
    extern __shared__ char smx[];
    uint32_t sb = smem_u32(smx);
    int tid = threadIdx.x, lane = tid & 31, warp = tid >> 5;
    int wm = warp >> 1, wn = warp & 1;
    int bm = blockIdx.y * BM, bn = blockIdx.x * BN;

    const __half* Ap = A + (size_t)bm * K;
    const __half* Bp = B + (size_t)bn * K;

    int r0 = tid >> 2, c0 = tid & 3;
    int r1 = r0 + 64;
    uint32_t sw0 = tswz(r0, c0), sw1 = tswz(r1, c0);

    float acc[2][8][4];
    #pragma unroll
    for (int mt = 0; mt < 2; mt++)
        #pragma unroll
        for (int nt = 0; nt < 8; nt++)
            #pragma unroll
            for (int j = 0; j < 4; j++) acc[mt][nt][j] = 0.f;

    int lrow8 = lane & 7, ghalf = (lane >> 3) & 1, ghi = lane >> 4;
    int NS = K / BKK;

    auto issue = [&](int s, int b) {
        uint32_t dst = sb + (uint32_t)b * F16_STG;
        size_t ko = (size_t)s * BKK;
        size_t o0 = (size_t)r0 * K + ko + c0*8;
        size_t o1 = (size_t)r1 * K + ko + c0*8;
        cp16(dst + sw0, Ap + o0);
        cp16(dst + sw1, Ap + o1);
        cp16(dst + TILE_B + sw0, Bp + o0);
        cp16(dst + TILE_B + sw1, Bp + o1);
        cp_commit();
    };

    issue(0, 0);
    for (int s = 0; s < NS; ++s) {
        int b = s & 1;
        if (s + 1 < NS) { issue(s + 1, b ^ 1); cp_wait<1>(); }
        else cp_wait<0>();
        __syncthreads();

        uint32_t stg = sb + (uint32_t)b * F16_STG;
        #pragma unroll
        for (int ks = 0; ks < 2; ++ks) {
            int kc = ks * 2;
            uint32_t fA[2][4], fB[4][4];
            #pragma unroll
            for (int mt = 0; mt < 2; mt++) {
                int r = wm*32 + mt*16 + lrow8 + ghalf*8;
                ldsm4(fA[mt], stg + tswz(r, kc + ghi));
            }
            #pragma unroll
            for (int t16 = 0; t16 < 4; t16++) {
                int r = wn*64 + t16*16 + lrow8 + ghalf*8;
                ldsm4(fB[t16], stg + TILE_B + tswz(r, kc + ghi));
            }
            #pragma unroll
            for (int mt = 0; mt < 2; mt++)
                #pragma unroll
                for (int nt = 0; nt < 8; nt++) {
                    int t16 = nt >> 1, hi = nt & 1;
                    mma16816h(acc[mt][nt], fA[mt], fB[t16][hi], fB[t16][hi+2]);
                }
        }
        __syncthreads();
    }

    #pragma unroll
    for (int mt = 0; mt < 2; mt++) {
        int rlo = bm + wm*32 + mt*16 + (lane >> 2);
        int rhi = rlo + 8;
        #pragma unroll
        for (int nt = 0; nt < 8; nt++) {
            int col = bn + wn*64 + nt*8 + (lane & 3)*2;
            float b0 = 0.f, b1 = 0.f;
            if (bias) { b0 = bias[col]; b1 = bias[col+1]; }
            float2 vlo = {acc[mt][nt][0] + b0, acc[mt][nt][1] + b1};
            float2 vhi = {acc[mt][nt][2] + b0, acc[mt][nt][3] + b1};
            *(float2*)&C[(size_t)rlo * ldc + col] = vlo;
            *(float2*)&C[(size_t)rhi * ldc + col] = vhi;
        }
    }
}

// ---------- RMSnorm + RoPE + fp16 scatter [B*H,N,D] ------------------------
__global__ __launch_bounds__(128) void prep_kernel(
    const float* __restrict__ qkv, const float* __restrict__ cs,
    const float* __restrict__ sn, const float* __restrict__ qw,
    const float* __restrict__ kw,
    __half* __restrict__ qf, __half* __restrict__ kf,
    __half* __restrict__ vf)
{
    int task = blockIdx.x * 4 + (threadIdx.x >> 5);   // (b*H + h)*SEQ + n
    int lane = threadIdx.x & 31;
    int n  = task & (SEQ - 1);
    int bh = task >> 11;
    int h = bh % NUMH, b = bh / NUMH;

    const float* base = qkv + ((size_t)(b*SEQ + n)) * (3*CH) + h*HD;
    float q1 = base[lane],        q2 = base[lane+32];
    float k1 = base[CH+lane],     k2 = base[CH+lane+32];
    float v1 = base[2*CH+lane],   v2 = base[2*CH+lane+32];

    float sq = q1*q1 + q2*q2, sk = k1*k1 + k2*k2;
    #pragma unroll
    for (int o = 16; o >= 1; o >>= 1) {
        sq += __shfl_xor_sync(0xffffffffu, sq, o);
        sk += __shfl_xor_sync(0xffffffffu, sk, o);
    }
    float rq = rsqrtf(sq * (1.f/64.f) + 1e-6f) * 0.125f;   // fold attn scale into q
    float rk = rsqrtf(sk * (1.f/64.f) + 1e-6f);
    q1 *= rq * qw[lane]; q2 *= rq * qw[lane+32];
    k1 *= rk * kw[lane]; k2 *= rk * kw[lane+32];

    float c = cs[n*32 + lane], s = sn[n*32 + lane];
    float qa = q1*c - q2*s, qb2 = q2*c + q1*s;
    float ka = k1*c - k2*s, kb2 = k2*c + k1*s;

    size_t o = ((size_t)bh * SEQ + n) * HD + lane;
    qf[o]    = __float2half(qa);
    qf[o+32] = __float2half(qb2);
    kf[o]    = __float2half(ka);
    kf[o+32] = __float2half(kb2);
    vf[o]    = __float2half(v1);
    vf[o+32] = __float2half(v2);
}

// ---------------- flash attention via HMMA (all fp16) ----------------------
// 128 q x 64 k tiles. 8 warps, each owns 16 q rows. 1-pass fp16 QK and PV.
#define AQ 128
#define AK 64
#define ANT (SEQ/AK)            // 32
#define QF_OFF 0
#define ASTG0  (AQ*128)         // 16384
#define KF_O 0
#define VF_O (AK*128)           // 8192
#define ASTG (2*AK*128)         // 16384
#define ASMEM (ASTG0 + 2*ASTG)  // 49152

__device__ __forceinline__ uint32_t swz(int row, int ch) {
    return (uint32_t)(row*128 + ((ch ^ (row & 7)) << 4));
}

__global__ __launch_bounds__(256, 2) void attn_mma(
    const __half* __restrict__ Qf, const __half* __restrict__ Kf,
    const __half* __restrict__ Vf, __half* __restrict__ Of)
{
    extern __shared__ char smx[];
    uint32_t sb = smem_u32(smx);
    int tid = threadIdx.x, lane = tid & 31, warp = tid >> 5;
    int qt = blockIdx.x, bh = blockIdx.y;

    const __half* Qfb = Qf + ((size_t)bh*SEQ + qt*AQ) * HD;
    const __half* Kfb = Kf + (size_t)bh*SEQ*HD;
    const __half* Vfb = Vf + (size_t)bh*SEQ*HD;

    auto issueKV = [&](int s, int b) {
        uint32_t dst = sb + ASTG0 + (uint32_t)b * ASTG;
        #pragma unroll
        for (int t = 0; t < 2; ++t) {
            int v = tid + t*256;
            int row = v >> 3, ch = v & 7;
            size_t go = (size_t)(s*AK + row) * HD + ch*8;
            uint32_t so = swz(row, ch);
            cp16(dst + KF_O + so, Kfb + go);
            cp16(dst + VF_O + so, Vfb + go);
        }
        cp_commit();
    };

    // load Q + stage 0 in group 0
    {
        #pragma unroll
        for (int t = 0; t < 4; ++t) {
            int v = tid + t*256;
            int row = v >> 3, ch = v & 7;
            cp16(sb + QF_OFF + swz(row, ch), Qfb + (size_t)row * HD + ch*8);
        }
        #pragma unroll
        for (int t = 0; t < 2; ++t) {
            int v = tid + t*256;
            int row = v >> 3, ch = v & 7;
            size_t go = (size_t)row * HD + ch*8;
            uint32_t so = swz(row, ch);
            cp16(sb + ASTG0 + KF_O + so, Kfb + go);
            cp16(sb + ASTG0 + VF_O + so, Vfb + go);
        }
        cp_commit();
    }
    issueKV(1, 1);

    int lrow8 = lane & 7, ghalf = (lane >> 3) & 1, ghi = lane >> 4;
    int arow = warp*16 + lrow8 + ghalf*8;

    float m0 = -CUDART_INF_F, m1 = -CUDART_INF_F, sl0 = 0.f, sl1 = 0.f;
    float o[8][4];
    #pragma unroll
    for (int j = 0; j < 8; j++)
        #pragma unroll
        for (int t = 0; t < 4; t++) o[j][t] = 0.f;

    for (int kt = 0; kt < ANT; ++kt) {
        cp_wait<1>();
        __syncthreads();
        uint32_t stg = sb + ASTG0 + (uint32_t)(kt & 1) * ASTG;

        // ---- S = Q Kᵀ (1-pass fp16)
        float s[8][4];
        #pragma unroll
        for (int j = 0; j < 8; j++)
            #pragma unroll
            for (int t = 0; t < 4; t++) s[j][t] = 0.f;
        #pragma unroll
        for (int ks = 0; ks < 4; ++ks) {
            uint32_t aF[4];
            ldsm4(aF, sb + QF_OFF + swz(arow, ks*2 + ghi));
            #pragma unroll
            for (int nt = 0; nt < 4; ++nt) {
                uint32_t bF[4];
                ldsm4(bF, stg + KF_O + swz(nt*16 + lrow8 + ghalf*8, ks*2 + ghi));
                mma16816h(s[nt*2],   aF, bF[0], bF[2]);
                mma16816h(s[nt*2+1], aF, bF[1], bF[3]);
            }
        }

        // ---- online softmax (rows r and r+8)
        float mx0 = -CUDART_INF_F, mx1 = -CUDART_INF_F;
        #pragma unroll
        for (int j = 0; j < 8; j++) {
            mx0 = fmaxf(mx0, fmaxf(s[j][0], s[j][1]));
            mx1 = fmaxf(mx1, fmaxf(s[j][2], s[j][3]));
        }
        mx0 = fmaxf(mx0, __shfl_xor_sync(0xffffffffu, mx0, 1));
        mx0 = fmaxf(mx0, __shfl_xor_sync(0xffffffffu, mx0, 2));
        mx1 = fmaxf(mx1, __shfl_xor_sync(0xffffffffu, mx1, 1));
        mx1 = fmaxf(mx1, __shfl_xor_sync(0xffffffffu, mx1, 2));
        float nm0 = fmaxf(m0, mx0), nm1 = fmaxf(m1, mx1);
        float al0 = __expf(m0 - nm0), al1 = __expf(m1 - nm1);
        m0 = nm0; m1 = nm1;
        float rs0 = 0.f, rs1 = 0.f;
        #pragma unroll
        for (int j = 0; j < 8; j++) {
            s[j][0] = __expf(s[j][0] - nm0); rs0 += s[j][0];
            s[j][1] = __expf(s[j][1] - nm0); rs0 += s[j][1];
            s[j][2] = __expf(s[j][2] - nm1); rs1 += s[j][2];
            s[j][3] = __expf(s[j][3] - nm1); rs1 += s[j][3];
        }
        rs0 += __shfl_xor_sync(0xffffffffu, rs0, 1);
        rs0 += __shfl_xor_sync(0xffffffffu, rs0, 2);
        rs1 += __shfl_xor_sync(0xffffffffu, rs1, 1);
        rs1 += __shfl_xor_sync(0xffffffffu, rs1, 2);
        sl0 = sl0*al0 + rs0;
        sl1 = sl1*al1 + rs1;
        #pragma unroll
        for (int j = 0; j < 8; j++) {
            o[j][0] *= al0; o[j][1] *= al0;
            o[j][2] *= al1; o[j][3] *= al1;
        }

        // ---- O += P V (1-pass fp16)
        #pragma unroll
        for (int ks = 0; ks < 4; ++ks) {
            uint32_t ph[4];
            ph[0] = packhf(s[2*ks][0],   s[2*ks][1]);
            ph[1] = packhf(s[2*ks][2],   s[2*ks][3]);
            ph[2] = packhf(s[2*ks+1][0], s[2*ks+1][1]);
            ph[3] = packhf(s[2*ks+1][2], s[2*ks+1][3]);

            int vrow = ks*16 + lrow8 + ghalf*8;
            #pragma unroll
            for (int nb2 = 0; nb2 < 4; ++nb2) {
                uint32_t vF[4];
                ldsm4t(vF, stg + VF_O + swz(vrow, nb2*2 + ghi));
                mma16816h(o[nb2*2],   ph, vF[0], vF[1]);
                mma16816h(o[nb2*2+1], ph, vF[2], vF[3]);
            }
        }
        __syncthreads();
        if (kt + 2 < ANT) issueKV(kt + 2, kt & 1);
    }

    // ---- epilogue: normalize, write fp16 O [B,N,C]
    int b_ = bh / NUMH, h_ = bh % NUMH;
    int r0 = warp*16 + (lane >> 2);
    size_t row0 = (size_t)b_*SEQ + qt*AQ + r0;
    size_t row1 = row0 + 8;
    float inv0 = 1.f / sl0, inv1 = 1.f / sl1;
    #pragma unroll
    for (int j = 0; j < 8; j++) {
        int col = h_*HD + j*8 + (lane & 3)*2;
        __half2 h0, h1;
        h0.x = __float2half(o[j][0]*inv0); h0.y = __float2half(o[j][1]*inv0);
        h1.x = __float2half(o[j][2]*inv1); h1.y = __float2half(o[j][3]*inv1);
        *(__half2*)&Of[row0*CH + col] = h0;
        *(__half2*)&Of[row1*CH + col] = h1;
    }
}

// ---------------------------------------------------------------------------
extern "C" void kernel_launch(void* const* d_in, const int* in_sizes, int n_in,
                              void* d_out, int out_size)
{
    const float* x      = (const float*)d_in[0];
    const float* cs     = (const float*)d_in[1];
    const float* sn     = (const float*)d_in[2];
    const float* qkv_w  = (const float*)d_in[3];
    const float* qnw    = (const float*)d_in[4];
    const float* knw    = (const float*)d_in[5];
    const float* proj_w = (const float*)d_in[6];
    const float* proj_b = (const float*)d_in[7];
    float* out = (float*)d_out;

    float* qkv;
    cudaGetSymbolAddress((void**)&qkv, g_qkv);
    __half *xf, *wqf, *wpf, *qf, *kf, *vf, *of;
    cudaGetSymbolAddress((void**)&xf,  g_xf);
    cudaGetSymbolAddress((void**)&wqf, g_wqf);
    cudaGetSymbolAddress((void**)&wpf, g_wpf);
    cudaGetSymbolAddress((void**)&qf,  g_qf);
    cudaGetSymbolAddress((void**)&kf,  g_kf);
    cudaGetSymbolAddress((void**)&vf,  g_vf);
    cudaGetSymbolAddress((void**)&of,  g_of);

    // 0) converts: x/qkv_w/proj_w -> fp16
    {
        int n4x = MROWS*CH/4, n4q = 3*CH*CH/4, n4p = CH*CH/4;
        cvt_f16<<<(n4x+255)/256, 256>>>(x, xf, n4x);
        cvt_f16<<<(n4q+255)/256, 256>>>(qkv_w, wqf, n4q);
        cvt_f16<<<(n4p+255)/256, 256>>>(proj_w, wpf, n4p);
    }

    // 1) QKV projection (HMMA, 1-pass fp16)
    cudaFuncSetAttribute(hmma_gemm_f16, cudaFuncAttributeMaxDynamicSharedMemorySize,
                         F16_SMEM);
    hmma_gemm_f16<<<dim3(3*CH/BN, MROWS/BM), 256, F16_SMEM>>>(
        xf, wqf, nullptr, qkv, CH, 3*CH);

    // 2) RMSnorm + RoPE + fp16 scatter
    prep_kernel<<<(NBH*SEQ)/4, 128>>>(qkv, cs, sn, qnw, knw, qf, kf, vf);

    // 3) flash attention (HMMA, all fp16, fp16 O out)
    cudaFuncSetAttribute(attn_mma, cudaFuncAttributeMaxDynamicSharedMemorySize,
                         ASMEM);
    attn_mma<<<dim3(SEQ/AQ, NBH), 256, ASMEM>>>(qf, kf, vf, of);

    // 4) output projection (+bias, HMMA 1-pass fp16)
    hmma_gemm_f16<<<dim3(CH/BN, MROWS/BM), 256, F16_SMEM>>>(
        of, wpf, proj_b, out, CH, CH);
}

// round 17
// speedup vs baseline: 7.2069x; 1.0400x over previous
#include <cuda_runtime.h>
#include <cuda_fp16.h>
#include <math_constants.h>
#include <cstdint>

#define NUMH 12
#define HD   64
#define BATCH 4
#define SEQ  2048
#define CH   768
#define MROWS (BATCH*SEQ)   // 8192
#define NBH  (BATCH*NUMH)   // 48

// ---------------- base-PTX tensor helpers (compute_80+) --------------------
__device__ __forceinline__ uint32_t smem_u32(const void* p) {
    uint32_t a;
    asm("{ .reg .u64 t; cvta.to.shared.u64 t, %1; cvt.u32.u64 %0, t; }"
        : "=r"(a) : "l"(p));
    return a;
}
__device__ __forceinline__ void cp16(uint32_t dst, const void* src) {
    asm volatile("cp.async.cg.shared.global [%0], [%1], 16;"
                 :: "r"(dst), "l"(src) : "memory");
}
__device__ __forceinline__ void cp_commit() {
    asm volatile("cp.async.commit_group;" ::: "memory");
}
template<int N>
__device__ __forceinline__ void cp_wait() {
    asm volatile("cp.async.wait_group %0;" :: "n"(N) : "memory");
}
__device__ __forceinline__ void ldsm4(uint32_t* r, uint32_t addr) {
    asm volatile("ldmatrix.sync.aligned.m8n8.x4.shared.b16 {%0,%1,%2,%3}, [%4];"
                 : "=r"(r[0]), "=r"(r[1]), "=r"(r[2]), "=r"(r[3]) : "r"(addr));
}
__device__ __forceinline__ void ldsm4t(uint32_t* r, uint32_t addr) {
    asm volatile("ldmatrix.sync.aligned.m8n8.x4.trans.shared.b16 {%0,%1,%2,%3}, [%4];"
                 : "=r"(r[0]), "=r"(r[1]), "=r"(r[2]), "=r"(r[3]) : "r"(addr));
}
__device__ __forceinline__ void mma16816h(float* d, const uint32_t* a,
                                          uint32_t b0, uint32_t b1) {
    asm volatile(
        "mma.sync.aligned.m16n8k16.row.col.f32.f16.f16.f32 "
        "{%0,%1,%2,%3}, {%4,%5,%6,%7}, {%8,%9}, {%0,%1,%2,%3};"
        : "+f"(d[0]), "+f"(d[1]), "+f"(d[2]), "+f"(d[3])
        : "r"(a[0]), "r"(a[1]), "r"(a[2]), "r"(a[3]), "r"(b0), "r"(b1));
}
__device__ __forceinline__ uint32_t packhf(float lo, float hi) {
    uint32_t r;
    asm("cvt.rn.f16x2.f32 %0, %1, %2;" : "=r"(r) : "f"(hi), "f"(lo));
    return r;
}
// epilogue store overloads
__device__ __forceinline__ void store2(float* C, size_t idx, float a, float b) {
    float2 v = {a, b}; *(float2*)&C[idx] = v;
}
__device__ __forceinline__ void store2(__half* C, size_t idx, float a, float b) {
    __half2 v; v.x = __float2half(a); v.y = __float2half(b);
    *(__half2*)&C[idx] = v;
}

// ---------------- scratch (device globals; no allocation allowed) ----------
__device__ __half g_qkvh[(size_t)MROWS * 3 * CH];        // fp16 qkv intermediate

// fp16 operands for GEMMs
__device__ __half g_xf[(size_t)MROWS * CH];
__device__ __half g_wqf[(size_t)3 * CH * CH];
__device__ __half g_wpf[(size_t)CH * CH];

// attention operands: all fp16
__device__ __half g_qf[(size_t)NBH*SEQ*HD];
__device__ __half g_kf[(size_t)NBH*SEQ*HD];
__device__ __half g_vf[(size_t)NBH*SEQ*HD];

// attention output (proj A operand, fp16)
__device__ __half g_of[(size_t)MROWS * CH];

// ---------------- fp32 -> fp16 convert --------------------------------------
__global__ __launch_bounds__(256) void cvt_f16(
    const float* __restrict__ s, __half* __restrict__ d, int n4)
{
    int i = blockIdx.x * 256 + threadIdx.x;
    if (i >= n4) return;
    float4 v = ((const float4*)s)[i];
    __half2 a, b;
    a.x = __float2half(v.x); a.y = __float2half(v.y);
    b.x = __float2half(v.z); b.y = __float2half(v.w);
    ((__half2*)d)[2*i]   = a;
    ((__half2*)d)[2*i+1] = b;
}

// ---------------- shared GEMM geometry --------------------------------------
#define BM 128
#define BN 128
#define BKK 32
#define TILE_B   (BM*BKK*2)          // 8192 B per tile
#define F16_STG  (2*TILE_B)          // 16384 B per stage
#define F16_SMEM (3*F16_STG)         // 49152 B (3-stage)

__device__ __forceinline__ uint32_t tswz(int row, int ch) {
    return (uint32_t)(row*64 + ((ch ^ ((row>>1)&3))<<4));
}

// ---------------- HMMA GEMM (1-pass fp16, 3-stage): C = A·Bᵀ (+bias) --------
template<typename OUT>
__global__ __launch_bounds__(256, 2) void hmma_gemm_f16(
    const __half* __restrict__ A, const __half* __restrict__ B,
    const float* __restrict__ bias, OUT* __restrict__ C, int K, int ldc)
{
    extern __shared__ char smx[];
    uint32_t sb = smem_u32(smx);
    int tid = threadIdx.x, lane = tid & 31, warp = tid >> 5;
    int wm = warp >> 1, wn = warp & 1;
    int bm = blockIdx.y * BM, bn = blockIdx.x * BN;

    const __half* Ap = A + (size_t)bm * K;
    const __half* Bp = B + (size_t)bn * K;

    int r0 = tid >> 2, c0 = tid & 3;
    int r1 = r0 + 64;
    uint32_t sw0 = tswz(r0, c0), sw1 = tswz(r1, c0);

    float acc[2][8][4];
    #pragma unroll
    for (int mt = 0; mt < 2; mt++)
        #pragma unroll
        for (int nt = 0; nt < 8; nt++)
            #pragma unroll
            for (int j = 0; j < 4; j++) acc[mt][nt][j] = 0.f;

    int lrow8 = lane & 7, ghalf = (lane >> 3) & 1, ghi = lane >> 4;
    int NS = K / BKK;   // 24

    auto issue = [&](int s, int b) {
        uint32_t dst = sb + (uint32_t)b * F16_STG;
        size_t ko = (size_t)s * BKK;
        size_t o0 = (size_t)r0 * K + ko + c0*8;
        size_t o1 = (size_t)r1 * K + ko + c0*8;
        cp16(dst + sw0, Ap + o0);
        cp16(dst + sw1, Ap + o1);
        cp16(dst + TILE_B + sw0, Bp + o0);
        cp16(dst + TILE_B + sw1, Bp + o1);
        cp_commit();
    };

    issue(0, 0); issue(1, 1); issue(2, 2);
    for (int s = 0; s < NS; ++s) {
        if (s + 3 <= NS)      cp_wait<2>();
        else if (s + 2 == NS) cp_wait<1>();
        else                  cp_wait<0>();
        __syncthreads();

        uint32_t stg = sb + (uint32_t)(s % 3) * F16_STG;
        #pragma unroll
        for (int ks = 0; ks < 2; ++ks) {
            int kc = ks * 2;
            uint32_t fA[2][4], fB[4][4];
            #pragma unroll
            for (int mt = 0; mt < 2; mt++) {
                int r = wm*32 + mt*16 + lrow8 + ghalf*8;
                ldsm4(fA[mt], stg + tswz(r, kc + ghi));
            }
            #pragma unroll
            for (int t16 = 0; t16 < 4; t16++) {
                int r = wn*64 + t16*16 + lrow8 + ghalf*8;
                ldsm4(fB[t16], stg + TILE_B + tswz(r, kc + ghi));
            }
            #pragma unroll
            for (int mt = 0; mt < 2; mt++)
                #pragma unroll
                for (int nt = 0; nt < 8; nt++) {
                    int t16 = nt >> 1, hi = nt & 1;
                    mma16816h(acc[mt][nt], fA[mt], fB[t16][hi], fB[t16][hi+2]);
                }
        }
        __syncthreads();
        if (s + 3 < NS) issue(s + 3, s % 3);
    }

    #pragma unroll
    for (int mt = 0; mt < 2; mt++) {
        int rlo = bm + wm*32 + mt*16 + (lane >> 2);
        int rhi = rlo + 8;
        #pragma unroll
        for (int nt = 0; nt < 8; nt++) {
            int col = bn + wn*64 + nt*8 + (lane & 3)*2;
            float b0 = 0.f, b1 = 0.f;
            if (bias) { b0 = bias[col]; b1 = bias[col+1]; }
            store2(C, (size_t)rlo * ldc + col, acc[mt][nt][0] + b0, acc[mt][nt][1] + b1);
            store2(C, (size_t)rhi * ldc + col, acc[mt][nt][2] + b0, acc[mt][nt][3] + b1);
        }
    }
}

// ---------- RMSnorm + RoPE + fp16 scatter [B*H,N,D] ------------------------
// reads fp16 qkv; q scale folds attn 1/8 AND log2(e) for exp2-softmax
__global__ __launch_bounds__(128) void prep_kernel(
    const __half* __restrict__ qkv, const float* __restrict__ cs,
    const float* __restrict__ sn, const float* __restrict__ qw,
    const float* __restrict__ kw,
    __half* __restrict__ qf, __half* __restrict__ kf,
    __half* __restrict__ vf)
{
    int task = blockIdx.x * 4 + (threadIdx.x >> 5);   // (b*H + h)*SEQ + n
    int lane = threadIdx.x & 31;
    int n  = task & (SEQ - 1);
    int bh = task >> 11;
    int h = bh % NUMH, b = bh / NUMH;

    const __half* base = qkv + ((size_t)(b*SEQ + n)) * (3*CH) + h*HD;
    float q1 = __half2float(base[lane]),        q2 = __half2float(base[lane+32]);
    float k1 = __half2float(base[CH+lane]),     k2 = __half2float(base[CH+lane+32]);
    float v1 = __half2float(base[2*CH+lane]),   v2 = __half2float(base[2*CH+lane+32]);

    float sq = q1*q1 + q2*q2, sk = k1*k1 + k2*k2;
    #pragma unroll
    for (int o = 16; o >= 1; o >>= 1) {
        sq += __shfl_xor_sync(0xffffffffu, sq, o);
        sk += __shfl_xor_sync(0xffffffffu, sk, o);
    }
    float rq = rsqrtf(sq * (1.f/64.f) + 1e-6f) * 0.125f * 1.44269504f;
    float rk = rsqrtf(sk * (1.f/64.f) + 1e-6f);
    q1 *= rq * qw[lane]; q2 *= rq * qw[lane+32];
    k1 *= rk * kw[lane]; k2 *= rk * kw[lane+32];

    float c = cs[n*32 + lane], s = sn[n*32 + lane];
    float qa = q1*c - q2*s, qb2 = q2*c + q1*s;
    float ka = k1*c - k2*s, kb2 = k2*c + k1*s;

    size_t o = ((size_t)bh * SEQ + n) * HD + lane;
    qf[o]    = __float2half(qa);
    qf[o+32] = __float2half(qb2);
    kf[o]    = __float2half(ka);
    kf[o+32] = __float2half(kb2);
    vf[o]    = __float2half(v1);
    vf[o+32] = __float2half(v2);
}

// ---------------- flash attention via HMMA (all fp16, 3-stage KV) ----------
#define AQ 128
#define AK 64
#define ANT (SEQ/AK)            // 32
#define QF_OFF 0
#define ASTG0  (AQ*128)         // 16384
#define KF_O 0
#define VF_O (AK*128)           // 8192
#define ASTG (2*AK*128)         // 16384
#define ASMEM (ASTG0 + 3*ASTG)  // 65536

__device__ __forceinline__ uint32_t swz(int row, int ch) {
    return (uint32_t)(row*128 + ((ch ^ (row & 7)) << 4));
}

__global__ __launch_bounds__(256, 2) void attn_mma(
    const __half* __restrict__ Qf, const __half* __restrict__ Kf,
    const __half* __restrict__ Vf, __half* __restrict__ Of)
{
    extern __shared__ char smx[];
    uint32_t sb = smem_u32(smx);
    int tid = threadIdx.x, lane = tid & 31, warp = tid >> 5;
    int qt = blockIdx.x, bh = blockIdx.y;

    const __half* Qfb = Qf + ((size_t)bh*SEQ + qt*AQ) * HD;
    const __half* Kfb = Kf + (size_t)bh*SEQ*HD;
    const __half* Vfb = Vf + (size_t)bh*SEQ*HD;

    auto issueKV = [&](int s, int b) {
        uint32_t dst = sb + ASTG0 + (uint32_t)b * ASTG;
        #pragma unroll
        for (int t = 0; t < 2; ++t) {
            int v = tid + t*256;
            int row = v >> 3, ch = v & 7;
            size_t go = (size_t)(s*AK + row) * HD + ch*8;
            uint32_t so = swz(row, ch);
            cp16(dst + KF_O + so, Kfb + go);
            cp16(dst + VF_O + so, Vfb + go);
        }
        cp_commit();
    };

    // group0: Q + KV stage 0; then stages 1, 2
    {
        #pragma unroll
        for (int t = 0; t < 4; ++t) {
            int v = tid + t*256;
            int row = v >> 3, ch = v & 7;
            cp16(sb + QF_OFF + swz(row, ch), Qfb + (size_t)row * HD + ch*8);
        }
        #pragma unroll
        for (int t = 0; t < 2; ++t) {
            int v = tid + t*256;
            int row = v >> 3, ch = v & 7;
            size_t go = (size_t)row * HD + ch*8;
            uint32_t so = swz(row, ch);
            cp16(sb + ASTG0 + KF_O + so, Kfb + go);
            cp16(sb + ASTG0 + VF_O + so, Vfb + go);
        }
        cp_commit();
    }
    issueKV(1, 1);
    issueKV(2, 2);

    int lrow8 = lane & 7, ghalf = (lane >> 3) & 1, ghi = lane >> 4;
    int arow = warp*16 + lrow8 + ghalf*8;

    float m0 = -CUDART_INF_F, m1 = -CUDART_INF_F, sl0 = 0.f, sl1 = 0.f;
    float o[8][4];
    #pragma unroll
    for (int j = 0; j < 8; j++)
        #pragma unroll
        for (int t = 0; t < 4; t++) o[j][t] = 0.f;

    for (int kt = 0; kt < ANT; ++kt) {
        if (kt + 3 <= ANT)      cp_wait<2>();
        else if (kt + 2 == ANT) cp_wait<1>();
        else                    cp_wait<0>();
        __syncthreads();
        uint32_t stg = sb + ASTG0 + (uint32_t)(kt % 3) * ASTG;

        // ---- S = Q Kᵀ (1-pass fp16; log2e pre-folded into Q)
        float s[8][4];
        #pragma unroll
        for (int j = 0; j < 8; j++)
            #pragma unroll
            for (int t = 0; t < 4; t++) s[j][t] = 0.f;
        #pragma unroll
        for (int ks = 0; ks < 4; ++ks) {
            uint32_t aF[4];
            ldsm4(aF, sb + QF_OFF + swz(arow, ks*2 + ghi));
            #pragma unroll
            for (int nt = 0; nt < 4; ++nt) {
                uint32_t bF[4];
                ldsm4(bF, stg + KF_O + swz(nt*16 + lrow8 + ghalf*8, ks*2 + ghi));
                mma16816h(s[nt*2],   aF, bF[0], bF[2]);
                mma16816h(s[nt*2+1], aF, bF[1], bF[3]);
            }
        }

        // ---- online softmax in exp2 domain (rows r and r+8)
        float mx0 = -CUDART_INF_F, mx1 = -CUDART_INF_F;
        #pragma unroll
        for (int j = 0; j < 8; j++) {
            mx0 = fmaxf(mx0, fmaxf(s[j][0], s[j][1]));
            mx1 = fmaxf(mx1, fmaxf(s[j][2], s[j][3]));
        }
        mx0 = fmaxf(mx0, __shfl_xor_sync(0xffffffffu, mx0, 1));
        mx0 = fmaxf(mx0, __shfl_xor_sync(0xffffffffu, mx0, 2));
        mx1 = fmaxf(mx1, __shfl_xor_sync(0xffffffffu, mx1, 1));
        mx1 = fmaxf(mx1, __shfl_xor_sync(0xffffffffu, mx1, 2));
        float nm0 = fmaxf(m0, mx0), nm1 = fmaxf(m1, mx1);
        float al0 = exp2f(m0 - nm0), al1 = exp2f(m1 - nm1);
        m0 = nm0; m1 = nm1;
        float rs0 = 0.f, rs1 = 0.f;
        #pragma unroll
        for (int j = 0; j < 8; j++) {
            s[j][0] = exp2f(s[j][0] - nm0); rs0 += s[j][0];
            s[j][1] = exp2f(s[j][1] - nm0); rs0 += s[j][1];
            s[j][2] = exp2f(s[j][2] - nm1); rs1 += s[j][2];
            s[j][3] = exp2f(s[j][3] - nm1); rs1 += s[j][3];
        }
        rs0 += __shfl_xor_sync(0xffffffffu, rs0, 1);
        rs0 += __shfl_xor_sync(0xffffffffu, rs0, 2);
        rs1 += __shfl_xor_sync(0xffffffffu, rs1, 1);
        rs1 += __shfl_xor_sync(0xffffffffu, rs1, 2);
        sl0 = sl0*al0 + rs0;
        sl1 = sl1*al1 + rs1;
        #pragma unroll
        for (int j = 0; j < 8; j++) {
            o[j][0] *= al0; o[j][1] *= al0;
            o[j][2] *= al1; o[j][3] *= al1;
        }

        // ---- O += P V (1-pass fp16)
        #pragma unroll
        for (int ks = 0; ks < 4; ++ks) {
            uint32_t ph[4];
            ph[0] = packhf(s[2*ks][0],   s[2*ks][1]);
            ph[1] = packhf(s[2*ks][2],   s[2*ks][3]);
            ph[2] = packhf(s[2*ks+1][0], s[2*ks+1][1]);
            ph[3] = packhf(s[2*ks+1][2], s[2*ks+1][3]);

            int vrow = ks*16 + lrow8 + ghalf*8;
            #pragma unroll
            for (int nb2 = 0; nb2 < 4; ++nb2) {
                uint32_t vF[4];
                ldsm4t(vF, stg + VF_O + swz(vrow, nb2*2 + ghi));
                mma16816h(o[nb2*2],   ph, vF[0], vF[1]);
                mma16816h(o[nb2*2+1], ph, vF[2], vF[3]);
            }
        }
        __syncthreads();
        if (kt + 3 < ANT) issueKV(kt + 3, kt % 3);
    }

    // ---- epilogue: normalize, write fp16 O [B,N,C]
    int b_ = bh / NUMH, h_ = bh % NUMH;
    int r0 = warp*16 + (lane >> 2);
    size_t row0 = (size_t)b_*SEQ + qt*AQ + r0;
    size_t row1 = row0 + 8;
    float inv0 = 1.f / sl0, inv1 = 1.f / sl1;
    #pragma unroll
    for (int j = 0; j < 8; j++) {
        int col = h_*HD + j*8 + (lane & 3)*2;
        __half2 h0, h1;
        h0.x = __float2half(o[j][0]*inv0); h0.y = __float2half(o[j][1]*inv0);
        h1.x = __float2half(o[j][2]*inv1); h1.y = __float2half(o[j][3]*inv1);
        *(__half2*)&Of[row0*CH + col] = h0;
        *(__half2*)&Of[row1*CH + col] = h1;
    }
}

// ---------------------------------------------------------------------------
extern "C" void kernel_launch(void* const* d_in, const int* in_sizes, int n_in,
                              void* d_out, int out_size)
{
    const float* x      = (const float*)d_in[0];
    const float* cs     = (const float*)d_in[1];
    const float* sn     = (const float*)d_in[2];
    const float* qkv_w  = (const float*)d_in[3];
    const float* qnw    = (const float*)d_in[4];
    const float* knw    = (const float*)d_in[5];
    const float* proj_w = (const float*)d_in[6];
    const float* proj_b = (const float*)d_in[7];
    float* out = (float*)d_out;

    __half *qkvh, *xf, *wqf, *wpf, *qf, *kf, *vf, *of;
    cudaGetSymbolAddress((void**)&qkvh, g_qkvh);
    cudaGetSymbolAddress((void**)&xf,  g_xf);
    cudaGetSymbolAddress((void**)&wqf, g_wqf);
    cudaGetSymbolAddress((void**)&wpf, g_wpf);
    cudaGetSymbolAddress((void**)&qf,  g_qf);
    cudaGetSymbolAddress((void**)&kf,  g_kf);
    cudaGetSymbolAddress((void**)&vf,  g_vf);
    cudaGetSymbolAddress((void**)&of,  g_of);

    // 0) converts: x/qkv_w/proj_w -> fp16
    {
        int n4x = MROWS*CH/4, n4q = 3*CH*CH/4, n4p = CH*CH/4;
        cvt_f16<<<(n4x+255)/256, 256>>>(x, xf, n4x);
        cvt_f16<<<(n4q+255)/256, 256>>>(qkv_w, wqf, n4q);
        cvt_f16<<<(n4p+255)/256, 256>>>(proj_w, wpf, n4p);
    }

    // 1) QKV projection -> fp16 qkv (HMMA 1-pass, 3-stage)
    cudaFuncSetAttribute(hmma_gemm_f16<__half>,
                         cudaFuncAttributeMaxDynamicSharedMemorySize, F16_SMEM);
    hmma_gemm_f16<__half><<<dim3(3*CH/BN, MROWS/BM), 256, F16_SMEM>>>(
        xf, wqf, nullptr, qkvh, CH, 3*CH);

    // 2) RMSnorm + RoPE + fp16 scatter (log2e folded into q)
    prep_kernel<<<(NBH*SEQ)/4, 128>>>(qkvh, cs, sn, qnw, knw, qf, kf, vf);

    // 3) flash attention (HMMA fp16, 3-stage KV pipe, exp2 softmax)
    cudaFuncSetAttribute(attn_mma,
                         cudaFuncAttributeMaxDynamicSharedMemorySize, ASMEM);
    attn_mma<<<dim3(SEQ/AQ, NBH), 256, ASMEM>>>(qf, kf, vf, of);

    // 4) output projection (+bias, HMMA 1-pass, fp32 out)
    cudaFuncSetAttribute(hmma_gemm_f16<float>,
                         cudaFuncAttributeMaxDynamicSharedMemorySize, F16_SMEM);
    hmma_gemm_f16<float><<<dim3(CH/BN, MROWS/BM), 256, F16_SMEM>>>(
        of, wpf, proj_b, out, CH, CH);
}